// round 1
// baseline (speedup 1.0000x reference)
#include <cuda_runtime.h>

// Problem constants
#define B_  32
#define C_  512
#define CI_ 256
#define N_  1024   // H*W = 32*32

// ---------------- static device scratch (no allocations allowed) ----------------
__device__ float d_G [B_ * CI_ * N_];            // g   [B, Ci, N]
__device__ float d_T [B_ * CI_ * N_];            // theta [B, Ci, N]
__device__ float d_P [B_ * CI_ * N_];            // phi [B, Ci, N]
__device__ float d_F [(size_t)B_ * N_ * N_];     // attention logits / probs [B, N, N]
__device__ float d_Y [B_ * CI_ * N_];            // y [B, Ci, N]
__device__ float d_WY[(size_t)B_ * C_ * N_];     // w_y [B, C, N]
__device__ float d_scale[C_];
__device__ float d_shift[C_];

// ---------------- generic weight GEMM: Out[b,m,n] = sum_k W[m,k]*X[b,k,n] + bias[m] ----
// 128x128 tile, BK=8, 256 threads, 8x8 per thread. N fixed = 1024.
__global__ __launch_bounds__(256)
void wgemm_kernel(const float* __restrict__ W, const float* __restrict__ bias,
                  const float* __restrict__ X, float* __restrict__ Out,
                  int M, int K) {
    __shared__ float As[8][128];
    __shared__ float Bs[8][128];
    const int tid = threadIdx.x;
    const int tx = tid & 15;          // 0..15 -> n
    const int ty = tid >> 4;          // 0..15 -> m
    const int row0 = blockIdx.y * 128;
    const int col0 = blockIdx.x * 128;
    const float* Xb = X + (size_t)blockIdx.z * K * N_;
    float acc[8][8];
#pragma unroll
    for (int i = 0; i < 8; ++i)
#pragma unroll
        for (int j = 0; j < 8; ++j) acc[i][j] = 0.f;

    for (int k0 = 0; k0 < K; k0 += 8) {
        // A tile: W[row0+0..127][k0..k0+7], transposed into As[k][m]
        {
            int r  = tid >> 1;
            int kc = (tid & 1) * 4;
            float4 v = *(const float4*)&W[(size_t)(row0 + r) * K + k0 + kc];
            As[kc + 0][r] = v.x; As[kc + 1][r] = v.y;
            As[kc + 2][r] = v.z; As[kc + 3][r] = v.w;
        }
        // B tile: X[k0..k0+7][col0..col0+127]
        {
            int kr = tid >> 5;
            int nc = (tid & 31) * 4;
            *(float4*)&Bs[kr][nc] = *(const float4*)&Xb[(size_t)(k0 + kr) * N_ + col0 + nc];
        }
        __syncthreads();
#pragma unroll
        for (int k = 0; k < 8; ++k) {
            float a[8], b[8];
#pragma unroll
            for (int i = 0; i < 8; ++i) a[i] = As[k][ty * 8 + i];
#pragma unroll
            for (int j = 0; j < 8; ++j) b[j] = Bs[k][tx * 8 + j];
#pragma unroll
            for (int i = 0; i < 8; ++i)
#pragma unroll
                for (int j = 0; j < 8; ++j) acc[i][j] += a[i] * b[j];
        }
        __syncthreads();
    }
    float* Ob = Out + (size_t)blockIdx.z * M * N_;
#pragma unroll
    for (int i = 0; i < 8; ++i) {
        int m = row0 + ty * 8 + i;
        float bv = bias[m];
        float* op = &Ob[(size_t)m * N_ + col0 + tx * 8];
        float4 v0 = {acc[i][0] + bv, acc[i][1] + bv, acc[i][2] + bv, acc[i][3] + bv};
        float4 v1 = {acc[i][4] + bv, acc[i][5] + bv, acc[i][6] + bv, acc[i][7] + bv};
        *(float4*)(op)     = v0;
        *(float4*)(op + 4) = v1;
    }
}

// ---------------- f[b,n,m] = sum_c T[b,c,n] * P[b,c,m]  (A^T * B, K=Ci) --------------
__global__ __launch_bounds__(256)
void attn_score_kernel(const float* __restrict__ T, const float* __restrict__ P,
                       float* __restrict__ F) {
    __shared__ float As[8][128];
    __shared__ float Bs[8][128];
    const int tid = threadIdx.x;
    const int tx = tid & 15;
    const int ty = tid >> 4;
    const int row0 = blockIdx.y * 128;   // n
    const int col0 = blockIdx.x * 128;   // m
    const float* Tb = T + (size_t)blockIdx.z * CI_ * N_;
    const float* Pb = P + (size_t)blockIdx.z * CI_ * N_;
    float acc[8][8];
#pragma unroll
    for (int i = 0; i < 8; ++i)
#pragma unroll
        for (int j = 0; j < 8; ++j) acc[i][j] = 0.f;

    for (int k0 = 0; k0 < CI_; k0 += 8) {
        {
            int kr = tid >> 5;
            int nc = (tid & 31) * 4;
            *(float4*)&As[kr][nc] = *(const float4*)&Tb[(size_t)(k0 + kr) * N_ + row0 + nc];
            *(float4*)&Bs[kr][nc] = *(const float4*)&Pb[(size_t)(k0 + kr) * N_ + col0 + nc];
        }
        __syncthreads();
#pragma unroll
        for (int k = 0; k < 8; ++k) {
            float a[8], b[8];
#pragma unroll
            for (int i = 0; i < 8; ++i) a[i] = As[k][ty * 8 + i];
#pragma unroll
            for (int j = 0; j < 8; ++j) b[j] = Bs[k][tx * 8 + j];
#pragma unroll
            for (int i = 0; i < 8; ++i)
#pragma unroll
                for (int j = 0; j < 8; ++j) acc[i][j] += a[i] * b[j];
        }
        __syncthreads();
    }
    float* Fb = F + (size_t)blockIdx.z * N_ * N_;
#pragma unroll
    for (int i = 0; i < 8; ++i) {
        int n = row0 + ty * 8 + i;
        float* op = &Fb[(size_t)n * N_ + col0 + tx * 8];
        *(float4*)(op)     = make_float4(acc[i][0], acc[i][1], acc[i][2], acc[i][3]);
        *(float4*)(op + 4) = make_float4(acc[i][4], acc[i][5], acc[i][6], acc[i][7]);
    }
}

// ---------------- in-place row softmax over last dim (rows of length 1024) -----------
__global__ __launch_bounds__(256)
void softmax_kernel(float* __restrict__ F) {
    size_t row = blockIdx.x;
    float4* p = (float4*)(F + row * (size_t)N_);
    int t = threadIdx.x;
    float4 v = p[t];
    float m = fmaxf(fmaxf(v.x, v.y), fmaxf(v.z, v.w));
#pragma unroll
    for (int o = 16; o; o >>= 1) m = fmaxf(m, __shfl_xor_sync(~0u, m, o));
    __shared__ float smax[8], ssum[8];
    if ((t & 31) == 0) smax[t >> 5] = m;
    __syncthreads();
    float mm = smax[0];
#pragma unroll
    for (int i = 1; i < 8; ++i) mm = fmaxf(mm, smax[i]);
    v.x = __expf(v.x - mm); v.y = __expf(v.y - mm);
    v.z = __expf(v.z - mm); v.w = __expf(v.w - mm);
    float s = v.x + v.y + v.z + v.w;
#pragma unroll
    for (int o = 16; o; o >>= 1) s += __shfl_xor_sync(~0u, s, o);
    if ((t & 31) == 0) ssum[t >> 5] = s;
    __syncthreads();
    float tot = 0.f;
#pragma unroll
    for (int i = 0; i < 8; ++i) tot += ssum[i];
    float inv = 1.0f / tot;
    v.x *= inv; v.y *= inv; v.z *= inv; v.w *= inv;
    p[t] = v;
}

// ---------------- y[b,o,n] = sum_m G[b,o,m] * A[b,n,m]  (A * B^T, K=N) ---------------
__global__ __launch_bounds__(256)
void attn_apply_kernel(const float* __restrict__ G, const float* __restrict__ F,
                       float* __restrict__ Y) {
    __shared__ float As[8][128];
    __shared__ float Bs[8][128];
    const int tid = threadIdx.x;
    const int tx = tid & 15;
    const int ty = tid >> 4;
    const int row0 = blockIdx.y * 128;   // o
    const int col0 = blockIdx.x * 128;   // n
    const float* Gb = G + (size_t)blockIdx.z * CI_ * N_;
    const float* Fb = F + (size_t)blockIdx.z * N_ * N_;
    float acc[8][8];
#pragma unroll
    for (int i = 0; i < 8; ++i)
#pragma unroll
        for (int j = 0; j < 8; ++j) acc[i][j] = 0.f;

    for (int k0 = 0; k0 < N_; k0 += 8) {
        {
            int r  = tid >> 1;
            int kc = (tid & 1) * 4;
            float4 a = *(const float4*)&Gb[(size_t)(row0 + r) * N_ + k0 + kc];
            As[kc + 0][r] = a.x; As[kc + 1][r] = a.y;
            As[kc + 2][r] = a.z; As[kc + 3][r] = a.w;
            float4 b = *(const float4*)&Fb[(size_t)(col0 + r) * N_ + k0 + kc];
            Bs[kc + 0][r] = b.x; Bs[kc + 1][r] = b.y;
            Bs[kc + 2][r] = b.z; Bs[kc + 3][r] = b.w;
        }
        __syncthreads();
#pragma unroll
        for (int k = 0; k < 8; ++k) {
            float a[8], b[8];
#pragma unroll
            for (int i = 0; i < 8; ++i) a[i] = As[k][ty * 8 + i];
#pragma unroll
            for (int j = 0; j < 8; ++j) b[j] = Bs[k][tx * 8 + j];
#pragma unroll
            for (int i = 0; i < 8; ++i)
#pragma unroll
                for (int j = 0; j < 8; ++j) acc[i][j] += a[i] * b[j];
        }
        __syncthreads();
    }
    float* Yb = Y + (size_t)blockIdx.z * CI_ * N_;
#pragma unroll
    for (int i = 0; i < 8; ++i) {
        int o = row0 + ty * 8 + i;
        float* op = &Yb[(size_t)o * N_ + col0 + tx * 8];
        *(float4*)(op)     = make_float4(acc[i][0], acc[i][1], acc[i][2], acc[i][3]);
        *(float4*)(op + 4) = make_float4(acc[i][4], acc[i][5], acc[i][6], acc[i][7]);
    }
}

// ---------------- BatchNorm statistics per channel -> fused scale/shift --------------
__global__ __launch_bounds__(256)
void bnstats_kernel(const float* __restrict__ WY, const float* __restrict__ gamma,
                    const float* __restrict__ beta) {
    int c = blockIdx.x;
    int t = threadIdx.x;
    float s = 0.f, s2 = 0.f;
    for (int b = 0; b < B_; ++b) {
        const float* p = WY + ((size_t)b * C_ + c) * N_;
        for (int n = t; n < N_; n += 256) {
            float v = p[n];
            s += v; s2 += v * v;
        }
    }
#pragma unroll
    for (int o = 16; o; o >>= 1) {
        s  += __shfl_xor_sync(~0u, s,  o);
        s2 += __shfl_xor_sync(~0u, s2, o);
    }
    __shared__ float ss[8], ss2[8];
    if ((t & 31) == 0) { ss[t >> 5] = s; ss2[t >> 5] = s2; }
    __syncthreads();
    if (t == 0) {
        float S = 0.f, S2 = 0.f;
#pragma unroll
        for (int i = 0; i < 8; ++i) { S += ss[i]; S2 += ss2[i]; }
        const float invN = 1.0f / (float)(B_ * N_);
        float mean = S * invN;
        float var  = S2 * invN - mean * mean;
        float inv  = rsqrtf(var + 1e-5f);
        float sc   = gamma[c] * inv;
        d_scale[c] = sc;
        d_shift[c] = beta[c] - mean * sc;
    }
}

// ---------------- finalize: out = w_y*scale + shift + x ------------------------------
__global__ __launch_bounds__(256)
void finalize_kernel(const float* __restrict__ WY, const float* __restrict__ x,
                     float* __restrict__ out) {
    size_t i4 = (size_t)blockIdx.x * 256 + threadIdx.x;  // float4 index
    int c = (int)((i4 >> 8) & (C_ - 1));                 // 256 float4 per (b,c) row
    float sc = d_scale[c], sh = d_shift[c];
    float4 w = ((const float4*)WY)[i4];
    float4 xv = ((const float4*)x)[i4];
    float4 o;
    o.x = w.x * sc + sh + xv.x;
    o.y = w.y * sc + sh + xv.y;
    o.z = w.z * sc + sh + xv.z;
    o.w = w.w * sc + sh + xv.w;
    ((float4*)out)[i4] = o;
}

// ---------------- launch --------------------------------------------------------------
extern "C" void kernel_launch(void* const* d_in, const int* in_sizes, int n_in,
                              void* d_out, int out_size) {
    const float* x     = (const float*)d_in[0];
    const float* Wg    = (const float*)d_in[1];
    const float* bg    = (const float*)d_in[2];
    const float* Wt    = (const float*)d_in[3];
    const float* bt    = (const float*)d_in[4];
    const float* Wp    = (const float*)d_in[5];
    const float* bp    = (const float*)d_in[6];
    const float* Wz    = (const float*)d_in[7];
    const float* bz    = (const float*)d_in[8];
    const float* gamma = (const float*)d_in[9];
    const float* beta  = (const float*)d_in[10];
    float* out = (float*)d_out;

    float *G, *T, *P, *F, *Y, *WY;
    cudaGetSymbolAddress((void**)&G,  d_G);
    cudaGetSymbolAddress((void**)&T,  d_T);
    cudaGetSymbolAddress((void**)&P,  d_P);
    cudaGetSymbolAddress((void**)&F,  d_F);
    cudaGetSymbolAddress((void**)&Y,  d_Y);
    cudaGetSymbolAddress((void**)&WY, d_WY);

    dim3 blk(256);
    // projections: [B, Ci, N] = W(Ci x C) * x(b: C x N)
    wgemm_kernel<<<dim3(8, 2, 32), blk>>>(Wg, bg, x, G, CI_, C_);
    wgemm_kernel<<<dim3(8, 2, 32), blk>>>(Wt, bt, x, T, CI_, C_);
    wgemm_kernel<<<dim3(8, 2, 32), blk>>>(Wp, bp, x, P, CI_, C_);
    // attention logits + softmax
    attn_score_kernel<<<dim3(8, 8, 32), blk>>>(T, P, F);
    softmax_kernel<<<B_ * N_, 256>>>(F);
    // apply attention
    attn_apply_kernel<<<dim3(8, 2, 32), blk>>>(G, F, Y);
    // output 1x1 conv: [B, C, N] = Wz(C x Ci) * y(b: Ci x N)
    wgemm_kernel<<<dim3(8, 4, 32), blk>>>(Wz, bz, Y, WY, C_, CI_);
    // batchnorm stats -> scale/shift, then fused affine + residual
    bnstats_kernel<<<C_, 256>>>(WY, gamma, beta);
    finalize_kernel<<<(B_ * C_ * N_) / 4 / 256, 256>>>(WY, x, out);
}

// round 3
// speedup vs baseline: 2.0590x; 2.0590x over previous
#include <cuda_runtime.h>
#include <cstdint>

// Problem constants
#define B_  32
#define C_  512
#define CI_ 256
#define N_  1024   // H*W

// ---------------- static device scratch ----------------
__device__ float d_G [B_ * CI_ * N_];
__device__ float d_T [B_ * CI_ * N_];
__device__ float d_P [B_ * CI_ * N_];
__device__ float d_F [(size_t)B_ * N_ * N_];
__device__ float d_Y [B_ * CI_ * N_];
__device__ float d_WY[(size_t)B_ * C_ * N_];
__device__ float d_scale[C_];
__device__ float d_shift[C_];

// ---------------- helpers ----------------
static __device__ __forceinline__ uint32_t smem_u32(const void* p) {
    uint32_t a;
    asm("{ .reg .u64 t; cvta.to.shared.u64 t, %1; cvt.u32.u64 %0, t; }" : "=r"(a) : "l"(p));
    return a;
}

#define CP4(dst, src) \
    asm volatile("cp.async.ca.shared.global [%0], [%1], 4;" :: "r"(dst), "l"(src))
#define CP_COMMIT() asm volatile("cp.async.commit_group;" ::: "memory")
#define CP_WAIT1()  asm volatile("cp.async.wait_group 1;" ::: "memory")
#define CP_WAIT0()  asm volatile("cp.async.wait_group 0;" ::: "memory")

static __device__ __forceinline__ void mma_tf32(float* c, const uint4& a, const uint2& b) {
    asm volatile(
        "mma.sync.aligned.m16n8k8.row.col.f32.tf32.tf32.f32 "
        "{%0,%1,%2,%3},{%4,%5,%6,%7},{%8,%9},{%0,%1,%2,%3};"
        : "+f"(c[0]), "+f"(c[1]), "+f"(c[2]), "+f"(c[3])
        : "r"(a.x), "r"(a.y), "r"(a.z), "r"(a.w), "r"(b.x), "r"(b.y));
}

// SMEM: Abuf0 [0,16K) Abuf1 [16K,32K) Bbuf0 [32K,48K) Bbuf1 [48K,64K)
// A fragment buffer: [blk = (m>>4)*4 + (k>>3)][lane][4 regs] floats
//   lane = (m&7)*4 + (k&3); reg = ((m>>3)&1) + 2*((k>>2)&1)
// B fragment buffer: [blk = (n>>3)*4 + (k>>3)][lane][2 regs] floats
//   lane = (n&7)*4 + (k&3); reg = (k>>2)&1
#define SMEM_BYTES 65536

// ---------------- canonical 128x128 tensor-core tf32 GEMM ----------------
// Out[b, m0+0..127, n0+0..127] (+= bias[m]) = sum_k A'[m,k] * B'[n,k]
//   TA=false: A global [M, K] K-major (ld ldA);  TA=true: A global [K, M] (m contig)
//   TB=false: B global [N, K] K-major (ld ldB);  TB=true: B global [K, N] (n contig)
// Output row length is N_ for every output tensor in this problem.
template <bool TA, bool TB, bool BIAS>
__global__ __launch_bounds__(256, 2)
void mm_tc(const float* __restrict__ A, const float* __restrict__ Bm,
           const float* __restrict__ bias, float* __restrict__ Out,
           int K, int ldA, int ldB,
           long strideA, long strideB, long strideO) {
    extern __shared__ __align__(1024) char smem[];
    const uint32_t sb = smem_u32(smem);
    const int tid = threadIdx.x;
    const int w = tid >> 5;
    const int l = tid & 31;
    const int wm = w >> 2;       // 0..1
    const int wn = w & 3;        // 0..3
    const int m0 = blockIdx.y * 128;
    const int n0 = blockIdx.x * 128;
    const float* Ab = A  + (size_t)blockIdx.z * strideA;
    const float* Bb = Bm + (size_t)blockIdx.z * strideB;
    float*       Ob = Out + (size_t)blockIdx.z * strideO;

    // ---- staging: gmem -> fragment-layout smem via 4B cp.async, bank-conflict-free ----
    auto stageA = [&](int s, int sel) {
        const int k0 = s * 32;
        const uint32_t abuf = sb + sel * 16384;
        if constexpr (!TA) {
            const int k4 = l & 7;
            const int rot = (l >> 1) & 3;
#pragma unroll
            for (int j = 0; j < 4; ++j) {
                int m = ((l >> 3) & 1) + 2 * (w & 3) + 8 * ((l >> 4) & 1) + 16 * (w >> 2) + 32 * j;
                const float* src = Ab + (size_t)(m0 + m) * ldA + k0 + k4 * 4;
                int C0 = ((m >> 4) * 4 + (k4 >> 1)) * 128 + (m & 7) * 16 + ((m >> 3) & 1) + 2 * (k4 & 1);
                uint32_t dst = abuf + C0 * 4 + (rot << 4);
                uint64_t sp = (uint64_t)src + (rot << 2);
#pragma unroll
                for (int i = 0; i < 4; ++i)
                    CP4(dst ^ (i << 4), sp ^ (uint64_t)(i << 2));
            }
        } else {
            const int rot = (l >> 3) & 1;
#pragma unroll
            for (int j = 0; j < 4; ++j) {
                int k = (l & 7) + 8 * j;
                int m4 = ((l >> 3) & 1) + 2 * ((l >> 4) & 1) + 4 * w;
                const float* src = Ab + (size_t)(k0 + k) * ldA + m0 + m4 * 4;
                int C0 = ((m4 >> 2) * 4 + (k >> 3)) * 128 + 64 * (m4 & 1) + 4 * (k & 3)
                         + ((m4 >> 1) & 1) + 2 * ((k >> 2) & 1);
                uint32_t dst = abuf + C0 * 4 + (rot << 6);
                uint64_t sp = (uint64_t)src + (rot << 2);
#pragma unroll
                for (int i = 0; i < 4; ++i)
                    CP4(dst ^ (i << 6), sp ^ (uint64_t)(i << 2));
            }
        }
    };
    auto stageB = [&](int s, int sel) {
        const int k0 = s * 32;
        const uint32_t bbuf = sb + 32768 + sel * 16384;
        if constexpr (!TB) {
            const int rot = (l >> 3) & 3;
#pragma unroll
            for (int j = 0; j < 4; ++j) {
                int n  = (l & 3) + 4 * ((l >> 3) & 3) + 16 * (w & 3) + 64 * (j >> 1);
                int k4 = ((l >> 2) & 1) + 2 * ((w >> 2) & 1) + 4 * (j & 1);
                const float* src = Bb + (size_t)(n0 + n) * ldB + k0 + k4 * 4;
                int C0 = ((n >> 3) * 4 + (k4 >> 1)) * 64 + (n & 7) * 8 + (k4 & 1);
                uint32_t dst = bbuf + C0 * 4 + (rot << 3);
                uint64_t sp = (uint64_t)src + (rot << 2);
#pragma unroll
                for (int i = 0; i < 4; ++i)
                    CP4(dst ^ (i << 3), sp ^ (uint64_t)(i << 2));
            }
        } else {
            const int rot = (l >> 3) & 3;
#pragma unroll
            for (int j = 0; j < 4; ++j) {
                int k  = (l & 7) + 8 * j;
                int n4 = ((l >> 3) & 3) + 4 * w;
                const float* src = Bb + (size_t)(k0 + k) * ldB + n0 + n4 * 4;
                int C0 = ((n4 >> 1) * 4 + (k >> 3)) * 64 + 32 * (n4 & 1) + 2 * (k & 3) + ((k >> 2) & 1);
                uint32_t dst = bbuf + C0 * 4 + (rot << 5);
                uint64_t sp = (uint64_t)src + (rot << 2);
#pragma unroll
                for (int i = 0; i < 4; ++i)
                    CP4(dst ^ (i << 5), sp ^ (uint64_t)(i << 2));
            }
        }
    };

    float acc[4][4][4];
#pragma unroll
    for (int mt = 0; mt < 4; ++mt)
#pragma unroll
        for (int nt = 0; nt < 4; ++nt)
#pragma unroll
            for (int q = 0; q < 4; ++q) acc[mt][nt][q] = 0.f;

    const int S = K / 32;
    stageA(0, 0); stageB(0, 0); CP_COMMIT();

    for (int s = 0; s < S; ++s) {
        if (s + 1 < S) {
            stageA(s + 1, (s + 1) & 1);
            stageB(s + 1, (s + 1) & 1);
            CP_COMMIT();
            CP_WAIT1();
        } else {
            CP_WAIT0();
        }
        __syncthreads();

        const int sel = s & 1;
        const uint4* Af = (const uint4*)(smem + sel * 16384);
        const uint2* Bf = (const uint2*)(smem + 32768 + sel * 16384);
#pragma unroll
        for (int ks = 0; ks < 4; ++ks) {
            uint4 af[4];
            uint2 bf[4];
#pragma unroll
            for (int mt = 0; mt < 4; ++mt)
                af[mt] = Af[((wm * 4 + mt) * 4 + ks) * 32 + l];
#pragma unroll
            for (int nt = 0; nt < 4; ++nt)
                bf[nt] = Bf[((wn * 4 + nt) * 4 + ks) * 32 + l];
#pragma unroll
            for (int mt = 0; mt < 4; ++mt)
#pragma unroll
                for (int nt = 0; nt < 4; ++nt)
                    mma_tf32(acc[mt][nt], af[mt], bf[nt]);
        }
        __syncthreads();
    }

    // ---- epilogue ----
#pragma unroll
    for (int mt = 0; mt < 4; ++mt) {
        int row = m0 + (wm * 4 + mt) * 16 + (l >> 2);
        float bv0 = 0.f, bv1 = 0.f;
        if constexpr (BIAS) { bv0 = bias[row]; bv1 = bias[row + 8]; }
#pragma unroll
        for (int nt = 0; nt < 4; ++nt) {
            int col = n0 + (wn * 4 + nt) * 8 + (l & 3) * 2;
            float2 v0 = {acc[mt][nt][0] + bv0, acc[mt][nt][1] + bv0};
            float2 v1 = {acc[mt][nt][2] + bv1, acc[mt][nt][3] + bv1};
            *(float2*)&Ob[(size_t)row * N_ + col]       = v0;
            *(float2*)&Ob[(size_t)(row + 8) * N_ + col] = v1;
        }
    }
}

// ---------------- row softmax over last dim (rows of 1024) ----------------
__global__ __launch_bounds__(256)
void softmax_kernel(float* __restrict__ F) {
    size_t row = blockIdx.x;
    float4* p = (float4*)(F + row * (size_t)N_);
    int t = threadIdx.x;
    float4 v = p[t];
    float m = fmaxf(fmaxf(v.x, v.y), fmaxf(v.z, v.w));
#pragma unroll
    for (int o = 16; o; o >>= 1) m = fmaxf(m, __shfl_xor_sync(~0u, m, o));
    __shared__ float smax[8], ssum[8];
    if ((t & 31) == 0) smax[t >> 5] = m;
    __syncthreads();
    float mm = smax[0];
#pragma unroll
    for (int i = 1; i < 8; ++i) mm = fmaxf(mm, smax[i]);
    v.x = __expf(v.x - mm); v.y = __expf(v.y - mm);
    v.z = __expf(v.z - mm); v.w = __expf(v.w - mm);
    float s = v.x + v.y + v.z + v.w;
#pragma unroll
    for (int o = 16; o; o >>= 1) s += __shfl_xor_sync(~0u, s, o);
    if ((t & 31) == 0) ssum[t >> 5] = s;
    __syncthreads();
    float tot = 0.f;
#pragma unroll
    for (int i = 0; i < 8; ++i) tot += ssum[i];
    float inv = 1.0f / tot;
    v.x *= inv; v.y *= inv; v.z *= inv; v.w *= inv;
    p[t] = v;
}

// ---------------- BatchNorm stats -> fused scale/shift ----------------
__global__ __launch_bounds__(256)
void bnstats_kernel(const float* __restrict__ WY, const float* __restrict__ gamma,
                    const float* __restrict__ beta) {
    int c = blockIdx.x;
    int t = threadIdx.x;
    float s = 0.f, s2 = 0.f;
    for (int b = 0; b < B_; ++b) {
        const float* p = WY + ((size_t)b * C_ + c) * N_;
        for (int n = t; n < N_; n += 256) {
            float v = p[n];
            s += v; s2 += v * v;
        }
    }
#pragma unroll
    for (int o = 16; o; o >>= 1) {
        s  += __shfl_xor_sync(~0u, s,  o);
        s2 += __shfl_xor_sync(~0u, s2, o);
    }
    __shared__ float ss[8], ss2[8];
    if ((t & 31) == 0) { ss[t >> 5] = s; ss2[t >> 5] = s2; }
    __syncthreads();
    if (t == 0) {
        float S = 0.f, S2 = 0.f;
#pragma unroll
        for (int i = 0; i < 8; ++i) { S += ss[i]; S2 += ss2[i]; }
        const float invN = 1.0f / (float)(B_ * N_);
        float mean = S * invN;
        float var  = S2 * invN - mean * mean;
        float inv  = rsqrtf(var + 1e-5f);
        float sc   = gamma[c] * inv;
        d_scale[c] = sc;
        d_shift[c] = beta[c] - mean * sc;
    }
}

// ---------------- finalize: out = w_y*scale + shift + x ----------------
__global__ __launch_bounds__(256)
void finalize_kernel(const float* __restrict__ WY, const float* __restrict__ x,
                     float* __restrict__ out) {
    size_t i4 = (size_t)blockIdx.x * 256 + threadIdx.x;
    int c = (int)((i4 >> 8) & (C_ - 1));
    float sc = d_scale[c], sh = d_shift[c];
    float4 w  = ((const float4*)WY)[i4];
    float4 xv = ((const float4*)x)[i4];
    float4 o;
    o.x = w.x * sc + sh + xv.x;
    o.y = w.y * sc + sh + xv.y;
    o.z = w.z * sc + sh + xv.z;
    o.w = w.w * sc + sh + xv.w;
    ((float4*)out)[i4] = o;
}

// ---------------- launch ----------------
extern "C" void kernel_launch(void* const* d_in, const int* in_sizes, int n_in,
                              void* d_out, int out_size) {
    const float* x     = (const float*)d_in[0];
    const float* Wg    = (const float*)d_in[1];
    const float* bg    = (const float*)d_in[2];
    const float* Wt    = (const float*)d_in[3];
    const float* bt    = (const float*)d_in[4];
    const float* Wp    = (const float*)d_in[5];
    const float* bp    = (const float*)d_in[6];
    const float* Wz    = (const float*)d_in[7];
    const float* bz    = (const float*)d_in[8];
    const float* gamma = (const float*)d_in[9];
    const float* beta  = (const float*)d_in[10];
    float* out = (float*)d_out;

    float *G, *T, *P, *F, *Y, *WY;
    cudaGetSymbolAddress((void**)&G,  d_G);
    cudaGetSymbolAddress((void**)&T,  d_T);
    cudaGetSymbolAddress((void**)&P,  d_P);
    cudaGetSymbolAddress((void**)&F,  d_F);
    cudaGetSymbolAddress((void**)&Y,  d_Y);
    cudaGetSymbolAddress((void**)&WY, d_WY);

    cudaFuncSetAttribute(mm_tc<false, true,  true >, cudaFuncAttributeMaxDynamicSharedMemorySize, SMEM_BYTES);
    cudaFuncSetAttribute(mm_tc<true,  true,  false>, cudaFuncAttributeMaxDynamicSharedMemorySize, SMEM_BYTES);
    cudaFuncSetAttribute(mm_tc<false, false, false>, cudaFuncAttributeMaxDynamicSharedMemorySize, SMEM_BYTES);

    const long sX  = (long)C_  * N_;
    const long sCi = (long)CI_ * N_;
    const long sF  = (long)N_  * N_;
    const long sC  = (long)C_  * N_;

    // projections: Out[b] (Ci x N) = W (Ci x C) * x[b] (C x N)
    mm_tc<false, true, true><<<dim3(8, 2, 32), 256, SMEM_BYTES>>>(Wg, x, bg, G, C_, C_, N_, 0, sX, sCi);
    mm_tc<false, true, true><<<dim3(8, 2, 32), 256, SMEM_BYTES>>>(Wt, x, bt, T, C_, C_, N_, 0, sX, sCi);
    mm_tc<false, true, true><<<dim3(8, 2, 32), 256, SMEM_BYTES>>>(Wp, x, bp, P, C_, C_, N_, 0, sX, sCi);
    // scores: f[b,n,m] = sum_c T[b,c,n] * P[b,c,m]
    mm_tc<true, true, false><<<dim3(8, 8, 32), 256, SMEM_BYTES>>>(T, P, nullptr, F, CI_, N_, N_, sCi, sCi, sF);
    softmax_kernel<<<B_ * N_, 256>>>(F);
    // apply: y[b,o,n] = sum_m G[b,o,m] * attn[b,n,m]
    mm_tc<false, false, false><<<dim3(8, 2, 32), 256, SMEM_BYTES>>>(G, F, nullptr, Y, N_, N_, N_, sCi, sF, sCi);
    // z-conv: WY[b] (C x N) = Wz (C x Ci) * y[b] (Ci x N)
    mm_tc<false, true, true><<<dim3(8, 4, 32), 256, SMEM_BYTES>>>(Wz, Y, bz, WY, CI_, CI_, N_, 0, sCi, sC);
    // BN + residual
    bnstats_kernel<<<C_, 256>>>(WY, gamma, beta);
    finalize_kernel<<<(B_ * C_ * N_) / 4 / 256, 256>>>(WY, x, out);
}

// round 4
// speedup vs baseline: 3.3852x; 1.6441x over previous
#include <cuda_runtime.h>
#include <cstdint>

// Problem constants
#define B_  32
#define C_  512
#define CI_ 256
#define N_  1024   // H*W

// ---------------- static device scratch ----------------
__device__ float d_G [B_ * CI_ * N_];
__device__ float d_T [B_ * CI_ * N_];
__device__ float d_P [B_ * CI_ * N_];
__device__ float d_F [(size_t)B_ * N_ * N_];
__device__ float d_Y [B_ * CI_ * N_];
__device__ float d_WY[(size_t)B_ * C_ * N_];
__device__ float d_scale[C_];
__device__ float d_shift[C_];

// ---------------- helpers ----------------
static __device__ __forceinline__ uint32_t smem_u32(const void* p) {
    uint32_t a;
    asm("{ .reg .u64 t; cvta.to.shared.u64 t, %1; cvt.u32.u64 %0, t; }" : "=r"(a) : "l"(p));
    return a;
}

#define CP16(dst, src) \
    asm volatile("cp.async.cg.shared.global [%0], [%1], 16;" :: "r"(dst), "l"(src))
#define CP_COMMIT() asm volatile("cp.async.commit_group;" ::: "memory")
#define CP_WAIT1()  asm volatile("cp.async.wait_group 1;" ::: "memory")
#define CP_WAIT0()  asm volatile("cp.async.wait_group 0;" ::: "memory")

static __device__ __forceinline__ void mma_tf32(float* c, const float* a, const float* b) {
    asm volatile(
        "mma.sync.aligned.m16n8k8.row.col.f32.tf32.tf32.f32 "
        "{%0,%1,%2,%3},{%4,%5,%6,%7},{%8,%9},{%0,%1,%2,%3};"
        : "+f"(c[0]), "+f"(c[1]), "+f"(c[2]), "+f"(c[3])
        : "r"(__float_as_uint(a[0])), "r"(__float_as_uint(a[1])),
          "r"(__float_as_uint(a[2])), "r"(__float_as_uint(a[3])),
          "r"(__float_as_uint(b[0])), "r"(__float_as_uint(b[1])));
}

// Tile buffers: canonical layouts.
//   non-transposed input ([M,K] K-major): smem [m][k], row stride 36 floats (pad 4)
//   transposed input     ([K,M] M-contig): smem [k][m], row stride 136 floats (pad 8)
// Both fit in 18432 bytes.
#define TILE_B 18432
#define SMEM_BYTES (4 * TILE_B)

// stage one 128x32-float tile via 16B cp.async (128 threads, 8 ops/thread)
template <bool TR>
static __device__ __forceinline__ void stage_tile(const float* __restrict__ src, int ld,
                                                  uint32_t dst, int k0, int t, int l) {
    if constexpr (!TR) {
        const int m  = t >> 3;        // 0..15 (+16*i)
        const int c4 = t & 7;         // 16B chunk within 128B row
        const float* s = src + (size_t)m * ld + k0 + c4 * 4;
        uint32_t d = dst + m * 144 + c4 * 16;
#pragma unroll
        for (int i = 0; i < 8; ++i)
            CP16(d + i * 16 * 144, s + (size_t)i * 16 * ld);
    } else {
        const int kk = t >> 5;        // 0..3 (+4*i)
        const float* s = src + (size_t)(k0 + kk) * ld + l * 4;
        uint32_t d = dst + kk * 544 + l * 16;
#pragma unroll
        for (int i = 0; i < 8; ++i)
            CP16(d + i * 4 * 544, s + (size_t)i * 4 * ld);
    }
}

// ---------------- canonical 128x128 tensor-core tf32 GEMM ----------------
// Out[b, m0+0..127, n0+0..127] (+= bias[m]) = sum_k A'[m,k] * B'[n,k]
//   TA/TB=false: operand global [rows, K] K-major;  true: [K, rows] rows-contig
// 128 threads, 4 warps in 2x2, warp tile 64x64.
template <bool TA, bool TB, bool BIAS>
__global__ __launch_bounds__(128, 2)
void mm_tc(const float* __restrict__ A, const float* __restrict__ Bm,
           const float* __restrict__ bias, float* __restrict__ Out,
           int K, int ldA, int ldB,
           long strideA, long strideB, long strideO) {
    extern __shared__ __align__(128) char smem[];
    const uint32_t sb = smem_u32(smem);
    const int t = threadIdx.x;
    const int l = t & 31;
    const int w = t >> 5;
    const int wm = (w >> 1) * 64;    // warp m offset
    const int wn = (w & 1) * 64;     // warp n offset
    const int m0 = blockIdx.y * 128;
    const int n0 = blockIdx.x * 128;
    const float* Ab = (TA ? A  + m0 : A  + (size_t)m0 * ldA) + (size_t)blockIdx.z * strideA;
    const float* Bb = (TB ? Bm + n0 : Bm + (size_t)n0 * ldB) + (size_t)blockIdx.z * strideB;
    float*       Ob = Out + (size_t)blockIdx.z * strideO;

    float acc[4][8][4];
#pragma unroll
    for (int mt = 0; mt < 4; ++mt)
#pragma unroll
        for (int nt = 0; nt < 8; ++nt)
#pragma unroll
            for (int q = 0; q < 4; ++q) acc[mt][nt][q] = 0.f;

    const int S = K / 32;
    stage_tile<TA>(Ab, ldA, sb,              0, t, l);
    stage_tile<TB>(Bb, ldB, sb + 2 * TILE_B, 0, t, l);
    CP_COMMIT();

    for (int s = 0; s < S; ++s) {
        if (s + 1 < S) {
            const int nb = (s + 1) & 1;
            stage_tile<TA>(Ab, ldA, sb + nb * TILE_B,       (s + 1) * 32, t, l);
            stage_tile<TB>(Bb, ldB, sb + (2 + nb) * TILE_B, (s + 1) * 32, t, l);
            CP_COMMIT();
            CP_WAIT1();
        } else {
            CP_WAIT0();
        }
        __syncthreads();

        const int sel = s & 1;
        const float* As = (const float*)(smem + sel * TILE_B);
        const float* Bs = (const float*)(smem + (2 + sel) * TILE_B);
        const int ar = l >> 2;        // 0..7
        const int al = l & 3;         // 0..3
#pragma unroll
        for (int ks = 0; ks < 4; ++ks) {
            const int ac = ks * 8 + al;
            float af[4][4];
#pragma unroll
            for (int mt = 0; mt < 4; ++mt) {
                const int r = wm + mt * 16 + ar;
                if constexpr (TA) {
                    af[mt][0] = As[ac * 136 + r];
                    af[mt][1] = As[ac * 136 + r + 8];
                    af[mt][2] = As[(ac + 4) * 136 + r];
                    af[mt][3] = As[(ac + 4) * 136 + r + 8];
                } else {
                    af[mt][0] = As[r * 36 + ac];
                    af[mt][1] = As[(r + 8) * 36 + ac];
                    af[mt][2] = As[r * 36 + ac + 4];
                    af[mt][3] = As[(r + 8) * 36 + ac + 4];
                }
            }
            float bf[8][2];
#pragma unroll
            for (int nt = 0; nt < 8; ++nt) {
                const int r = wn + nt * 8 + ar;
                if constexpr (TB) {
                    bf[nt][0] = Bs[ac * 136 + r];
                    bf[nt][1] = Bs[(ac + 4) * 136 + r];
                } else {
                    bf[nt][0] = Bs[r * 36 + ac];
                    bf[nt][1] = Bs[r * 36 + ac + 4];
                }
            }
#pragma unroll
            for (int mt = 0; mt < 4; ++mt)
#pragma unroll
                for (int nt = 0; nt < 8; ++nt)
                    mma_tf32(acc[mt][nt], af[mt], bf[nt]);
        }
        __syncthreads();
    }

    // ---- epilogue: direct global stores ----
#pragma unroll
    for (int mt = 0; mt < 4; ++mt) {
        const int row = m0 + wm + mt * 16 + (l >> 2);
        float bv0 = 0.f, bv1 = 0.f;
        if constexpr (BIAS) { bv0 = bias[row]; bv1 = bias[row + 8]; }
#pragma unroll
        for (int nt = 0; nt < 8; ++nt) {
            const int col = n0 + wn + nt * 8 + (l & 3) * 2;
            float2 v0 = {acc[mt][nt][0] + bv0, acc[mt][nt][1] + bv0};
            float2 v1 = {acc[mt][nt][2] + bv1, acc[mt][nt][3] + bv1};
            *(float2*)&Ob[(size_t)row * N_ + col]       = v0;
            *(float2*)&Ob[(size_t)(row + 8) * N_ + col] = v1;
        }
    }
}

// ---------------- row softmax over last dim (rows of 1024) ----------------
__global__ __launch_bounds__(256)
void softmax_kernel(float* __restrict__ F) {
    size_t row = blockIdx.x;
    float4* p = (float4*)(F + row * (size_t)N_);
    int t = threadIdx.x;
    float4 v = p[t];
    float m = fmaxf(fmaxf(v.x, v.y), fmaxf(v.z, v.w));
#pragma unroll
    for (int o = 16; o; o >>= 1) m = fmaxf(m, __shfl_xor_sync(~0u, m, o));
    __shared__ float smax[8], ssum[8];
    if ((t & 31) == 0) smax[t >> 5] = m;
    __syncthreads();
    float mm = smax[0];
#pragma unroll
    for (int i = 1; i < 8; ++i) mm = fmaxf(mm, smax[i]);
    v.x = __expf(v.x - mm); v.y = __expf(v.y - mm);
    v.z = __expf(v.z - mm); v.w = __expf(v.w - mm);
    float s = v.x + v.y + v.z + v.w;
#pragma unroll
    for (int o = 16; o; o >>= 1) s += __shfl_xor_sync(~0u, s, o);
    if ((t & 31) == 0) ssum[t >> 5] = s;
    __syncthreads();
    float tot = 0.f;
#pragma unroll
    for (int i = 0; i < 8; ++i) tot += ssum[i];
    float inv = 1.0f / tot;
    v.x *= inv; v.y *= inv; v.z *= inv; v.w *= inv;
    p[t] = v;
}

// ---------------- BatchNorm stats -> fused scale/shift ----------------
__global__ __launch_bounds__(256)
void bnstats_kernel(const float* __restrict__ WY, const float* __restrict__ gamma,
                    const float* __restrict__ beta) {
    int c = blockIdx.x;
    int t = threadIdx.x;
    float s = 0.f, s2 = 0.f;
    for (int b = 0; b < B_; ++b) {
        const float* p = WY + ((size_t)b * C_ + c) * N_;
        for (int n = t; n < N_; n += 256) {
            float v = p[n];
            s += v; s2 += v * v;
        }
    }
#pragma unroll
    for (int o = 16; o; o >>= 1) {
        s  += __shfl_xor_sync(~0u, s,  o);
        s2 += __shfl_xor_sync(~0u, s2, o);
    }
    __shared__ float ss[8], ss2[8];
    if ((t & 31) == 0) { ss[t >> 5] = s; ss2[t >> 5] = s2; }
    __syncthreads();
    if (t == 0) {
        float S = 0.f, S2 = 0.f;
#pragma unroll
        for (int i = 0; i < 8; ++i) { S += ss[i]; S2 += ss2[i]; }
        const float invN = 1.0f / (float)(B_ * N_);
        float mean = S * invN;
        float var  = S2 * invN - mean * mean;
        float inv  = rsqrtf(var + 1e-5f);
        float sc   = gamma[c] * inv;
        d_scale[c] = sc;
        d_shift[c] = beta[c] - mean * sc;
    }
}

// ---------------- finalize: out = w_y*scale + shift + x ----------------
__global__ __launch_bounds__(256)
void finalize_kernel(const float* __restrict__ WY, const float* __restrict__ x,
                     float* __restrict__ out) {
    size_t i4 = (size_t)blockIdx.x * 256 + threadIdx.x;
    int c = (int)((i4 >> 8) & (C_ - 1));
    float sc = d_scale[c], sh = d_shift[c];
    float4 w  = ((const float4*)WY)[i4];
    float4 xv = ((const float4*)x)[i4];
    float4 o;
    o.x = w.x * sc + sh + xv.x;
    o.y = w.y * sc + sh + xv.y;
    o.z = w.z * sc + sh + xv.z;
    o.w = w.w * sc + sh + xv.w;
    ((float4*)out)[i4] = o;
}

// ---------------- launch ----------------
extern "C" void kernel_launch(void* const* d_in, const int* in_sizes, int n_in,
                              void* d_out, int out_size) {
    const float* x     = (const float*)d_in[0];
    const float* Wg    = (const float*)d_in[1];
    const float* bg    = (const float*)d_in[2];
    const float* Wt    = (const float*)d_in[3];
    const float* bt    = (const float*)d_in[4];
    const float* Wp    = (const float*)d_in[5];
    const float* bp    = (const float*)d_in[6];
    const float* Wz    = (const float*)d_in[7];
    const float* bz    = (const float*)d_in[8];
    const float* gamma = (const float*)d_in[9];
    const float* beta  = (const float*)d_in[10];
    float* out = (float*)d_out;

    float *G, *T, *P, *F, *Y, *WY;
    cudaGetSymbolAddress((void**)&G,  d_G);
    cudaGetSymbolAddress((void**)&T,  d_T);
    cudaGetSymbolAddress((void**)&P,  d_P);
    cudaGetSymbolAddress((void**)&F,  d_F);
    cudaGetSymbolAddress((void**)&Y,  d_Y);
    cudaGetSymbolAddress((void**)&WY, d_WY);

    cudaFuncSetAttribute(mm_tc<false, true,  true >, cudaFuncAttributeMaxDynamicSharedMemorySize, SMEM_BYTES);
    cudaFuncSetAttribute(mm_tc<true,  true,  false>, cudaFuncAttributeMaxDynamicSharedMemorySize, SMEM_BYTES);
    cudaFuncSetAttribute(mm_tc<false, false, false>, cudaFuncAttributeMaxDynamicSharedMemorySize, SMEM_BYTES);

    const long sX  = (long)C_  * N_;
    const long sCi = (long)CI_ * N_;
    const long sF  = (long)N_  * N_;
    const long sC  = (long)C_  * N_;

    // projections: Out[b] (Ci x N) = W (Ci x C) * x[b] (C x N)
    mm_tc<false, true, true><<<dim3(8, 2, 32), 128, SMEM_BYTES>>>(Wg, x, bg, G, C_, C_, N_, 0, sX, sCi);
    mm_tc<false, true, true><<<dim3(8, 2, 32), 128, SMEM_BYTES>>>(Wt, x, bt, T, C_, C_, N_, 0, sX, sCi);
    mm_tc<false, true, true><<<dim3(8, 2, 32), 128, SMEM_BYTES>>>(Wp, x, bp, P, C_, C_, N_, 0, sX, sCi);
    // scores: f[b,n,m] = sum_c T[b,c,n] * P[b,c,m]
    mm_tc<true, true, false><<<dim3(8, 8, 32), 128, SMEM_BYTES>>>(T, P, nullptr, F, CI_, N_, N_, sCi, sCi, sF);
    softmax_kernel<<<B_ * N_, 256>>>(F);
    // apply: y[b,o,n] = sum_m G[b,o,m] * attn[b,n,m]
    mm_tc<false, false, false><<<dim3(8, 2, 32), 128, SMEM_BYTES>>>(G, F, nullptr, Y, N_, N_, N_, sCi, sF, sCi);
    // z-conv: WY[b] (C x N) = Wz (C x Ci) * y[b] (Ci x N)
    mm_tc<false, true, true><<<dim3(8, 4, 32), 128, SMEM_BYTES>>>(Wz, Y, bz, WY, CI_, CI_, N_, 0, sCi, sC);
    // BN + residual
    bnstats_kernel<<<C_, 256>>>(WY, gamma, beta);
    finalize_kernel<<<(B_ * C_ * N_) / 4 / 256, 256>>>(WY, x, out);
}

// round 5
// speedup vs baseline: 5.3984x; 1.5947x over previous
#include <cuda_runtime.h>
#include <cuda_fp16.h>
#include <cstdint>

// Problem constants
#define B_  32
#define C_  512
#define CI_ 256
#define N_  1024   // H*W

// ---------------- static device scratch ----------------
__device__ __align__(128) __half d_x16[(size_t)B_ * C_ * N_];
__device__ __align__(128) __half d_Wg16[CI_ * C_];
__device__ __align__(128) __half d_Wt16[CI_ * C_];
__device__ __align__(128) __half d_Wp16[CI_ * C_];
__device__ __align__(128) __half d_Wz16[C_ * CI_];
__device__ __align__(128) __half d_Gh[(size_t)B_ * CI_ * N_];
__device__ __align__(128) __half d_Th[(size_t)B_ * CI_ * N_];
__device__ __align__(128) __half d_Ph[(size_t)B_ * CI_ * N_];
__device__ __align__(128) float  d_F [(size_t)B_ * N_ * N_];     // logits fp32
__device__ __align__(128) __half d_Pr[(size_t)B_ * N_ * N_];     // probs fp16
__device__ __align__(128) __half d_Yh[(size_t)B_ * CI_ * N_];
__device__ __align__(128) __half d_WYh[(size_t)B_ * C_ * N_];
__device__ float d_scale[C_];
__device__ float d_shift[C_];

// ---------------- helpers ----------------
static __device__ __forceinline__ uint32_t smem_u32(const void* p) {
    uint32_t a;
    asm("{ .reg .u64 t; cvta.to.shared.u64 t, %1; cvt.u32.u64 %0, t; }" : "=r"(a) : "l"(p));
    return a;
}

#define CP16(dst, src) \
    asm volatile("cp.async.cg.shared.global [%0], [%1], 16;" :: "r"(dst), "l"(src))
#define CP_COMMIT() asm volatile("cp.async.commit_group;" ::: "memory")
#define CP_WAIT1()  asm volatile("cp.async.wait_group 1;" ::: "memory")
#define CP_WAIT0()  asm volatile("cp.async.wait_group 0;" ::: "memory")

#define LDSM4(r, addr) \
    asm volatile("ldmatrix.sync.aligned.m8n8.x4.shared.b16 {%0,%1,%2,%3}, [%4];" \
        : "=r"((r)[0]), "=r"((r)[1]), "=r"((r)[2]), "=r"((r)[3]) : "r"(addr))
#define LDSM4T(r, addr) \
    asm volatile("ldmatrix.sync.aligned.m8n8.x4.trans.shared.b16 {%0,%1,%2,%3}, [%4];" \
        : "=r"((r)[0]), "=r"((r)[1]), "=r"((r)[2]), "=r"((r)[3]) : "r"(addr))

static __device__ __forceinline__ void mma_f16(float* c, const uint32_t* a, const uint32_t* b) {
    asm volatile(
        "mma.sync.aligned.m16n8k16.row.col.f32.f16.f16.f32 "
        "{%0,%1,%2,%3},{%4,%5,%6,%7},{%8,%9},{%0,%1,%2,%3};"
        : "+f"(c[0]), "+f"(c[1]), "+f"(c[2]), "+f"(c[3])
        : "r"(a[0]), "r"(a[1]), "r"(a[2]), "r"(a[3]), "r"(b[0]), "r"(b[1]));
}

// SMEM: A0 [0,16K) A1 [16K,32K) B0 [32K,48K) B1 [48K,64K)
// non-trans tile: 128 rows x 64 k fp16, 128B rows, chunk swizzle c^(r&7)
// trans tile:     64 k-rows x 128 cols fp16, 256B rows, chunk swizzle c^((k&7)<<1)
#define SMEM_BYTES 65536

template <bool TR>
static __device__ __forceinline__ void stage_tile(const __half* __restrict__ src, int ld,
                                                  uint32_t dst, int k0, int t) {
#pragma unroll
    for (int i = 0; i < 4; ++i) {
        int idx = t + i * 256;
        if constexpr (!TR) {
            int r = idx >> 3, c = idx & 7;
            const __half* s = src + (size_t)r * ld + k0 + c * 8;
            CP16(dst + r * 128 + ((c ^ (r & 7)) << 4), s);
        } else {
            int k = idx >> 4, c = idx & 15;
            const __half* s = src + (size_t)(k0 + k) * ld + c * 8;
            CP16(dst + k * 256 + ((c ^ ((k & 7) << 1)) << 4), s);
        }
    }
}

// ---------------- canonical 128x128 fp16 tensor-core GEMM ----------------
// Out[b, m0+0..127, n0+0..127] (+= bias[m]) = sum_k A'[m,k] * B'[n,k]
//   TA/TB=false: operand global [rows, K] K-major;  true: [K, rows] rows-contig
// 256 threads, 8 warps (2 m x 4 n), warp tile 64x32, K-chunk 64.
template <bool TA, bool TB, bool OUT16, bool BIAS>
__global__ __launch_bounds__(256, 2)
void mm_f16(const __half* __restrict__ A, const __half* __restrict__ Bm,
            const float* __restrict__ bias, void* __restrict__ Out,
            int K, int ldA, int ldB,
            long strideA, long strideB, long strideO) {
    extern __shared__ __align__(128) char smem[];
    const uint32_t sb = smem_u32(smem);
    const int t = threadIdx.x;
    const int l = t & 31;
    const int w = t >> 5;
    const int wm = (w >> 2) * 64;
    const int wn = (w & 3) * 32;
    const int m0 = blockIdx.y * 128;
    const int n0 = blockIdx.x * 128;
    const __half* Ab = A  + (size_t)blockIdx.z * strideA + (TA ? m0 : (size_t)m0 * ldA);
    const __half* Bb = Bm + (size_t)blockIdx.z * strideB + (TB ? n0 : (size_t)n0 * ldB);

    float acc[4][4][4];
#pragma unroll
    for (int mt = 0; mt < 4; ++mt)
#pragma unroll
        for (int nt = 0; nt < 4; ++nt)
#pragma unroll
            for (int q = 0; q < 4; ++q) acc[mt][nt][q] = 0.f;

    const int S = K / 64;
    stage_tile<TA>(Ab, ldA, sb,         0, t);
    stage_tile<TB>(Bb, ldB, sb + 32768, 0, t);
    CP_COMMIT();

    for (int s = 0; s < S; ++s) {
        if (s + 1 < S) {
            const int nb = (s + 1) & 1;
            stage_tile<TA>(Ab, ldA, sb + nb * 16384,         (s + 1) * 64, t);
            stage_tile<TB>(Bb, ldB, sb + 32768 + nb * 16384, (s + 1) * 64, t);
            CP_COMMIT();
            CP_WAIT1();
        } else {
            CP_WAIT0();
        }
        __syncthreads();

        const uint32_t abase = sb + (s & 1) * 16384;
        const uint32_t bbase = sb + 32768 + (s & 1) * 16384;
#pragma unroll
        for (int ks = 0; ks < 4; ++ks) {
            uint32_t af[4][4], bf[2][4];
#pragma unroll
            for (int mt = 0; mt < 4; ++mt) {
                if constexpr (!TA) {
                    int row = wm + mt * 16 + (l & 7) + ((l >> 3) & 1) * 8;
                    int ch  = ks * 2 + (l >> 4);
                    LDSM4(af[mt], abase + row * 128 + ((ch ^ (row & 7)) << 4));
                } else {
                    int kr = ks * 16 + (l & 7) + (l >> 4) * 8;
                    int ch = ((wm + mt * 16) >> 3) + ((l >> 3) & 1);
                    LDSM4T(af[mt], abase + kr * 256 + ((ch ^ ((kr & 7) << 1)) << 4));
                }
            }
#pragma unroll
            for (int np = 0; np < 2; ++np) {
                if constexpr (!TB) {
                    int row = wn + np * 16 + (l & 7) + (l >> 4) * 8;
                    int ch  = ks * 2 + ((l >> 3) & 1);
                    LDSM4(bf[np], bbase + row * 128 + ((ch ^ (row & 7)) << 4));
                } else {
                    int kr = ks * 16 + (l & 7) + ((l >> 3) & 1) * 8;
                    int ch = ((wn + np * 16) >> 3) + (l >> 4);
                    LDSM4T(bf[np], bbase + kr * 256 + ((ch ^ ((kr & 7) << 1)) << 4));
                }
            }
#pragma unroll
            for (int mt = 0; mt < 4; ++mt)
#pragma unroll
                for (int nt = 0; nt < 4; ++nt)
                    mma_f16(acc[mt][nt], af[mt], &bf[nt >> 1][(nt & 1) * 2]);
        }
        __syncthreads();
    }

    // ---- epilogue ----
#pragma unroll
    for (int mt = 0; mt < 4; ++mt) {
        const int row = m0 + wm + mt * 16 + (l >> 2);
        float bv0 = 0.f, bv1 = 0.f;
        if constexpr (BIAS) { bv0 = bias[row]; bv1 = bias[row + 8]; }
#pragma unroll
        for (int nt = 0; nt < 4; ++nt) {
            const int col = n0 + wn + nt * 8 + 2 * (l & 3);
            if constexpr (OUT16) {
                __half* Ob = (__half*)Out + (size_t)blockIdx.z * strideO;
                *(__half2*)(Ob + (size_t)row * N_ + col) =
                    __floats2half2_rn(acc[mt][nt][0] + bv0, acc[mt][nt][1] + bv0);
                *(__half2*)(Ob + (size_t)(row + 8) * N_ + col) =
                    __floats2half2_rn(acc[mt][nt][2] + bv1, acc[mt][nt][3] + bv1);
            } else {
                float* Ob = (float*)Out + (size_t)blockIdx.z * strideO;
                *(float2*)(Ob + (size_t)row * N_ + col) =
                    make_float2(acc[mt][nt][0] + bv0, acc[mt][nt][1] + bv0);
                *(float2*)(Ob + (size_t)(row + 8) * N_ + col) =
                    make_float2(acc[mt][nt][2] + bv1, acc[mt][nt][3] + bv1);
            }
        }
    }
}

// ---------------- fp32 -> fp16 conversion ----------------
__global__ __launch_bounds__(256)
void cvt_kernel(const float* __restrict__ src, __half* __restrict__ dst, int n4) {
    int i = blockIdx.x * 256 + threadIdx.x;
    if (i < n4) {
        float4 v = ((const float4*)src)[i];
        __half2 h0 = __floats2half2_rn(v.x, v.y);
        __half2 h1 = __floats2half2_rn(v.z, v.w);
        uint2 u = { *(uint32_t*)&h0, *(uint32_t*)&h1 };
        ((uint2*)dst)[i] = u;
    }
}

// ---------------- row softmax: fp32 logits -> fp16 probs ----------------
__global__ __launch_bounds__(256)
void softmax_kernel(const float* __restrict__ F, __half* __restrict__ Pr) {
    size_t row = blockIdx.x;
    const float4* p = (const float4*)(F + row * (size_t)N_);
    int t = threadIdx.x;
    float4 v = p[t];
    float m = fmaxf(fmaxf(v.x, v.y), fmaxf(v.z, v.w));
#pragma unroll
    for (int o = 16; o; o >>= 1) m = fmaxf(m, __shfl_xor_sync(~0u, m, o));
    __shared__ float smax[8], ssum[8];
    if ((t & 31) == 0) smax[t >> 5] = m;
    __syncthreads();
    float mm = smax[0];
#pragma unroll
    for (int i = 1; i < 8; ++i) mm = fmaxf(mm, smax[i]);
    v.x = __expf(v.x - mm); v.y = __expf(v.y - mm);
    v.z = __expf(v.z - mm); v.w = __expf(v.w - mm);
    float s = v.x + v.y + v.z + v.w;
#pragma unroll
    for (int o = 16; o; o >>= 1) s += __shfl_xor_sync(~0u, s, o);
    if ((t & 31) == 0) ssum[t >> 5] = s;
    __syncthreads();
    float tot = 0.f;
#pragma unroll
    for (int i = 0; i < 8; ++i) tot += ssum[i];
    float inv = 1.0f / tot;
    __half2 h0 = __floats2half2_rn(v.x * inv, v.y * inv);
    __half2 h1 = __floats2half2_rn(v.z * inv, v.w * inv);
    uint2 u = { *(uint32_t*)&h0, *(uint32_t*)&h1 };
    ((uint2*)(Pr + row * (size_t)N_))[t] = u;
}

// ---------------- BatchNorm stats on fp16 WY -> fused scale/shift ----------------
__global__ __launch_bounds__(256)
void bnstats_kernel(const __half* __restrict__ WY, const float* __restrict__ gamma,
                    const float* __restrict__ beta) {
    int c = blockIdx.x;
    int t = threadIdx.x;
    float s = 0.f, s2 = 0.f;
    for (int b = 0; b < B_; ++b) {
        const __half2* p = (const __half2*)(WY + ((size_t)b * C_ + c) * N_);
        for (int n = t; n < N_ / 2; n += 256) {
            float2 v = __half22float2(p[n]);
            s += v.x + v.y; s2 += v.x * v.x + v.y * v.y;
        }
    }
#pragma unroll
    for (int o = 16; o; o >>= 1) {
        s  += __shfl_xor_sync(~0u, s,  o);
        s2 += __shfl_xor_sync(~0u, s2, o);
    }
    __shared__ float ss[8], ss2[8];
    if ((t & 31) == 0) { ss[t >> 5] = s; ss2[t >> 5] = s2; }
    __syncthreads();
    if (t == 0) {
        float S = 0.f, S2 = 0.f;
#pragma unroll
        for (int i = 0; i < 8; ++i) { S += ss[i]; S2 += ss2[i]; }
        const float invN = 1.0f / (float)(B_ * N_);
        float mean = S * invN;
        float var  = S2 * invN - mean * mean;
        float inv  = rsqrtf(var + 1e-5f);
        float sc   = gamma[c] * inv;
        d_scale[c] = sc;
        d_shift[c] = beta[c] - mean * sc;
    }
}

// ---------------- finalize: out = w_y*scale + shift + x (x fp32) ----------------
__global__ __launch_bounds__(256)
void finalize_kernel(const __half* __restrict__ WY, const float* __restrict__ x,
                     float* __restrict__ out) {
    size_t i4 = (size_t)blockIdx.x * 256 + threadIdx.x;   // 4-elem index
    int c = (int)((i4 >> 8) & (C_ - 1));                  // 256 quads per (b,c) row
    float sc = d_scale[c], sh = d_shift[c];
    uint2 u = ((const uint2*)WY)[i4];
    float2 w0 = __half22float2(*(__half2*)&u.x);
    float2 w1 = __half22float2(*(__half2*)&u.y);
    float4 xv = ((const float4*)x)[i4];
    float4 o;
    o.x = w0.x * sc + sh + xv.x;
    o.y = w0.y * sc + sh + xv.y;
    o.z = w1.x * sc + sh + xv.z;
    o.w = w1.y * sc + sh + xv.w;
    ((float4*)out)[i4] = o;
}

// ---------------- launch ----------------
extern "C" void kernel_launch(void* const* d_in, const int* in_sizes, int n_in,
                              void* d_out, int out_size) {
    const float* x     = (const float*)d_in[0];
    const float* Wg    = (const float*)d_in[1];
    const float* bg    = (const float*)d_in[2];
    const float* Wt    = (const float*)d_in[3];
    const float* bt    = (const float*)d_in[4];
    const float* Wp    = (const float*)d_in[5];
    const float* bp    = (const float*)d_in[6];
    const float* Wz    = (const float*)d_in[7];
    const float* bz    = (const float*)d_in[8];
    const float* gamma = (const float*)d_in[9];
    const float* beta  = (const float*)d_in[10];
    float* out = (float*)d_out;

    __half *x16, *Wg16, *Wt16, *Wp16, *Wz16, *Gh, *Th, *Ph, *Pr, *Yh, *WYh;
    float *F;
    cudaGetSymbolAddress((void**)&x16,  d_x16);
    cudaGetSymbolAddress((void**)&Wg16, d_Wg16);
    cudaGetSymbolAddress((void**)&Wt16, d_Wt16);
    cudaGetSymbolAddress((void**)&Wp16, d_Wp16);
    cudaGetSymbolAddress((void**)&Wz16, d_Wz16);
    cudaGetSymbolAddress((void**)&Gh,   d_Gh);
    cudaGetSymbolAddress((void**)&Th,   d_Th);
    cudaGetSymbolAddress((void**)&Ph,   d_Ph);
    cudaGetSymbolAddress((void**)&F,    d_F);
    cudaGetSymbolAddress((void**)&Pr,   d_Pr);
    cudaGetSymbolAddress((void**)&Yh,   d_Yh);
    cudaGetSymbolAddress((void**)&WYh,  d_WYh);

    cudaFuncSetAttribute(mm_f16<false, true,  true,  true >, cudaFuncAttributeMaxDynamicSharedMemorySize, SMEM_BYTES);
    cudaFuncSetAttribute(mm_f16<true,  true,  false, false>, cudaFuncAttributeMaxDynamicSharedMemorySize, SMEM_BYTES);
    cudaFuncSetAttribute(mm_f16<false, false, true,  false>, cudaFuncAttributeMaxDynamicSharedMemorySize, SMEM_BYTES);

    const long sCi = (long)CI_ * N_;
    const long sF  = (long)N_  * N_;
    const long sC  = (long)C_  * N_;

    // fp16 conversions
    cvt_kernel<<<(B_ * C_ * N_ / 4 + 255) / 256, 256>>>(x,  x16,  B_ * C_ * N_ / 4);
    cvt_kernel<<<(CI_ * C_ / 4 + 255) / 256, 256>>>(Wg, Wg16, CI_ * C_ / 4);
    cvt_kernel<<<(CI_ * C_ / 4 + 255) / 256, 256>>>(Wt, Wt16, CI_ * C_ / 4);
    cvt_kernel<<<(CI_ * C_ / 4 + 255) / 256, 256>>>(Wp, Wp16, CI_ * C_ / 4);
    cvt_kernel<<<(C_ * CI_ / 4 + 255) / 256, 256>>>(Wz, Wz16, C_ * CI_ / 4);

    // projections: Out[b] (Ci x N) = W (Ci x C) * x[b] (C x N)
    mm_f16<false, true, true, true><<<dim3(8, 2, 32), 256, SMEM_BYTES>>>(Wg16, x16, bg, Gh, C_, C_, N_, 0, sC, sCi);
    mm_f16<false, true, true, true><<<dim3(8, 2, 32), 256, SMEM_BYTES>>>(Wt16, x16, bt, Th, C_, C_, N_, 0, sC, sCi);
    mm_f16<false, true, true, true><<<dim3(8, 2, 32), 256, SMEM_BYTES>>>(Wp16, x16, bp, Ph, C_, C_, N_, 0, sC, sCi);
    // scores: f[b,n,m] = sum_c T[b,c,n] * P[b,c,m]  -> fp32 logits
    mm_f16<true, true, false, false><<<dim3(8, 8, 32), 256, SMEM_BYTES>>>(Th, Ph, nullptr, F, CI_, N_, N_, sCi, sCi, sF);
    softmax_kernel<<<B_ * N_, 256>>>(F, Pr);
    // apply: y[b,o,n] = sum_m G[b,o,m] * attn[b,n,m]
    mm_f16<false, false, true, false><<<dim3(8, 2, 32), 256, SMEM_BYTES>>>(Gh, Pr, nullptr, Yh, N_, N_, N_, sCi, sF, sCi);
    // z-conv: WY[b] (C x N) = Wz (C x Ci) * y[b] (Ci x N)
    mm_f16<false, true, true, true><<<dim3(8, 4, 32), 256, SMEM_BYTES>>>(Wz16, Yh, bz, WYh, CI_, CI_, N_, 0, sCi, sC);
    // BN + residual
    bnstats_kernel<<<C_, 256>>>(WYh, gamma, beta);
    finalize_kernel<<<(B_ * C_ * N_) / 4 / 256, 256>>>(WYh, x, out);
}

// round 6
// speedup vs baseline: 6.4188x; 1.1890x over previous
#include <cuda_runtime.h>
#include <cuda_fp16.h>
#include <cstdint>

// Problem constants
#define B_  32
#define C_  512
#define CI_ 256
#define N_  1024   // H*W

// ---------------- static device scratch ----------------
__device__ __align__(128) __half d_x16[(size_t)B_ * C_ * N_];
__device__ __align__(128) __half d_Wg16[CI_ * C_];
__device__ __align__(128) __half d_Wt16[CI_ * C_];
__device__ __align__(128) __half d_Wp16[CI_ * C_];
__device__ __align__(128) __half d_Wz16[C_ * CI_];
__device__ __align__(128) __half d_Gh[(size_t)B_ * CI_ * N_];   // g   [b][Ci][N]
__device__ __align__(128) __half d_Th[(size_t)B_ * CI_ * N_];   // theta [b][Ci][N]
__device__ __align__(128) __half d_Ph[(size_t)B_ * CI_ * N_];   // phi [b][Ci][N]
__device__ __align__(128) __half d_Yh[(size_t)B_ * N_ * CI_];   // y [b][N][Ci]  (n rows, ci contig)
__device__ __align__(128) __half d_WYh[(size_t)B_ * C_ * N_];
__device__ float d_scale[C_];
__device__ float d_shift[C_];

// ---------------- helpers ----------------
static __device__ __forceinline__ uint32_t smem_u32(const void* p) {
    uint32_t a;
    asm("{ .reg .u64 t; cvta.to.shared.u64 t, %1; cvt.u32.u64 %0, t; }" : "=r"(a) : "l"(p));
    return a;
}

#define CP16(dst, src) \
    asm volatile("cp.async.cg.shared.global [%0], [%1], 16;" :: "r"(dst), "l"(src))
#define CP_COMMIT() asm volatile("cp.async.commit_group;" ::: "memory")
#define CP_WAIT0()  asm volatile("cp.async.wait_group 0;" ::: "memory")
#define CP_WAIT1()  asm volatile("cp.async.wait_group 1;" ::: "memory")
#define CP_WAIT2()  asm volatile("cp.async.wait_group 2;" ::: "memory")

#define LDSM4(r, addr) \
    asm volatile("ldmatrix.sync.aligned.m8n8.x4.shared.b16 {%0,%1,%2,%3}, [%4];" \
        : "=r"((r)[0]), "=r"((r)[1]), "=r"((r)[2]), "=r"((r)[3]) : "r"(addr))
#define LDSM4T(r, addr) \
    asm volatile("ldmatrix.sync.aligned.m8n8.x4.trans.shared.b16 {%0,%1,%2,%3}, [%4];" \
        : "=r"((r)[0]), "=r"((r)[1]), "=r"((r)[2]), "=r"((r)[3]) : "r"(addr))

static __device__ __forceinline__ void mma_f16(float* c, const uint32_t* a, const uint32_t* b) {
    asm volatile(
        "mma.sync.aligned.m16n8k16.row.col.f32.f16.f16.f32 "
        "{%0,%1,%2,%3},{%4,%5,%6,%7},{%8,%9},{%0,%1,%2,%3};"
        : "+f"(c[0]), "+f"(c[1]), "+f"(c[2]), "+f"(c[3])
        : "r"(a[0]), "r"(a[1]), "r"(a[2]), "r"(a[3]), "r"(b[0]), "r"(b[1]));
}

static __device__ __forceinline__ uint32_t h2pack(float a, float b) {
    __half2 h = __floats2half2_rn(a, b);
    return *(uint32_t*)&h;
}

// =====================================================================
//                         GEMM (projections / z-conv)
// =====================================================================
// SMEM: A0 [0,16K) A1 [16K,32K) B0 [32K,48K) B1 [48K,64K)
// non-trans tile: 128 rows x 64 k fp16, 128B rows, chunk swizzle c^(r&7)
// trans tile:     64 k-rows x 128 cols fp16, 256B rows, chunk swizzle c^(k&7)
#define SMEM_BYTES 65536

template <bool TR>
static __device__ __forceinline__ void stage_tile(const __half* __restrict__ src, int ld,
                                                  uint32_t dst, int k0, int t) {
#pragma unroll
    for (int i = 0; i < 4; ++i) {
        int idx = t + i * 256;
        if constexpr (!TR) {
            int r = idx >> 3, c = idx & 7;
            const __half* s = src + (size_t)r * ld + k0 + c * 8;
            CP16(dst + r * 128 + ((c ^ (r & 7)) << 4), s);
        } else {
            int k = idx >> 4, c = idx & 15;
            const __half* s = src + (size_t)(k0 + k) * ld + c * 8;
            CP16(dst + k * 256 + ((c ^ (k & 7)) << 4), s);
        }
    }
}

template <bool TA, bool TB, bool BIAS>
__global__ __launch_bounds__(256, 2)
void mm_f16(const __half* __restrict__ A, const __half* __restrict__ Bm,
            const float* __restrict__ bias, __half* __restrict__ Out,
            int K, int ldA, int ldB,
            long strideA, long strideB, long strideO) {
    extern __shared__ __align__(128) char smem[];
    const uint32_t sb = smem_u32(smem);
    const int t = threadIdx.x;
    const int l = t & 31;
    const int w = t >> 5;
    const int wm = (w >> 2) * 64;
    const int wn = (w & 3) * 32;
    const int m0 = blockIdx.y * 128;
    const int n0 = blockIdx.x * 128;
    const __half* Ab = A  + (size_t)blockIdx.z * strideA + (TA ? m0 : (size_t)m0 * ldA);
    const __half* Bb = Bm + (size_t)blockIdx.z * strideB + (TB ? n0 : (size_t)n0 * ldB);

    float acc[4][4][4];
#pragma unroll
    for (int mt = 0; mt < 4; ++mt)
#pragma unroll
        for (int nt = 0; nt < 4; ++nt)
#pragma unroll
            for (int q = 0; q < 4; ++q) acc[mt][nt][q] = 0.f;

    const int S = K / 64;
    stage_tile<TA>(Ab, ldA, sb,         0, t);
    stage_tile<TB>(Bb, ldB, sb + 32768, 0, t);
    CP_COMMIT();

    for (int s = 0; s < S; ++s) {
        if (s + 1 < S) {
            const int nb = (s + 1) & 1;
            stage_tile<TA>(Ab, ldA, sb + nb * 16384,         (s + 1) * 64, t);
            stage_tile<TB>(Bb, ldB, sb + 32768 + nb * 16384, (s + 1) * 64, t);
            CP_COMMIT();
            CP_WAIT1();
        } else {
            CP_WAIT0();
        }
        __syncthreads();

        const uint32_t abase = sb + (s & 1) * 16384;
        const uint32_t bbase = sb + 32768 + (s & 1) * 16384;
#pragma unroll
        for (int ks = 0; ks < 4; ++ks) {
            uint32_t af[4][4], bf[2][4];
#pragma unroll
            for (int mt = 0; mt < 4; ++mt) {
                if constexpr (!TA) {
                    int row = wm + mt * 16 + (l & 7) + ((l >> 3) & 1) * 8;
                    int ch  = ks * 2 + (l >> 4);
                    LDSM4(af[mt], abase + row * 128 + ((ch ^ (row & 7)) << 4));
                } else {
                    int kr = ks * 16 + (l & 7) + (l >> 4) * 8;
                    int ch = ((wm + mt * 16) >> 3) + ((l >> 3) & 1);
                    LDSM4T(af[mt], abase + kr * 256 + ((ch ^ (kr & 7)) << 4));
                }
            }
#pragma unroll
            for (int np = 0; np < 2; ++np) {
                if constexpr (!TB) {
                    int row = wn + np * 16 + (l & 7) + (l >> 4) * 8;
                    int ch  = ks * 2 + ((l >> 3) & 1);
                    LDSM4(bf[np], bbase + row * 128 + ((ch ^ (row & 7)) << 4));
                } else {
                    int kr = ks * 16 + (l & 7) + ((l >> 3) & 1) * 8;
                    int ch = ((wn + np * 16) >> 3) + (l >> 4);
                    LDSM4T(bf[np], bbase + kr * 256 + ((ch ^ (kr & 7)) << 4));
                }
            }
#pragma unroll
            for (int mt = 0; mt < 4; ++mt)
#pragma unroll
                for (int nt = 0; nt < 4; ++nt)
                    mma_f16(acc[mt][nt], af[mt], &bf[nt >> 1][(nt & 1) * 2]);
        }
        __syncthreads();
    }

#pragma unroll
    for (int mt = 0; mt < 4; ++mt) {
        const int row = m0 + wm + mt * 16 + (l >> 2);
        float bv0 = 0.f, bv1 = 0.f;
        if constexpr (BIAS) { bv0 = bias[row]; bv1 = bias[row + 8]; }
        __half* Ob = Out + (size_t)blockIdx.z * strideO;
#pragma unroll
        for (int nt = 0; nt < 4; ++nt) {
            const int col = n0 + wn + nt * 8 + 2 * (l & 3);
            *(__half2*)(Ob + (size_t)row * N_ + col) =
                __floats2half2_rn(acc[mt][nt][0] + bv0, acc[mt][nt][1] + bv0);
            *(__half2*)(Ob + (size_t)(row + 8) * N_ + col) =
                __floats2half2_rn(acc[mt][nt][2] + bv1, acc[mt][nt][3] + bv1);
        }
    }
}

// =====================================================================
//          Flash-fused attention: S = theta^T phi, softmax, O = P~ G^T
// =====================================================================
// Per block: 128 query positions (n), full loop over 8 m-tiles of 128 keys.
// 256 threads, 8 warps; warp w owns rows w*16..w*16+15 (all reductions 4-lane).
// SMEM: theta [256 c][128 n] @0 (64K); phi half-buffers 2x[128 c][128 m]
//       @64K,@96K (32K each); G [256 ci][128 m] @128K (64K). 256B-pitch rows,
//       chunk swizzle c^(r&7). Output Y[n][ci], ci contiguous.
#define FL_SMEM (192 * 1024)

template <int ROWS>
static __device__ __forceinline__ void stage256(const __half* __restrict__ src, uint32_t dst, int t) {
#pragma unroll
    for (int i = 0; i < ROWS / 16; ++i) {
        int idx = t + i * 256;
        int r = idx >> 4, c = idx & 15;
        CP16(dst + r * 256 + ((c ^ (r & 7)) << 4), src + (size_t)r * N_ + c * 8);
    }
}

__global__ __launch_bounds__(256, 1)
void flash_kernel(const __half* __restrict__ T, const __half* __restrict__ P,
                  const __half* __restrict__ G, __half* __restrict__ Y) {
    extern __shared__ __align__(128) char smem[];
    const uint32_t sb = smem_u32(smem);
    const int t = threadIdx.x, l = t & 31, w = t >> 5;
    const int n0 = blockIdx.x * 128;
    const size_t bb = (size_t)blockIdx.y * CI_ * N_;
    const __half* Tb = T + bb;
    const __half* Pb = P + bb;
    const __half* Gb = G + bb;
    const uint32_t ph0 = sb + 65536, gbuf = sb + 131072;

    float oacc[32][4];
#pragma unroll
    for (int nt = 0; nt < 32; ++nt)
#pragma unroll
        for (int q = 0; q < 4; ++q) oacc[nt][q] = 0.f;
    float M0 = -1e30f, M1 = -1e30f, L0 = 0.f, L1 = 0.f;

    // prologue commits: {theta, phi(0,0)}, {G(0)}, {phi(0,1)}
    stage256<256>(Tb + n0, sb, t);
    stage256<128>(Pb + 0, ph0, t);
    CP_COMMIT();
    stage256<256>(Gb + 0, gbuf, t);
    CP_COMMIT();
    stage256<128>(Pb + (size_t)128 * N_ + 0, ph0 + 32768, t);
    CP_COMMIT();

    for (int it = 0; it < 8; ++it) {
        const int m0 = it * 128;
        float sacc[16][4];
#pragma unroll
        for (int nt = 0; nt < 16; ++nt)
#pragma unroll
            for (int q = 0; q < 4; ++q) sacc[nt][q] = 0.f;

        // ---- phase 1: S += theta^T phi over K=256 in two 128-halves ----
#pragma unroll
        for (int h = 0; h < 2; ++h) {
            if (h == 0) { CP_WAIT2(); }
            else if (it == 0 || it == 7) { CP_WAIT1(); } else { CP_WAIT2(); }
            __syncthreads();
            const uint32_t phb = ph0 + h * 32768;
#pragma unroll
            for (int j = 0; j < 8; ++j) {
                uint32_t af[4];
                {
                    int kr = (h * 8 + j) * 16 + (l & 7) + (l >> 4) * 8;
                    int ch = 2 * w + ((l >> 3) & 1);
                    LDSM4T(af, sb + kr * 256 + ((ch ^ (kr & 7)) << 4));
                }
#pragma unroll
                for (int jj = 0; jj < 8; ++jj) {
                    uint32_t bf[4];
                    {
                        int kr = j * 16 + (l & 7) + ((l >> 3) & 1) * 8;
                        int ch = 2 * jj + (l >> 4);
                        LDSM4T(bf, phb + kr * 256 + ((ch ^ (kr & 7)) << 4));
                    }
                    mma_f16(sacc[2 * jj],     af, bf);
                    mma_f16(sacc[2 * jj + 1], af, bf + 2);
                }
            }
            __syncthreads();
            if (it < 7) {   // refill this phi half for next m-tile
                stage256<128>(Pb + (size_t)(h * 128) * N_ + m0 + 128, phb, t);
                CP_COMMIT();
            }
        }

        // ---- online softmax (rows owned within 4-lane groups) ----
        float tmax0 = -1e30f, tmax1 = -1e30f;
#pragma unroll
        for (int nt = 0; nt < 16; ++nt) {
            tmax0 = fmaxf(tmax0, fmaxf(sacc[nt][0], sacc[nt][1]));
            tmax1 = fmaxf(tmax1, fmaxf(sacc[nt][2], sacc[nt][3]));
        }
        tmax0 = fmaxf(tmax0, __shfl_xor_sync(~0u, tmax0, 1));
        tmax0 = fmaxf(tmax0, __shfl_xor_sync(~0u, tmax0, 2));
        tmax1 = fmaxf(tmax1, __shfl_xor_sync(~0u, tmax1, 1));
        tmax1 = fmaxf(tmax1, __shfl_xor_sync(~0u, tmax1, 2));
        float Mn0 = fmaxf(M0, tmax0), Mn1 = fmaxf(M1, tmax1);
        float sc0 = __expf(M0 - Mn0), sc1 = __expf(M1 - Mn1);
        float ts0 = 0.f, ts1 = 0.f;
        uint32_t afp[8][4];
#pragma unroll
        for (int j = 0; j < 8; ++j) {
            float p00 = __expf(sacc[2 * j][0] - Mn0);
            float p01 = __expf(sacc[2 * j][1] - Mn0);
            float p02 = __expf(sacc[2 * j][2] - Mn1);
            float p03 = __expf(sacc[2 * j][3] - Mn1);
            float p10 = __expf(sacc[2 * j + 1][0] - Mn0);
            float p11 = __expf(sacc[2 * j + 1][1] - Mn0);
            float p12 = __expf(sacc[2 * j + 1][2] - Mn1);
            float p13 = __expf(sacc[2 * j + 1][3] - Mn1);
            ts0 += p00 + p01 + p10 + p11;
            ts1 += p02 + p03 + p12 + p13;
            afp[j][0] = h2pack(p00, p01);
            afp[j][1] = h2pack(p02, p03);
            afp[j][2] = h2pack(p10, p11);
            afp[j][3] = h2pack(p12, p13);
        }
        ts0 += __shfl_xor_sync(~0u, ts0, 1); ts0 += __shfl_xor_sync(~0u, ts0, 2);
        ts1 += __shfl_xor_sync(~0u, ts1, 1); ts1 += __shfl_xor_sync(~0u, ts1, 2);
        L0 = L0 * sc0 + ts0; L1 = L1 * sc1 + ts1;
        M0 = Mn0; M1 = Mn1;
#pragma unroll
        for (int nt = 0; nt < 32; ++nt) {
            oacc[nt][0] *= sc0; oacc[nt][1] *= sc0;
            oacc[nt][2] *= sc1; oacc[nt][3] *= sc1;
        }

        // ---- phase 2: O += P~ @ G^T ----
        if (it < 7) { CP_WAIT2(); } else { CP_WAIT0(); }
        __syncthreads();
#pragma unroll
        for (int ks = 0; ks < 8; ++ks) {
#pragma unroll
            for (int jj = 0; jj < 16; ++jj) {
                uint32_t bf[4];
                {
                    int row = 16 * jj + (l & 7) + (l >> 4) * 8;
                    int ch  = ks * 2 + ((l >> 3) & 1);
                    LDSM4(bf, gbuf + row * 256 + ((ch ^ (row & 7)) << 4));
                }
                mma_f16(oacc[2 * jj],     afp[ks], bf);
                mma_f16(oacc[2 * jj + 1], afp[ks], bf + 2);
            }
        }
        __syncthreads();
        if (it < 7) {
            stage256<256>(Gb + m0 + 128, gbuf, t);
            CP_COMMIT();
        }
    }

    // ---- epilogue: normalize and store Y[n][ci] ----
    const float i0 = 1.f / L0, i1 = 1.f / L1;
    __half* Yb = Y + (size_t)blockIdx.y * N_ * CI_;
    const int row0 = n0 + w * 16 + (l >> 2);
#pragma unroll
    for (int nt = 0; nt < 32; ++nt) {
        const int col = nt * 8 + (l & 3) * 2;
        *(__half2*)(Yb + (size_t)row0 * CI_ + col) =
            __floats2half2_rn(oacc[nt][0] * i0, oacc[nt][1] * i0);
        *(__half2*)(Yb + (size_t)(row0 + 8) * CI_ + col) =
            __floats2half2_rn(oacc[nt][2] * i1, oacc[nt][3] * i1);
    }
}

// ---------------- fp32 -> fp16 conversion ----------------
__global__ __launch_bounds__(256)
void cvt_kernel(const float* __restrict__ src, __half* __restrict__ dst, int n4) {
    int i = blockIdx.x * 256 + threadIdx.x;
    if (i < n4) {
        float4 v = ((const float4*)src)[i];
        __half2 h0 = __floats2half2_rn(v.x, v.y);
        __half2 h1 = __floats2half2_rn(v.z, v.w);
        uint2 u = { *(uint32_t*)&h0, *(uint32_t*)&h1 };
        ((uint2*)dst)[i] = u;
    }
}

// ---------------- BatchNorm stats on fp16 WY -> fused scale/shift ----------------
__global__ __launch_bounds__(256)
void bnstats_kernel(const __half* __restrict__ WY, const float* __restrict__ gamma,
                    const float* __restrict__ beta) {
    int c = blockIdx.x;
    int t = threadIdx.x;
    float s = 0.f, s2 = 0.f;
    for (int b = 0; b < B_; ++b) {
        const __half2* p = (const __half2*)(WY + ((size_t)b * C_ + c) * N_);
        for (int n = t; n < N_ / 2; n += 256) {
            float2 v = __half22float2(p[n]);
            s += v.x + v.y; s2 += v.x * v.x + v.y * v.y;
        }
    }
#pragma unroll
    for (int o = 16; o; o >>= 1) {
        s  += __shfl_xor_sync(~0u, s,  o);
        s2 += __shfl_xor_sync(~0u, s2, o);
    }
    __shared__ float ss[8], ss2[8];
    if ((t & 31) == 0) { ss[t >> 5] = s; ss2[t >> 5] = s2; }
    __syncthreads();
    if (t == 0) {
        float S = 0.f, S2 = 0.f;
#pragma unroll
        for (int i = 0; i < 8; ++i) { S += ss[i]; S2 += ss2[i]; }
        const float invN = 1.0f / (float)(B_ * N_);
        float mean = S * invN;
        float var  = S2 * invN - mean * mean;
        float inv  = rsqrtf(var + 1e-5f);
        float sc   = gamma[c] * inv;
        d_scale[c] = sc;
        d_shift[c] = beta[c] - mean * sc;
    }
}

// ---------------- finalize: out = w_y*scale + shift + x (x fp32) ----------------
__global__ __launch_bounds__(256)
void finalize_kernel(const __half* __restrict__ WY, const float* __restrict__ x,
                     float* __restrict__ out) {
    size_t i4 = (size_t)blockIdx.x * 256 + threadIdx.x;
    int c = (int)((i4 >> 8) & (C_ - 1));
    float sc = d_scale[c], sh = d_shift[c];
    uint2 u = ((const uint2*)WY)[i4];
    float2 w0 = __half22float2(*(__half2*)&u.x);
    float2 w1 = __half22float2(*(__half2*)&u.y);
    float4 xv = ((const float4*)x)[i4];
    float4 o;
    o.x = w0.x * sc + sh + xv.x;
    o.y = w0.y * sc + sh + xv.y;
    o.z = w1.x * sc + sh + xv.z;
    o.w = w1.y * sc + sh + xv.w;
    ((float4*)out)[i4] = o;
}

// ---------------- launch ----------------
extern "C" void kernel_launch(void* const* d_in, const int* in_sizes, int n_in,
                              void* d_out, int out_size) {
    const float* x     = (const float*)d_in[0];
    const float* Wg    = (const float*)d_in[1];
    const float* bg    = (const float*)d_in[2];
    const float* Wt    = (const float*)d_in[3];
    const float* bt    = (const float*)d_in[4];
    const float* Wp    = (const float*)d_in[5];
    const float* bp    = (const float*)d_in[6];
    const float* Wz    = (const float*)d_in[7];
    const float* bz    = (const float*)d_in[8];
    const float* gamma = (const float*)d_in[9];
    const float* beta  = (const float*)d_in[10];
    float* out = (float*)d_out;

    __half *x16, *Wg16, *Wt16, *Wp16, *Wz16, *Gh, *Th, *Ph, *Yh, *WYh;
    cudaGetSymbolAddress((void**)&x16,  d_x16);
    cudaGetSymbolAddress((void**)&Wg16, d_Wg16);
    cudaGetSymbolAddress((void**)&Wt16, d_Wt16);
    cudaGetSymbolAddress((void**)&Wp16, d_Wp16);
    cudaGetSymbolAddress((void**)&Wz16, d_Wz16);
    cudaGetSymbolAddress((void**)&Gh,   d_Gh);
    cudaGetSymbolAddress((void**)&Th,   d_Th);
    cudaGetSymbolAddress((void**)&Ph,   d_Ph);
    cudaGetSymbolAddress((void**)&Yh,   d_Yh);
    cudaGetSymbolAddress((void**)&WYh,  d_WYh);

    cudaFuncSetAttribute(mm_f16<false, true,  true>,  cudaFuncAttributeMaxDynamicSharedMemorySize, SMEM_BYTES);
    cudaFuncSetAttribute(mm_f16<false, false, true>,  cudaFuncAttributeMaxDynamicSharedMemorySize, SMEM_BYTES);
    cudaFuncSetAttribute(flash_kernel, cudaFuncAttributeMaxDynamicSharedMemorySize, FL_SMEM);

    const long sCi = (long)CI_ * N_;
    const long sC  = (long)C_  * N_;

    // fp16 conversions
    cvt_kernel<<<(B_ * C_ * N_ / 4 + 255) / 256, 256>>>(x,  x16,  B_ * C_ * N_ / 4);
    cvt_kernel<<<(CI_ * C_ / 4 + 255) / 256, 256>>>(Wg, Wg16, CI_ * C_ / 4);
    cvt_kernel<<<(CI_ * C_ / 4 + 255) / 256, 256>>>(Wt, Wt16, CI_ * C_ / 4);
    cvt_kernel<<<(CI_ * C_ / 4 + 255) / 256, 256>>>(Wp, Wp16, CI_ * C_ / 4);
    cvt_kernel<<<(C_ * CI_ / 4 + 255) / 256, 256>>>(Wz, Wz16, C_ * CI_ / 4);

    // projections: Out[b] (Ci x N) = W (Ci x C) * x[b] (C x N)
    mm_f16<false, true, true><<<dim3(8, 2, 32), 256, SMEM_BYTES>>>(Wg16, x16, bg, Gh, C_, C_, N_, 0, sC, sCi);
    mm_f16<false, true, true><<<dim3(8, 2, 32), 256, SMEM_BYTES>>>(Wt16, x16, bt, Th, C_, C_, N_, 0, sC, sCi);
    mm_f16<false, true, true><<<dim3(8, 2, 32), 256, SMEM_BYTES>>>(Wp16, x16, bp, Ph, C_, C_, N_, 0, sC, sCi);

    // fused attention: Y[b][n][ci]
    flash_kernel<<<dim3(8, 32), 256, FL_SMEM>>>(Th, Ph, Gh, Yh);

    // z-conv: WY[b] (C x N) = Wz (C x Ci) * Y[b] (N x Ci, K-major rows)
    mm_f16<false, false, true><<<dim3(8, 4, 32), 256, SMEM_BYTES>>>(Wz16, Yh, bz, WYh, CI_, CI_, CI_, 0, sCi, sC);

    // BN + residual
    bnstats_kernel<<<C_, 256>>>(WYh, gamma, beta);
    finalize_kernel<<<(B_ * C_ * N_) / 4 / 256, 256>>>(WYh, x, out);
}

// round 7
// speedup vs baseline: 7.1024x; 1.1065x over previous
#include <cuda_runtime.h>
#include <cuda_fp16.h>
#include <cstdint>

// Problem constants
#define B_  32
#define C_  512
#define CI_ 256
#define N_  1024   // H*W

// ---------------- static device scratch ----------------
__device__ __align__(128) __half d_x16[(size_t)B_ * C_ * N_];
__device__ __align__(128) __half d_Wstk[768 * C_];              // [g;theta;phi] stacked
__device__ __align__(128) float  d_bstk[768];
__device__ __align__(128) __half d_Wz16[C_ * CI_];
__device__ __align__(128) __half d_GTP[(size_t)B_ * 768 * N_];  // [b][768][N]
__device__ __align__(128) __half d_Yh[(size_t)B_ * N_ * CI_];   // y [b][N][Ci]
__device__ __align__(128) __half d_WYh[(size_t)B_ * C_ * N_];
__device__ float d_ssum[C_];
__device__ float d_ssq[C_];
__device__ float d_scale[C_];
__device__ float d_shift[C_];

// ---------------- helpers ----------------
static __device__ __forceinline__ uint32_t smem_u32(const void* p) {
    uint32_t a;
    asm("{ .reg .u64 t; cvta.to.shared.u64 t, %1; cvt.u32.u64 %0, t; }" : "=r"(a) : "l"(p));
    return a;
}

#define CP16(dst, src) \
    asm volatile("cp.async.cg.shared.global [%0], [%1], 16;" :: "r"(dst), "l"(src))
#define CP_COMMIT() asm volatile("cp.async.commit_group;" ::: "memory")
#define CP_WAIT0()  asm volatile("cp.async.wait_group 0;" ::: "memory")
#define CP_WAIT1()  asm volatile("cp.async.wait_group 1;" ::: "memory")
#define CP_WAIT2()  asm volatile("cp.async.wait_group 2;" ::: "memory")

#define LDSM4(r, addr) \
    asm volatile("ldmatrix.sync.aligned.m8n8.x4.shared.b16 {%0,%1,%2,%3}, [%4];" \
        : "=r"((r)[0]), "=r"((r)[1]), "=r"((r)[2]), "=r"((r)[3]) : "r"(addr))
#define LDSM4T(r, addr) \
    asm volatile("ldmatrix.sync.aligned.m8n8.x4.trans.shared.b16 {%0,%1,%2,%3}, [%4];" \
        : "=r"((r)[0]), "=r"((r)[1]), "=r"((r)[2]), "=r"((r)[3]) : "r"(addr))

static __device__ __forceinline__ void mma_f16(float* c, const uint32_t* a, const uint32_t* b) {
    asm volatile(
        "mma.sync.aligned.m16n8k16.row.col.f32.f16.f16.f32 "
        "{%0,%1,%2,%3},{%4,%5,%6,%7},{%8,%9},{%0,%1,%2,%3};"
        : "+f"(c[0]), "+f"(c[1]), "+f"(c[2]), "+f"(c[3])
        : "r"(a[0]), "r"(a[1]), "r"(a[2]), "r"(a[3]), "r"(b[0]), "r"(b[1]));
}

static __device__ __forceinline__ uint32_t h2pack(float a, float b) {
    __half2 h = __floats2half2_rn(a, b);
    return *(uint32_t*)&h;
}

// =====================================================================
//                         GEMM (projections / z-conv)
// =====================================================================
#define SMEM_BYTES 65536

template <bool TR>
static __device__ __forceinline__ void stage_tile(const __half* __restrict__ src, int ld,
                                                  uint32_t dst, int k0, int t) {
#pragma unroll
    for (int i = 0; i < 4; ++i) {
        int idx = t + i * 256;
        if constexpr (!TR) {
            int r = idx >> 3, c = idx & 7;
            const __half* s = src + (size_t)r * ld + k0 + c * 8;
            CP16(dst + r * 128 + ((c ^ (r & 7)) << 4), s);
        } else {
            int k = idx >> 4, c = idx & 15;
            const __half* s = src + (size_t)(k0 + k) * ld + c * 8;
            CP16(dst + k * 256 + ((c ^ (k & 7)) << 4), s);
        }
    }
}

template <bool TA, bool TB, bool BIAS, bool STATS>
__global__ __launch_bounds__(256, 2)
void mm_f16(const __half* __restrict__ A, const __half* __restrict__ Bm,
            const float* __restrict__ bias, __half* __restrict__ Out,
            int K, int ldA, int ldB,
            long strideA, long strideB, long strideO,
            float* gs, float* gs2) {
    extern __shared__ __align__(128) char smem[];
    const uint32_t sb = smem_u32(smem);
    const int t = threadIdx.x;
    const int l = t & 31;
    const int w = t >> 5;
    const int wm = (w >> 2) * 64;
    const int wn = (w & 3) * 32;
    const int m0 = blockIdx.y * 128;
    const int n0 = blockIdx.x * 128;
    const __half* Ab = A  + (size_t)blockIdx.z * strideA + (TA ? m0 : (size_t)m0 * ldA);
    const __half* Bb = Bm + (size_t)blockIdx.z * strideB + (TB ? n0 : (size_t)n0 * ldB);

    float acc[4][4][4];
#pragma unroll
    for (int mt = 0; mt < 4; ++mt)
#pragma unroll
        for (int nt = 0; nt < 4; ++nt)
#pragma unroll
            for (int q = 0; q < 4; ++q) acc[mt][nt][q] = 0.f;

    const int S = K / 64;
    stage_tile<TA>(Ab, ldA, sb,         0, t);
    stage_tile<TB>(Bb, ldB, sb + 32768, 0, t);
    CP_COMMIT();

    for (int s = 0; s < S; ++s) {
        if (s + 1 < S) {
            const int nb = (s + 1) & 1;
            stage_tile<TA>(Ab, ldA, sb + nb * 16384,         (s + 1) * 64, t);
            stage_tile<TB>(Bb, ldB, sb + 32768 + nb * 16384, (s + 1) * 64, t);
            CP_COMMIT();
            CP_WAIT1();
        } else {
            CP_WAIT0();
        }
        __syncthreads();

        const uint32_t abase = sb + (s & 1) * 16384;
        const uint32_t bbase = sb + 32768 + (s & 1) * 16384;
#pragma unroll
        for (int ks = 0; ks < 4; ++ks) {
            uint32_t af[4][4], bf[2][4];
#pragma unroll
            for (int mt = 0; mt < 4; ++mt) {
                if constexpr (!TA) {
                    int row = wm + mt * 16 + (l & 7) + ((l >> 3) & 1) * 8;
                    int ch  = ks * 2 + (l >> 4);
                    LDSM4(af[mt], abase + row * 128 + ((ch ^ (row & 7)) << 4));
                } else {
                    int kr = ks * 16 + (l & 7) + (l >> 4) * 8;
                    int ch = ((wm + mt * 16) >> 3) + ((l >> 3) & 1);
                    LDSM4T(af[mt], abase + kr * 256 + ((ch ^ (kr & 7)) << 4));
                }
            }
#pragma unroll
            for (int np = 0; np < 2; ++np) {
                if constexpr (!TB) {
                    int row = wn + np * 16 + (l & 7) + (l >> 4) * 8;
                    int ch  = ks * 2 + ((l >> 3) & 1);
                    LDSM4(bf[np], bbase + row * 128 + ((ch ^ (row & 7)) << 4));
                } else {
                    int kr = ks * 16 + (l & 7) + ((l >> 3) & 1) * 8;
                    int ch = ((wn + np * 16) >> 3) + (l >> 4);
                    LDSM4T(bf[np], bbase + kr * 256 + ((ch ^ (kr & 7)) << 4));
                }
            }
#pragma unroll
            for (int mt = 0; mt < 4; ++mt)
#pragma unroll
                for (int nt = 0; nt < 4; ++nt)
                    mma_f16(acc[mt][nt], af[mt], &bf[nt >> 1][(nt & 1) * 2]);
        }
        __syncthreads();
    }

    if constexpr (STATS) {
        if (t < 256) ((float*)smem)[t] = 0.f;
        __syncthreads();
    }

#pragma unroll
    for (int mt = 0; mt < 4; ++mt) {
        const int row = m0 + wm + mt * 16 + (l >> 2);
        float bv0 = 0.f, bv1 = 0.f;
        if constexpr (BIAS) { bv0 = bias[row]; bv1 = bias[row + 8]; }
        __half* Ob = Out + (size_t)blockIdx.z * strideO;
        float s0 = 0.f, q0 = 0.f, s1 = 0.f, q1 = 0.f;
#pragma unroll
        for (int nt = 0; nt < 4; ++nt) {
            const int col = n0 + wn + nt * 8 + 2 * (l & 3);
            float v00 = acc[mt][nt][0] + bv0, v01 = acc[mt][nt][1] + bv0;
            float v10 = acc[mt][nt][2] + bv1, v11 = acc[mt][nt][3] + bv1;
            *(__half2*)(Ob + (size_t)row * N_ + col)       = __floats2half2_rn(v00, v01);
            *(__half2*)(Ob + (size_t)(row + 8) * N_ + col) = __floats2half2_rn(v10, v11);
            if constexpr (STATS) {
                s0 += v00 + v01; q0 += v00 * v00 + v01 * v01;
                s1 += v10 + v11; q1 += v10 * v10 + v11 * v11;
            }
        }
        if constexpr (STATS) {
            s0 += __shfl_xor_sync(~0u, s0, 1); s0 += __shfl_xor_sync(~0u, s0, 2);
            q0 += __shfl_xor_sync(~0u, q0, 1); q0 += __shfl_xor_sync(~0u, q0, 2);
            s1 += __shfl_xor_sync(~0u, s1, 1); s1 += __shfl_xor_sync(~0u, s1, 2);
            q1 += __shfl_xor_sync(~0u, q1, 1); q1 += __shfl_xor_sync(~0u, q1, 2);
            if ((l & 3) == 0) {
                const int lr = wm + mt * 16 + (l >> 2);
                float* ss = (float*)smem;
                atomicAdd(ss + lr, s0);       atomicAdd(ss + 128 + lr, q0);
                atomicAdd(ss + lr + 8, s1);   atomicAdd(ss + 128 + lr + 8, q1);
            }
        }
    }

    if constexpr (STATS) {
        __syncthreads();
        if (t < 128) {
            atomicAdd(gs  + m0 + t, ((float*)smem)[t]);
            atomicAdd(gs2 + m0 + t, ((float*)smem)[t + 128]);
        }
    }
}

// =====================================================================
//          Flash-fused attention (reads from stacked GTP tensor)
// =====================================================================
#define FL_SMEM (192 * 1024)
#define GSTRIDE ((size_t)768 * N_)

template <int ROWS>
static __device__ __forceinline__ void stage256(const __half* __restrict__ src, uint32_t dst, int t) {
#pragma unroll
    for (int i = 0; i < ROWS / 16; ++i) {
        int idx = t + i * 256;
        int r = idx >> 4, c = idx & 15;
        CP16(dst + r * 256 + ((c ^ (r & 7)) << 4), src + (size_t)r * N_ + c * 8);
    }
}

__global__ __launch_bounds__(256, 1)
void flash_kernel(const __half* __restrict__ GTP, __half* __restrict__ Y) {
    extern __shared__ __align__(128) char smem[];
    const uint32_t sb = smem_u32(smem);
    const int t = threadIdx.x, l = t & 31, w = t >> 5;
    const int n0 = blockIdx.x * 128;
    const __half* Gb = GTP + (size_t)blockIdx.y * GSTRIDE;
    const __half* Tb = Gb + (size_t)256 * N_;
    const __half* Pb = Gb + (size_t)512 * N_;
    const uint32_t ph0 = sb + 65536, gbuf = sb + 131072;

    float oacc[32][4];
#pragma unroll
    for (int nt = 0; nt < 32; ++nt)
#pragma unroll
        for (int q = 0; q < 4; ++q) oacc[nt][q] = 0.f;
    float M0 = -1e30f, M1 = -1e30f, L0 = 0.f, L1 = 0.f;

    stage256<256>(Tb + n0, sb, t);
    stage256<128>(Pb + 0, ph0, t);
    CP_COMMIT();
    stage256<256>(Gb + 0, gbuf, t);
    CP_COMMIT();
    stage256<128>(Pb + (size_t)128 * N_ + 0, ph0 + 32768, t);
    CP_COMMIT();

    for (int it = 0; it < 8; ++it) {
        const int m0 = it * 128;
        float sacc[16][4];
#pragma unroll
        for (int nt = 0; nt < 16; ++nt)
#pragma unroll
            for (int q = 0; q < 4; ++q) sacc[nt][q] = 0.f;

#pragma unroll
        for (int h = 0; h < 2; ++h) {
            if (h == 0) { CP_WAIT2(); }
            else if (it == 0 || it == 7) { CP_WAIT1(); } else { CP_WAIT2(); }
            __syncthreads();
            const uint32_t phb = ph0 + h * 32768;
#pragma unroll
            for (int j = 0; j < 8; ++j) {
                uint32_t af[4];
                {
                    int kr = (h * 8 + j) * 16 + (l & 7) + (l >> 4) * 8;
                    int ch = 2 * w + ((l >> 3) & 1);
                    LDSM4T(af, sb + kr * 256 + ((ch ^ (kr & 7)) << 4));
                }
#pragma unroll
                for (int jj = 0; jj < 8; ++jj) {
                    uint32_t bf[4];
                    {
                        int kr = j * 16 + (l & 7) + ((l >> 3) & 1) * 8;
                        int ch = 2 * jj + (l >> 4);
                        LDSM4T(bf, phb + kr * 256 + ((ch ^ (kr & 7)) << 4));
                    }
                    mma_f16(sacc[2 * jj],     af, bf);
                    mma_f16(sacc[2 * jj + 1], af, bf + 2);
                }
            }
            __syncthreads();
            if (it < 7) {
                stage256<128>(Pb + (size_t)(h * 128) * N_ + m0 + 128, phb, t);
                CP_COMMIT();
            }
        }

        float tmax0 = -1e30f, tmax1 = -1e30f;
#pragma unroll
        for (int nt = 0; nt < 16; ++nt) {
            tmax0 = fmaxf(tmax0, fmaxf(sacc[nt][0], sacc[nt][1]));
            tmax1 = fmaxf(tmax1, fmaxf(sacc[nt][2], sacc[nt][3]));
        }
        tmax0 = fmaxf(tmax0, __shfl_xor_sync(~0u, tmax0, 1));
        tmax0 = fmaxf(tmax0, __shfl_xor_sync(~0u, tmax0, 2));
        tmax1 = fmaxf(tmax1, __shfl_xor_sync(~0u, tmax1, 1));
        tmax1 = fmaxf(tmax1, __shfl_xor_sync(~0u, tmax1, 2));
        float Mn0 = fmaxf(M0, tmax0), Mn1 = fmaxf(M1, tmax1);
        float sc0 = __expf(M0 - Mn0), sc1 = __expf(M1 - Mn1);
        float ts0 = 0.f, ts1 = 0.f;
        uint32_t afp[8][4];
#pragma unroll
        for (int j = 0; j < 8; ++j) {
            float p00 = __expf(sacc[2 * j][0] - Mn0);
            float p01 = __expf(sacc[2 * j][1] - Mn0);
            float p02 = __expf(sacc[2 * j][2] - Mn1);
            float p03 = __expf(sacc[2 * j][3] - Mn1);
            float p10 = __expf(sacc[2 * j + 1][0] - Mn0);
            float p11 = __expf(sacc[2 * j + 1][1] - Mn0);
            float p12 = __expf(sacc[2 * j + 1][2] - Mn1);
            float p13 = __expf(sacc[2 * j + 1][3] - Mn1);
            ts0 += p00 + p01 + p10 + p11;
            ts1 += p02 + p03 + p12 + p13;
            afp[j][0] = h2pack(p00, p01);
            afp[j][1] = h2pack(p02, p03);
            afp[j][2] = h2pack(p10, p11);
            afp[j][3] = h2pack(p12, p13);
        }
        ts0 += __shfl_xor_sync(~0u, ts0, 1); ts0 += __shfl_xor_sync(~0u, ts0, 2);
        ts1 += __shfl_xor_sync(~0u, ts1, 1); ts1 += __shfl_xor_sync(~0u, ts1, 2);
        L0 = L0 * sc0 + ts0; L1 = L1 * sc1 + ts1;
        M0 = Mn0; M1 = Mn1;
#pragma unroll
        for (int nt = 0; nt < 32; ++nt) {
            oacc[nt][0] *= sc0; oacc[nt][1] *= sc0;
            oacc[nt][2] *= sc1; oacc[nt][3] *= sc1;
        }

        if (it < 7) { CP_WAIT2(); } else { CP_WAIT0(); }
        __syncthreads();
#pragma unroll
        for (int ks = 0; ks < 8; ++ks) {
#pragma unroll
            for (int jj = 0; jj < 16; ++jj) {
                uint32_t bf[4];
                {
                    int row = 16 * jj + (l & 7) + (l >> 4) * 8;
                    int ch  = ks * 2 + ((l >> 3) & 1);
                    LDSM4(bf, gbuf + row * 256 + ((ch ^ (row & 7)) << 4));
                }
                mma_f16(oacc[2 * jj],     afp[ks], bf);
                mma_f16(oacc[2 * jj + 1], afp[ks], bf + 2);
            }
        }
        __syncthreads();
        if (it < 7) {
            stage256<256>(Gb + m0 + 128, gbuf, t);
            CP_COMMIT();
        }
    }

    const float i0 = 1.f / L0, i1 = 1.f / L1;
    __half* Yb = Y + (size_t)blockIdx.y * N_ * CI_;
    const int row0 = n0 + w * 16 + (l >> 2);
#pragma unroll
    for (int nt = 0; nt < 32; ++nt) {
        const int col = nt * 8 + (l & 3) * 2;
        *(__half2*)(Yb + (size_t)row0 * CI_ + col) =
            __floats2half2_rn(oacc[nt][0] * i0, oacc[nt][1] * i0);
        *(__half2*)(Yb + (size_t)(row0 + 8) * CI_ + col) =
            __floats2half2_rn(oacc[nt][2] * i1, oacc[nt][3] * i1);
    }
}

// ---------------- small kernels ----------------
__global__ __launch_bounds__(512)
void zero_stats_kernel() {
    d_ssum[threadIdx.x] = 0.f;
    d_ssq[threadIdx.x] = 0.f;
}

__global__ __launch_bounds__(256)
void cvt_kernel(const float* __restrict__ src, __half* __restrict__ dst, int n4) {
    int i = blockIdx.x * 256 + threadIdx.x;
    if (i < n4) {
        float4 v = ((const float4*)src)[i];
        __half2 h0 = __floats2half2_rn(v.x, v.y);
        __half2 h1 = __floats2half2_rn(v.z, v.w);
        uint2 u = { *(uint32_t*)&h0, *(uint32_t*)&h1 };
        ((uint2*)dst)[i] = u;
    }
}

// pack Wg/Wt/Wp -> Wstk, Wz -> Wz16, biases -> bstk
__global__ __launch_bounds__(256)
void pack_kernel(const float* __restrict__ Wg, const float* __restrict__ Wt,
                 const float* __restrict__ Wp, const float* __restrict__ Wz,
                 const float* __restrict__ bg, const float* __restrict__ bt,
                 const float* __restrict__ bp,
                 __half* __restrict__ Wstk, __half* __restrict__ Wz16,
                 float* __restrict__ bstk) {
    const int WQ = (768 * C_) / 4;           // 98304
    const int ZQ = (C_ * CI_) / 4;           // 32768
    int i = blockIdx.x * 256 + threadIdx.x;
    if (i < WQ) {
        int row = (i * 4) >> 9;
        int col = (i * 4) & 511;
        const float* src = row < 256 ? Wg + row * C_
                         : row < 512 ? Wt + (row - 256) * C_
                                     : Wp + (row - 512) * C_;
        float4 v = *(const float4*)(src + col);
        __half2 h0 = __floats2half2_rn(v.x, v.y);
        __half2 h1 = __floats2half2_rn(v.z, v.w);
        uint2 u = { *(uint32_t*)&h0, *(uint32_t*)&h1 };
        ((uint2*)Wstk)[i] = u;
    } else if (i < WQ + ZQ) {
        int j = i - WQ;
        float4 v = ((const float4*)Wz)[j];
        __half2 h0 = __floats2half2_rn(v.x, v.y);
        __half2 h1 = __floats2half2_rn(v.z, v.w);
        uint2 u = { *(uint32_t*)&h0, *(uint32_t*)&h1 };
        ((uint2*)Wz16)[j] = u;
    } else if (i < WQ + ZQ + 192) {
        int e = (i - WQ - ZQ) * 4;
#pragma unroll
        for (int q = 0; q < 4; ++q) {
            int r = e + q;
            bstk[r] = r < 256 ? bg[r] : r < 512 ? bt[r - 256] : bp[r - 512];
        }
    }
}

__global__ __launch_bounds__(256)
void scaleshift_kernel(const float* __restrict__ gamma, const float* __restrict__ beta) {
    int c = blockIdx.x * 256 + threadIdx.x;
    const float invN = 1.0f / (float)(B_ * N_);
    float mean = d_ssum[c] * invN;
    float var  = d_ssq[c] * invN - mean * mean;
    float inv  = rsqrtf(var + 1e-5f);
    float sc   = gamma[c] * inv;
    d_scale[c] = sc;
    d_shift[c] = beta[c] - mean * sc;
}

__global__ __launch_bounds__(256)
void finalize_kernel(const __half* __restrict__ WY, const float* __restrict__ x,
                     float* __restrict__ out) {
    size_t i4 = (size_t)blockIdx.x * 256 + threadIdx.x;
    int c = (int)((i4 >> 8) & (C_ - 1));
    float sc = d_scale[c], sh = d_shift[c];
    uint2 u = ((const uint2*)WY)[i4];
    float2 w0 = __half22float2(*(__half2*)&u.x);
    float2 w1 = __half22float2(*(__half2*)&u.y);
    float4 xv = ((const float4*)x)[i4];
    float4 o;
    o.x = w0.x * sc + sh + xv.x;
    o.y = w0.y * sc + sh + xv.y;
    o.z = w1.x * sc + sh + xv.z;
    o.w = w1.y * sc + sh + xv.w;
    ((float4*)out)[i4] = o;
}

// ---------------- launch ----------------
extern "C" void kernel_launch(void* const* d_in, const int* in_sizes, int n_in,
                              void* d_out, int out_size) {
    const float* x     = (const float*)d_in[0];
    const float* Wg    = (const float*)d_in[1];
    const float* bg    = (const float*)d_in[2];
    const float* Wt    = (const float*)d_in[3];
    const float* bt    = (const float*)d_in[4];
    const float* Wp    = (const float*)d_in[5];
    const float* bp    = (const float*)d_in[6];
    const float* Wz    = (const float*)d_in[7];
    const float* bz    = (const float*)d_in[8];
    const float* gamma = (const float*)d_in[9];
    const float* beta  = (const float*)d_in[10];
    float* out = (float*)d_out;

    __half *x16, *Wstk, *Wz16, *GTP, *Yh, *WYh;
    float *bstk, *gs, *gs2;
    cudaGetSymbolAddress((void**)&x16,  d_x16);
    cudaGetSymbolAddress((void**)&Wstk, d_Wstk);
    cudaGetSymbolAddress((void**)&Wz16, d_Wz16);
    cudaGetSymbolAddress((void**)&GTP,  d_GTP);
    cudaGetSymbolAddress((void**)&Yh,   d_Yh);
    cudaGetSymbolAddress((void**)&WYh,  d_WYh);
    cudaGetSymbolAddress((void**)&bstk, d_bstk);
    cudaGetSymbolAddress((void**)&gs,   d_ssum);
    cudaGetSymbolAddress((void**)&gs2,  d_ssq);

    cudaFuncSetAttribute(mm_f16<false, true,  true, false>, cudaFuncAttributeMaxDynamicSharedMemorySize, SMEM_BYTES);
    cudaFuncSetAttribute(mm_f16<false, false, true, true >, cudaFuncAttributeMaxDynamicSharedMemorySize, SMEM_BYTES);
    cudaFuncSetAttribute(flash_kernel, cudaFuncAttributeMaxDynamicSharedMemorySize, FL_SMEM);

    const long sC  = (long)C_ * N_;
    const long sCi = (long)CI_ * N_;

    zero_stats_kernel<<<1, 512>>>();
    cvt_kernel<<<(B_ * C_ * N_ / 4 + 255) / 256, 256>>>(x, x16, B_ * C_ * N_ / 4);
    pack_kernel<<<((768 * C_ + C_ * CI_) / 4 + 192 + 255) / 256, 256>>>(
        Wg, Wt, Wp, Wz, bg, bt, bp, Wstk, Wz16, bstk);

    // stacked projections: GTP[b] (768 x N) = Wstk (768 x C) * x[b] (C x N)
    mm_f16<false, true, true, false><<<dim3(8, 6, 32), 256, SMEM_BYTES>>>(
        Wstk, x16, bstk, GTP, C_, C_, N_, 0, sC, (long)GSTRIDE, nullptr, nullptr);

    // fused attention: Y[b][n][ci]
    flash_kernel<<<dim3(8, 32), 256, FL_SMEM>>>(GTP, Yh);

    // z-conv + BN partial stats: WY[b] (C x N) = Wz (C x Ci) * Y[b] (N x Ci)
    mm_f16<false, false, true, true><<<dim3(8, 4, 32), 256, SMEM_BYTES>>>(
        Wz16, Yh, bz, WYh, CI_, CI_, CI_, 0, sCi, sC, gs, gs2);

    scaleshift_kernel<<<2, 256>>>(gamma, beta);
    finalize_kernel<<<(B_ * C_ * N_) / 4 / 256, 256>>>(WYh, x, out);
}

// round 8
// speedup vs baseline: 7.1469x; 1.0063x over previous
#include <cuda_runtime.h>
#include <cuda_fp16.h>
#include <cstdint>

// Problem constants
#define B_  32
#define C_  512
#define CI_ 256
#define N_  1024   // H*W

// ---------------- static device scratch ----------------
__device__ __align__(128) __half d_x16[(size_t)B_ * C_ * N_];
__device__ __align__(128) __half d_Wstk[768 * C_];              // [g;theta;phi] stacked
__device__ __align__(128) float  d_bstk[768];
__device__ __align__(128) __half d_Wz16[C_ * CI_];
__device__ __align__(128) __half d_GTP[(size_t)B_ * 768 * N_];  // [b][768][N]
__device__ __align__(128) __half d_Yh[(size_t)B_ * N_ * CI_];   // y [b][N][Ci]
__device__ __align__(128) __half d_WYh[(size_t)B_ * C_ * N_];
__device__ float d_ssum[C_];
__device__ float d_ssq[C_];
__device__ float d_scale[C_];
__device__ float d_shift[C_];

// ---------------- helpers ----------------
static __device__ __forceinline__ uint32_t smem_u32(const void* p) {
    uint32_t a;
    asm("{ .reg .u64 t; cvta.to.shared.u64 t, %1; cvt.u32.u64 %0, t; }" : "=r"(a) : "l"(p));
    return a;
}

#define CP16(dst, src) \
    asm volatile("cp.async.cg.shared.global [%0], [%1], 16;" :: "r"(dst), "l"(src))
#define CP_COMMIT() asm volatile("cp.async.commit_group;" ::: "memory")
#define CP_WAIT0()  asm volatile("cp.async.wait_group 0;" ::: "memory")
#define CP_WAIT1()  asm volatile("cp.async.wait_group 1;" ::: "memory")
#define CP_WAIT2()  asm volatile("cp.async.wait_group 2;" ::: "memory")

#define LDSM4(r, addr) \
    asm volatile("ldmatrix.sync.aligned.m8n8.x4.shared.b16 {%0,%1,%2,%3}, [%4];" \
        : "=r"((r)[0]), "=r"((r)[1]), "=r"((r)[2]), "=r"((r)[3]) : "r"(addr))
#define LDSM4T(r, addr) \
    asm volatile("ldmatrix.sync.aligned.m8n8.x4.trans.shared.b16 {%0,%1,%2,%3}, [%4];" \
        : "=r"((r)[0]), "=r"((r)[1]), "=r"((r)[2]), "=r"((r)[3]) : "r"(addr))

static __device__ __forceinline__ void mma_f16(float* c, const uint32_t* a, const uint32_t* b) {
    asm volatile(
        "mma.sync.aligned.m16n8k16.row.col.f32.f16.f16.f32 "
        "{%0,%1,%2,%3},{%4,%5,%6,%7},{%8,%9},{%0,%1,%2,%3};"
        : "+f"(c[0]), "+f"(c[1]), "+f"(c[2]), "+f"(c[3])
        : "r"(a[0]), "r"(a[1]), "r"(a[2]), "r"(a[3]), "r"(b[0]), "r"(b[1]));
}

static __device__ __forceinline__ uint32_t h2pack(float a, float b) {
    __half2 h = __floats2half2_rn(a, b);
    return *(uint32_t*)&h;
}

// =====================================================================
//                 GEMM (projections / z-conv), 3-stage pipeline
// =====================================================================
// SMEM: A bufs @0,16K,32K; B bufs @48K,64K,80K  (96 KB total)
#define SMEM_BYTES (96 * 1024)

template <bool TR>
static __device__ __forceinline__ void stage_tile(const __half* __restrict__ src, int ld,
                                                  uint32_t dst, int k0, int t) {
#pragma unroll
    for (int i = 0; i < 4; ++i) {
        int idx = t + i * 256;
        if constexpr (!TR) {
            int r = idx >> 3, c = idx & 7;
            const __half* s = src + (size_t)r * ld + k0 + c * 8;
            CP16(dst + r * 128 + ((c ^ (r & 7)) << 4), s);
        } else {
            int k = idx >> 4, c = idx & 15;
            const __half* s = src + (size_t)(k0 + k) * ld + c * 8;
            CP16(dst + k * 256 + ((c ^ (k & 7)) << 4), s);
        }
    }
}

template <bool TA, bool TB, bool BIAS, bool STATS>
__global__ __launch_bounds__(256, 2)
void mm_f16(const __half* __restrict__ A, const __half* __restrict__ Bm,
            const float* __restrict__ bias, __half* __restrict__ Out,
            int K, int ldA, int ldB,
            long strideA, long strideB, long strideO,
            float* gs, float* gs2) {
    extern __shared__ __align__(128) char smem[];
    const uint32_t sb = smem_u32(smem);
    const int t = threadIdx.x;
    const int l = t & 31;
    const int w = t >> 5;
    const int wm = (w >> 2) * 64;
    const int wn = (w & 3) * 32;
    const int m0 = blockIdx.y * 128;
    const int n0 = blockIdx.x * 128;
    const __half* Ab = A  + (size_t)blockIdx.z * strideA + (TA ? m0 : (size_t)m0 * ldA);
    const __half* Bb = Bm + (size_t)blockIdx.z * strideB + (TB ? n0 : (size_t)n0 * ldB);

    float acc[4][4][4];
#pragma unroll
    for (int mt = 0; mt < 4; ++mt)
#pragma unroll
        for (int nt = 0; nt < 4; ++nt)
#pragma unroll
            for (int q = 0; q < 4; ++q) acc[mt][nt][q] = 0.f;

    const int S = K / 64;
    // prologue: stages 0,1 into bufs 0,1
    stage_tile<TA>(Ab, ldA, sb,                 0, t);
    stage_tile<TB>(Bb, ldB, sb + 49152,         0, t);
    CP_COMMIT();
    stage_tile<TA>(Ab, ldA, sb + 16384,        64, t);
    stage_tile<TB>(Bb, ldB, sb + 49152 + 16384, 64, t);
    CP_COMMIT();

    int rb = 0;   // buffer holding chunk s
    for (int s = 0; s < S; ++s) {
        if (s == S - 1) { CP_WAIT0(); } else { CP_WAIT1(); }
        __syncthreads();
        // stage chunk s+2 into buf (rb+2)%3 == (s-1)%3 — safe after the sync above
        if (s + 2 < S) {
            int sbuf = rb >= 1 ? rb - 1 : rb + 2;
            stage_tile<TA>(Ab, ldA, sb + sbuf * 16384,         (s + 2) * 64, t);
            stage_tile<TB>(Bb, ldB, sb + 49152 + sbuf * 16384, (s + 2) * 64, t);
            CP_COMMIT();
        }

        const uint32_t abase = sb + rb * 16384;
        const uint32_t bbase = sb + 49152 + rb * 16384;
#pragma unroll
        for (int ks = 0; ks < 4; ++ks) {
            uint32_t af[4][4], bf[2][4];
#pragma unroll
            for (int mt = 0; mt < 4; ++mt) {
                if constexpr (!TA) {
                    int row = wm + mt * 16 + (l & 7) + ((l >> 3) & 1) * 8;
                    int ch  = ks * 2 + (l >> 4);
                    LDSM4(af[mt], abase + row * 128 + ((ch ^ (row & 7)) << 4));
                } else {
                    int kr = ks * 16 + (l & 7) + (l >> 4) * 8;
                    int ch = ((wm + mt * 16) >> 3) + ((l >> 3) & 1);
                    LDSM4T(af[mt], abase + kr * 256 + ((ch ^ (kr & 7)) << 4));
                }
            }
#pragma unroll
            for (int np = 0; np < 2; ++np) {
                if constexpr (!TB) {
                    int row = wn + np * 16 + (l & 7) + (l >> 4) * 8;
                    int ch  = ks * 2 + ((l >> 3) & 1);
                    LDSM4(bf[np], bbase + row * 128 + ((ch ^ (row & 7)) << 4));
                } else {
                    int kr = ks * 16 + (l & 7) + ((l >> 3) & 1) * 8;
                    int ch = ((wn + np * 16) >> 3) + (l >> 4);
                    LDSM4T(bf[np], bbase + kr * 256 + ((ch ^ (kr & 7)) << 4));
                }
            }
#pragma unroll
            for (int mt = 0; mt < 4; ++mt)
#pragma unroll
                for (int nt = 0; nt < 4; ++nt)
                    mma_f16(acc[mt][nt], af[mt], &bf[nt >> 1][(nt & 1) * 2]);
        }
        rb = rb == 2 ? 0 : rb + 1;
    }

    if constexpr (STATS) {
        __syncthreads();
        if (t < 256) ((float*)smem)[t] = 0.f;
        __syncthreads();
    }

#pragma unroll
    for (int mt = 0; mt < 4; ++mt) {
        const int row = m0 + wm + mt * 16 + (l >> 2);
        float bv0 = 0.f, bv1 = 0.f;
        if constexpr (BIAS) { bv0 = bias[row]; bv1 = bias[row + 8]; }
        __half* Ob = Out + (size_t)blockIdx.z * strideO;
        float s0 = 0.f, q0 = 0.f, s1 = 0.f, q1 = 0.f;
#pragma unroll
        for (int nt = 0; nt < 4; ++nt) {
            const int col = n0 + wn + nt * 8 + 2 * (l & 3);
            float v00 = acc[mt][nt][0] + bv0, v01 = acc[mt][nt][1] + bv0;
            float v10 = acc[mt][nt][2] + bv1, v11 = acc[mt][nt][3] + bv1;
            *(__half2*)(Ob + (size_t)row * N_ + col)       = __floats2half2_rn(v00, v01);
            *(__half2*)(Ob + (size_t)(row + 8) * N_ + col) = __floats2half2_rn(v10, v11);
            if constexpr (STATS) {
                s0 += v00 + v01; q0 += v00 * v00 + v01 * v01;
                s1 += v10 + v11; q1 += v10 * v10 + v11 * v11;
            }
        }
        if constexpr (STATS) {
            s0 += __shfl_xor_sync(~0u, s0, 1); s0 += __shfl_xor_sync(~0u, s0, 2);
            q0 += __shfl_xor_sync(~0u, q0, 1); q0 += __shfl_xor_sync(~0u, q0, 2);
            s1 += __shfl_xor_sync(~0u, s1, 1); s1 += __shfl_xor_sync(~0u, s1, 2);
            q1 += __shfl_xor_sync(~0u, q1, 1); q1 += __shfl_xor_sync(~0u, q1, 2);
            if ((l & 3) == 0) {
                const int lr = wm + mt * 16 + (l >> 2);
                float* ss = (float*)smem;
                atomicAdd(ss + lr, s0);       atomicAdd(ss + 128 + lr, q0);
                atomicAdd(ss + lr + 8, s1);   atomicAdd(ss + 128 + lr + 8, q1);
            }
        }
    }

    if constexpr (STATS) {
        __syncthreads();
        if (t < 128) {
            atomicAdd(gs  + m0 + t, ((float*)smem)[t]);
            atomicAdd(gs2 + m0 + t, ((float*)smem)[t + 128]);
        }
    }
}

// =====================================================================
//          Flash-fused attention (reads from stacked GTP tensor)
// =====================================================================
#define FL_SMEM (192 * 1024)
#define GSTRIDE ((size_t)768 * N_)

template <int ROWS>
static __device__ __forceinline__ void stage256(const __half* __restrict__ src, uint32_t dst, int t) {
#pragma unroll
    for (int i = 0; i < ROWS / 16; ++i) {
        int idx = t + i * 256;
        int r = idx >> 4, c = idx & 15;
        CP16(dst + r * 256 + ((c ^ (r & 7)) << 4), src + (size_t)r * N_ + c * 8);
    }
}

__global__ __launch_bounds__(256, 1)
void flash_kernel(const __half* __restrict__ GTP, __half* __restrict__ Y) {
    extern __shared__ __align__(128) char smem[];
    const uint32_t sb = smem_u32(smem);
    const int t = threadIdx.x, l = t & 31, w = t >> 5;
    const int n0 = blockIdx.x * 128;
    const __half* Gb = GTP + (size_t)blockIdx.y * GSTRIDE;
    const __half* Tb = Gb + (size_t)256 * N_;
    const __half* Pb = Gb + (size_t)512 * N_;
    const uint32_t ph0 = sb + 65536, gbuf = sb + 131072;

    float oacc[32][4];
#pragma unroll
    for (int nt = 0; nt < 32; ++nt)
#pragma unroll
        for (int q = 0; q < 4; ++q) oacc[nt][q] = 0.f;
    float M0 = -1e30f, M1 = -1e30f, L0 = 0.f, L1 = 0.f;

    stage256<256>(Tb + n0, sb, t);
    stage256<128>(Pb + 0, ph0, t);
    CP_COMMIT();
    stage256<256>(Gb + 0, gbuf, t);
    CP_COMMIT();
    stage256<128>(Pb + (size_t)128 * N_ + 0, ph0 + 32768, t);
    CP_COMMIT();

    for (int it = 0; it < 8; ++it) {
        const int m0 = it * 128;
        float sacc[16][4];
#pragma unroll
        for (int nt = 0; nt < 16; ++nt)
#pragma unroll
            for (int q = 0; q < 4; ++q) sacc[nt][q] = 0.f;

#pragma unroll
        for (int h = 0; h < 2; ++h) {
            if (h == 0) { CP_WAIT2(); }
            else if (it == 0 || it == 7) { CP_WAIT1(); } else { CP_WAIT2(); }
            __syncthreads();
            const uint32_t phb = ph0 + h * 32768;
#pragma unroll
            for (int j = 0; j < 8; ++j) {
                uint32_t af[4];
                {
                    int kr = (h * 8 + j) * 16 + (l & 7) + (l >> 4) * 8;
                    int ch = 2 * w + ((l >> 3) & 1);
                    LDSM4T(af, sb + kr * 256 + ((ch ^ (kr & 7)) << 4));
                }
#pragma unroll
                for (int jj = 0; jj < 8; ++jj) {
                    uint32_t bf[4];
                    {
                        int kr = j * 16 + (l & 7) + ((l >> 3) & 1) * 8;
                        int ch = 2 * jj + (l >> 4);
                        LDSM4T(bf, phb + kr * 256 + ((ch ^ (kr & 7)) << 4));
                    }
                    mma_f16(sacc[2 * jj],     af, bf);
                    mma_f16(sacc[2 * jj + 1], af, bf + 2);
                }
            }
            __syncthreads();
            if (it < 7) {
                stage256<128>(Pb + (size_t)(h * 128) * N_ + m0 + 128, phb, t);
                CP_COMMIT();
            }
        }

        float tmax0 = -1e30f, tmax1 = -1e30f;
#pragma unroll
        for (int nt = 0; nt < 16; ++nt) {
            tmax0 = fmaxf(tmax0, fmaxf(sacc[nt][0], sacc[nt][1]));
            tmax1 = fmaxf(tmax1, fmaxf(sacc[nt][2], sacc[nt][3]));
        }
        tmax0 = fmaxf(tmax0, __shfl_xor_sync(~0u, tmax0, 1));
        tmax0 = fmaxf(tmax0, __shfl_xor_sync(~0u, tmax0, 2));
        tmax1 = fmaxf(tmax1, __shfl_xor_sync(~0u, tmax1, 1));
        tmax1 = fmaxf(tmax1, __shfl_xor_sync(~0u, tmax1, 2));
        float Mn0 = fmaxf(M0, tmax0), Mn1 = fmaxf(M1, tmax1);
        float sc0 = __expf(M0 - Mn0), sc1 = __expf(M1 - Mn1);
        float ts0 = 0.f, ts1 = 0.f;
        uint32_t afp[8][4];
#pragma unroll
        for (int j = 0; j < 8; ++j) {
            float p00 = __expf(sacc[2 * j][0] - Mn0);
            float p01 = __expf(sacc[2 * j][1] - Mn0);
            float p02 = __expf(sacc[2 * j][2] - Mn1);
            float p03 = __expf(sacc[2 * j][3] - Mn1);
            float p10 = __expf(sacc[2 * j + 1][0] - Mn0);
            float p11 = __expf(sacc[2 * j + 1][1] - Mn0);
            float p12 = __expf(sacc[2 * j + 1][2] - Mn1);
            float p13 = __expf(sacc[2 * j + 1][3] - Mn1);
            ts0 += p00 + p01 + p10 + p11;
            ts1 += p02 + p03 + p12 + p13;
            afp[j][0] = h2pack(p00, p01);
            afp[j][1] = h2pack(p02, p03);
            afp[j][2] = h2pack(p10, p11);
            afp[j][3] = h2pack(p12, p13);
        }
        ts0 += __shfl_xor_sync(~0u, ts0, 1); ts0 += __shfl_xor_sync(~0u, ts0, 2);
        ts1 += __shfl_xor_sync(~0u, ts1, 1); ts1 += __shfl_xor_sync(~0u, ts1, 2);
        L0 = L0 * sc0 + ts0; L1 = L1 * sc1 + ts1;
        M0 = Mn0; M1 = Mn1;
#pragma unroll
        for (int nt = 0; nt < 32; ++nt) {
            oacc[nt][0] *= sc0; oacc[nt][1] *= sc0;
            oacc[nt][2] *= sc1; oacc[nt][3] *= sc1;
        }

        if (it < 7) { CP_WAIT2(); } else { CP_WAIT0(); }
        __syncthreads();
#pragma unroll
        for (int ks = 0; ks < 8; ++ks) {
#pragma unroll
            for (int jj = 0; jj < 16; ++jj) {
                uint32_t bf[4];
                {
                    int row = 16 * jj + (l & 7) + (l >> 4) * 8;
                    int ch  = ks * 2 + ((l >> 3) & 1);
                    LDSM4(bf, gbuf + row * 256 + ((ch ^ (row & 7)) << 4));
                }
                mma_f16(oacc[2 * jj],     afp[ks], bf);
                mma_f16(oacc[2 * jj + 1], afp[ks], bf + 2);
            }
        }
        __syncthreads();
        if (it < 7) {
            stage256<256>(Gb + m0 + 128, gbuf, t);
            CP_COMMIT();
        }
    }

    const float i0 = 1.f / L0, i1 = 1.f / L1;
    __half* Yb = Y + (size_t)blockIdx.y * N_ * CI_;
    const int row0 = n0 + w * 16 + (l >> 2);
#pragma unroll
    for (int nt = 0; nt < 32; ++nt) {
        const int col = nt * 8 + (l & 3) * 2;
        *(__half2*)(Yb + (size_t)row0 * CI_ + col) =
            __floats2half2_rn(oacc[nt][0] * i0, oacc[nt][1] * i0);
        *(__half2*)(Yb + (size_t)(row0 + 8) * CI_ + col) =
            __floats2half2_rn(oacc[nt][2] * i1, oacc[nt][3] * i1);
    }
}

// ---------------- prep: zero stats + cvt x + pack weights/biases ----------------
#define XQ_ (B_ * C_ * N_ / 4)       // 4194304
#define WQ_ ((768 * C_) / 4)         // 98304
#define ZQ_ ((C_ * CI_) / 4)         // 32768

__global__ __launch_bounds__(256)
void prep_kernel(const float* __restrict__ x,
                 const float* __restrict__ Wg, const float* __restrict__ Wt,
                 const float* __restrict__ Wp, const float* __restrict__ Wz,
                 const float* __restrict__ bg, const float* __restrict__ bt,
                 const float* __restrict__ bp,
                 __half* __restrict__ x16,
                 __half* __restrict__ Wstk, __half* __restrict__ Wz16,
                 float* __restrict__ bstk) {
    int i = blockIdx.x * 256 + threadIdx.x;
    if (i < XQ_) {
        float4 v = ((const float4*)x)[i];
        __half2 h0 = __floats2half2_rn(v.x, v.y);
        __half2 h1 = __floats2half2_rn(v.z, v.w);
        uint2 u = { *(uint32_t*)&h0, *(uint32_t*)&h1 };
        ((uint2*)x16)[i] = u;
        return;
    }
    int j = i - XQ_;
    if (j < WQ_) {
        int row = (j * 4) >> 9;
        int col = (j * 4) & 511;
        const float* src = row < 256 ? Wg + row * C_
                         : row < 512 ? Wt + (row - 256) * C_
                                     : Wp + (row - 512) * C_;
        float4 v = *(const float4*)(src + col);
        __half2 h0 = __floats2half2_rn(v.x, v.y);
        __half2 h1 = __floats2half2_rn(v.z, v.w);
        uint2 u = { *(uint32_t*)&h0, *(uint32_t*)&h1 };
        ((uint2*)Wstk)[j] = u;
    } else if (j < WQ_ + ZQ_) {
        int k = j - WQ_;
        float4 v = ((const float4*)Wz)[k];
        __half2 h0 = __floats2half2_rn(v.x, v.y);
        __half2 h1 = __floats2half2_rn(v.z, v.w);
        uint2 u = { *(uint32_t*)&h0, *(uint32_t*)&h1 };
        ((uint2*)Wz16)[k] = u;
    } else if (j < WQ_ + ZQ_ + 192) {
        int e = (j - WQ_ - ZQ_) * 4;
#pragma unroll
        for (int q = 0; q < 4; ++q) {
            int r = e + q;
            bstk[r] = r < 256 ? bg[r] : r < 512 ? bt[r - 256] : bp[r - 512];
        }
    } else if (j < WQ_ + ZQ_ + 192 + 128) {
        int c = (j - WQ_ - ZQ_ - 192) * 4;
#pragma unroll
        for (int q = 0; q < 4; ++q) { d_ssum[c + q] = 0.f; d_ssq[c + q] = 0.f; }
    }
}

__global__ __launch_bounds__(256)
void scaleshift_kernel(const float* __restrict__ gamma, const float* __restrict__ beta) {
    int c = blockIdx.x * 256 + threadIdx.x;
    const float invN = 1.0f / (float)(B_ * N_);
    float mean = d_ssum[c] * invN;
    float var  = d_ssq[c] * invN - mean * mean;
    float inv  = rsqrtf(var + 1e-5f);
    float sc   = gamma[c] * inv;
    d_scale[c] = sc;
    d_shift[c] = beta[c] - mean * sc;
}

__global__ __launch_bounds__(256)
void finalize_kernel(const __half* __restrict__ WY, const float* __restrict__ x,
                     float* __restrict__ out) {
    size_t i4 = (size_t)blockIdx.x * 256 + threadIdx.x;
    int c = (int)((i4 >> 8) & (C_ - 1));
    float sc = d_scale[c], sh = d_shift[c];
    uint2 u = ((const uint2*)WY)[i4];
    float2 w0 = __half22float2(*(__half2*)&u.x);
    float2 w1 = __half22float2(*(__half2*)&u.y);
    float4 xv = ((const float4*)x)[i4];
    float4 o;
    o.x = w0.x * sc + sh + xv.x;
    o.y = w0.y * sc + sh + xv.y;
    o.z = w1.x * sc + sh + xv.z;
    o.w = w1.y * sc + sh + xv.w;
    ((float4*)out)[i4] = o;
}

// ---------------- launch ----------------
extern "C" void kernel_launch(void* const* d_in, const int* in_sizes, int n_in,
                              void* d_out, int out_size) {
    const float* x     = (const float*)d_in[0];
    const float* Wg    = (const float*)d_in[1];
    const float* bg    = (const float*)d_in[2];
    const float* Wt    = (const float*)d_in[3];
    const float* bt    = (const float*)d_in[4];
    const float* Wp    = (const float*)d_in[5];
    const float* bp    = (const float*)d_in[6];
    const float* Wz    = (const float*)d_in[7];
    const float* bz    = (const float*)d_in[8];
    const float* gamma = (const float*)d_in[9];
    const float* beta  = (const float*)d_in[10];
    float* out = (float*)d_out;

    __half *x16, *Wstk, *Wz16, *GTP, *Yh, *WYh;
    float *bstk, *gs, *gs2;
    cudaGetSymbolAddress((void**)&x16,  d_x16);
    cudaGetSymbolAddress((void**)&Wstk, d_Wstk);
    cudaGetSymbolAddress((void**)&Wz16, d_Wz16);
    cudaGetSymbolAddress((void**)&GTP,  d_GTP);
    cudaGetSymbolAddress((void**)&Yh,   d_Yh);
    cudaGetSymbolAddress((void**)&WYh,  d_WYh);
    cudaGetSymbolAddress((void**)&bstk, d_bstk);
    cudaGetSymbolAddress((void**)&gs,   d_ssum);
    cudaGetSymbolAddress((void**)&gs2,  d_ssq);

    cudaFuncSetAttribute(mm_f16<false, true,  true, false>, cudaFuncAttributeMaxDynamicSharedMemorySize, SMEM_BYTES);
    cudaFuncSetAttribute(mm_f16<false, false, true, true >, cudaFuncAttributeMaxDynamicSharedMemorySize, SMEM_BYTES);
    cudaFuncSetAttribute(flash_kernel, cudaFuncAttributeMaxDynamicSharedMemorySize, FL_SMEM);

    const long sC  = (long)C_ * N_;
    const long sCi = (long)CI_ * N_;

    prep_kernel<<<(XQ_ + WQ_ + ZQ_ + 192 + 128 + 255) / 256, 256>>>(
        x, Wg, Wt, Wp, Wz, bg, bt, bp, x16, Wstk, Wz16, bstk);

    // stacked projections: GTP[b] (768 x N) = Wstk (768 x C) * x[b] (C x N)
    mm_f16<false, true, true, false><<<dim3(8, 6, 32), 256, SMEM_BYTES>>>(
        Wstk, x16, bstk, GTP, C_, C_, N_, 0, sC, (long)GSTRIDE, nullptr, nullptr);

    // fused attention: Y[b][n][ci]
    flash_kernel<<<dim3(8, 32), 256, FL_SMEM>>>(GTP, Yh);

    // z-conv + BN partial stats: WY[b] (C x N) = Wz (C x Ci) * Y[b] (N x Ci)
    mm_f16<false, false, true, true><<<dim3(8, 4, 32), 256, SMEM_BYTES>>>(
        Wz16, Yh, bz, WYh, CI_, CI_, CI_, 0, sCi, sC, gs, gs2);

    scaleshift_kernel<<<2, 256>>>(gamma, beta);
    finalize_kernel<<<(B_ * C_ * N_) / 4 / 256, 256>>>(WYh, x, out);
}

// round 9
// speedup vs baseline: 7.3128x; 1.0232x over previous
#include <cuda_runtime.h>
#include <cuda_fp16.h>
#include <cstdint>

// Problem constants
#define B_  32
#define C_  512
#define CI_ 256
#define N_  1024   // H*W

// ---------------- static device scratch ----------------
__device__ __align__(128) __half d_x16[(size_t)B_ * C_ * N_];
__device__ __align__(128) __half d_Wstk[768 * C_];              // [g;theta;phi] stacked
__device__ __align__(128) float  d_bstk[768];
__device__ __align__(128) __half d_Wz16[C_ * CI_];
__device__ __align__(128) __half d_GTP[(size_t)B_ * 768 * N_];  // [b][768][N]
__device__ __align__(128) __half d_Yh[(size_t)B_ * N_ * CI_];   // y [b][N][Ci]
__device__ __align__(128) __half d_WYh[(size_t)B_ * C_ * N_];
__device__ float d_ssum[C_];
__device__ float d_ssq[C_];

// ---------------- helpers ----------------
static __device__ __forceinline__ uint32_t smem_u32(const void* p) {
    uint32_t a;
    asm("{ .reg .u64 t; cvta.to.shared.u64 t, %1; cvt.u32.u64 %0, t; }" : "=r"(a) : "l"(p));
    return a;
}

#define CP16(dst, src) \
    asm volatile("cp.async.cg.shared.global [%0], [%1], 16;" :: "r"(dst), "l"(src))
#define CP_COMMIT() asm volatile("cp.async.commit_group;" ::: "memory")
#define CP_WAIT0()  asm volatile("cp.async.wait_group 0;" ::: "memory")
#define CP_WAIT1()  asm volatile("cp.async.wait_group 1;" ::: "memory")
#define CP_WAIT2()  asm volatile("cp.async.wait_group 2;" ::: "memory")

#define LDSM4(r, addr) \
    asm volatile("ldmatrix.sync.aligned.m8n8.x4.shared.b16 {%0,%1,%2,%3}, [%4];" \
        : "=r"((r)[0]), "=r"((r)[1]), "=r"((r)[2]), "=r"((r)[3]) : "r"(addr))
#define LDSM4T(r, addr) \
    asm volatile("ldmatrix.sync.aligned.m8n8.x4.trans.shared.b16 {%0,%1,%2,%3}, [%4];" \
        : "=r"((r)[0]), "=r"((r)[1]), "=r"((r)[2]), "=r"((r)[3]) : "r"(addr))

static __device__ __forceinline__ void mma_f16(float* c, const uint32_t* a, const uint32_t* b) {
    asm volatile(
        "mma.sync.aligned.m16n8k16.row.col.f32.f16.f16.f32 "
        "{%0,%1,%2,%3},{%4,%5,%6,%7},{%8,%9},{%0,%1,%2,%3};"
        : "+f"(c[0]), "+f"(c[1]), "+f"(c[2]), "+f"(c[3])
        : "r"(a[0]), "r"(a[1]), "r"(a[2]), "r"(a[3]), "r"(b[0]), "r"(b[1]));
}

static __device__ __forceinline__ uint32_t h2pack(float a, float b) {
    __half2 h = __floats2half2_rn(a, b);
    return *(uint32_t*)&h;
}

// =====================================================================
//     GEMM: 128x128 block, 128 threads (2x2 warps, 64x64 warp tiles)
//     3-stage cp.async pipeline. A always [M][K] K-major.
// =====================================================================
// SMEM: A bufs @0,16K,32K; B bufs @48K,64K,80K  (96 KB)
#define SMEM_BYTES (96 * 1024)

template <bool TR>
static __device__ __forceinline__ void stage_tile128(const __half* __restrict__ src, int ld,
                                                     uint32_t dst, int k0, int t) {
#pragma unroll
    for (int i = 0; i < 8; ++i) {
        int idx = t + i * 128;
        if constexpr (!TR) {
            int r = idx >> 3, c = idx & 7;
            const __half* s = src + (size_t)r * ld + k0 + c * 8;
            CP16(dst + r * 128 + ((c ^ (r & 7)) << 4), s);
        } else {
            int k = idx >> 4, c = idx & 15;
            const __half* s = src + (size_t)(k0 + k) * ld + c * 8;
            CP16(dst + k * 256 + ((c ^ (k & 7)) << 4), s);
        }
    }
}

template <bool TB, bool BIAS, bool STATS>
__global__ __launch_bounds__(128, 2)
void mm_f16(const __half* __restrict__ A, const __half* __restrict__ Bm,
            const float* __restrict__ bias, __half* __restrict__ Out,
            int K, int ldA, int ldB,
            long strideA, long strideB, long strideO,
            float* gs, float* gs2) {
    extern __shared__ __align__(128) char smem[];
    const uint32_t sb = smem_u32(smem);
    const int t = threadIdx.x;
    const int l = t & 31;
    const int w = t >> 5;            // 0..3
    const int wm = (w >> 1) * 64;
    const int wn = (w & 1) * 64;
    const int m0 = blockIdx.y * 128;
    const int n0 = blockIdx.x * 128;
    const __half* Ab = A  + (size_t)blockIdx.z * strideA + (size_t)m0 * ldA;
    const __half* Bb = Bm + (size_t)blockIdx.z * strideB + (TB ? n0 : (size_t)n0 * ldB);

    float acc[4][8][4];
#pragma unroll
    for (int mt = 0; mt < 4; ++mt)
#pragma unroll
        for (int nt = 0; nt < 8; ++nt)
#pragma unroll
            for (int q = 0; q < 4; ++q) acc[mt][nt][q] = 0.f;

    const int S = K / 64;
    stage_tile128<false>(Ab, ldA, sb,                 0, t);
    stage_tile128<TB>   (Bb, ldB, sb + 49152,         0, t);
    CP_COMMIT();
    stage_tile128<false>(Ab, ldA, sb + 16384,        64, t);
    stage_tile128<TB>   (Bb, ldB, sb + 49152 + 16384, 64, t);
    CP_COMMIT();

    int rb = 0;
    for (int s = 0; s < S; ++s) {
        if (s == S - 1) { CP_WAIT0(); } else { CP_WAIT1(); }
        __syncthreads();
        if (s + 2 < S) {
            int sbuf = rb >= 1 ? rb - 1 : rb + 2;
            stage_tile128<false>(Ab, ldA, sb + sbuf * 16384,         (s + 2) * 64, t);
            stage_tile128<TB>   (Bb, ldB, sb + 49152 + sbuf * 16384, (s + 2) * 64, t);
            CP_COMMIT();
        }

        const uint32_t abase = sb + rb * 16384;
        const uint32_t bbase = sb + 49152 + rb * 16384;
#pragma unroll
        for (int ks = 0; ks < 4; ++ks) {
            uint32_t af[4][4], bf[4][4];
#pragma unroll
            for (int mt = 0; mt < 4; ++mt) {
                int row = wm + mt * 16 + (l & 7) + ((l >> 3) & 1) * 8;
                int ch  = ks * 2 + (l >> 4);
                LDSM4(af[mt], abase + row * 128 + ((ch ^ (row & 7)) << 4));
            }
#pragma unroll
            for (int np = 0; np < 4; ++np) {
                if constexpr (!TB) {
                    int row = wn + np * 16 + (l & 7) + (l >> 4) * 8;
                    int ch  = ks * 2 + ((l >> 3) & 1);
                    LDSM4(bf[np], bbase + row * 128 + ((ch ^ (row & 7)) << 4));
                } else {
                    int kr = ks * 16 + (l & 7) + ((l >> 3) & 1) * 8;
                    int ch = ((wn + np * 16) >> 3) + (l >> 4);
                    LDSM4T(bf[np], bbase + kr * 256 + ((ch ^ (kr & 7)) << 4));
                }
            }
#pragma unroll
            for (int mt = 0; mt < 4; ++mt)
#pragma unroll
                for (int nt = 0; nt < 8; ++nt)
                    mma_f16(acc[mt][nt], af[mt], &bf[nt >> 1][(nt & 1) * 2]);
        }
        rb = rb == 2 ? 0 : rb + 1;
    }

    if constexpr (STATS) {
        __syncthreads();
        ((float*)smem)[t] = 0.f;
        ((float*)smem)[t + 128] = 0.f;
        __syncthreads();
    }

#pragma unroll
    for (int mt = 0; mt < 4; ++mt) {
        const int row = m0 + wm + mt * 16 + (l >> 2);
        float bv0 = 0.f, bv1 = 0.f;
        if constexpr (BIAS) { bv0 = bias[row]; bv1 = bias[row + 8]; }
        __half* Ob = Out + (size_t)blockIdx.z * strideO;
        float s0 = 0.f, q0 = 0.f, s1 = 0.f, q1 = 0.f;
#pragma unroll
        for (int nt = 0; nt < 8; ++nt) {
            const int col = n0 + wn + nt * 8 + 2 * (l & 3);
            float v00 = acc[mt][nt][0] + bv0, v01 = acc[mt][nt][1] + bv0;
            float v10 = acc[mt][nt][2] + bv1, v11 = acc[mt][nt][3] + bv1;
            *(__half2*)(Ob + (size_t)row * N_ + col)       = __floats2half2_rn(v00, v01);
            *(__half2*)(Ob + (size_t)(row + 8) * N_ + col) = __floats2half2_rn(v10, v11);
            if constexpr (STATS) {
                s0 += v00 + v01; q0 += v00 * v00 + v01 * v01;
                s1 += v10 + v11; q1 += v10 * v10 + v11 * v11;
            }
        }
        if constexpr (STATS) {
            s0 += __shfl_xor_sync(~0u, s0, 1); s0 += __shfl_xor_sync(~0u, s0, 2);
            q0 += __shfl_xor_sync(~0u, q0, 1); q0 += __shfl_xor_sync(~0u, q0, 2);
            s1 += __shfl_xor_sync(~0u, s1, 1); s1 += __shfl_xor_sync(~0u, s1, 2);
            q1 += __shfl_xor_sync(~0u, q1, 1); q1 += __shfl_xor_sync(~0u, q1, 2);
            if ((l & 3) == 0) {
                const int lr = wm + mt * 16 + (l >> 2);
                float* ss = (float*)smem;
                atomicAdd(ss + lr, s0);       atomicAdd(ss + 128 + lr, q0);
                atomicAdd(ss + lr + 8, s1);   atomicAdd(ss + 128 + lr + 8, q1);
            }
        }
    }

    if constexpr (STATS) {
        __syncthreads();
        atomicAdd(gs  + m0 + t, ((float*)smem)[t]);
        atomicAdd(gs2 + m0 + t, ((float*)smem)[t + 128]);
    }
}

// =====================================================================
//          Flash-fused attention (reads from stacked GTP tensor)
// =====================================================================
#define FL_SMEM (192 * 1024)
#define GSTRIDE ((size_t)768 * N_)

template <int ROWS>
static __device__ __forceinline__ void stage256(const __half* __restrict__ src, uint32_t dst, int t) {
#pragma unroll
    for (int i = 0; i < ROWS / 16; ++i) {
        int idx = t + i * 256;
        int r = idx >> 4, c = idx & 15;
        CP16(dst + r * 256 + ((c ^ (r & 7)) << 4), src + (size_t)r * N_ + c * 8);
    }
}

__global__ __launch_bounds__(256, 1)
void flash_kernel(const __half* __restrict__ GTP, __half* __restrict__ Y) {
    extern __shared__ __align__(128) char smem[];
    const uint32_t sb = smem_u32(smem);
    const int t = threadIdx.x, l = t & 31, w = t >> 5;
    const int n0 = blockIdx.x * 128;
    const __half* Gb = GTP + (size_t)blockIdx.y * GSTRIDE;
    const __half* Tb = Gb + (size_t)256 * N_;
    const __half* Pb = Gb + (size_t)512 * N_;
    const uint32_t ph0 = sb + 65536, gbuf = sb + 131072;

    float oacc[32][4];
#pragma unroll
    for (int nt = 0; nt < 32; ++nt)
#pragma unroll
        for (int q = 0; q < 4; ++q) oacc[nt][q] = 0.f;
    float M0 = -1e30f, M1 = -1e30f, L0 = 0.f, L1 = 0.f;

    stage256<256>(Tb + n0, sb, t);
    stage256<128>(Pb + 0, ph0, t);
    CP_COMMIT();
    stage256<256>(Gb + 0, gbuf, t);
    CP_COMMIT();
    stage256<128>(Pb + (size_t)128 * N_ + 0, ph0 + 32768, t);
    CP_COMMIT();

    for (int it = 0; it < 8; ++it) {
        const int m0 = it * 128;
        float sacc[16][4];
#pragma unroll
        for (int nt = 0; nt < 16; ++nt)
#pragma unroll
            for (int q = 0; q < 4; ++q) sacc[nt][q] = 0.f;

#pragma unroll
        for (int h = 0; h < 2; ++h) {
            if (h == 0) { CP_WAIT2(); }
            else if (it == 0 || it == 7) { CP_WAIT1(); } else { CP_WAIT2(); }
            __syncthreads();
            const uint32_t phb = ph0 + h * 32768;
#pragma unroll
            for (int j = 0; j < 8; ++j) {
                uint32_t af[4];
                {
                    int kr = (h * 8 + j) * 16 + (l & 7) + (l >> 4) * 8;
                    int ch = 2 * w + ((l >> 3) & 1);
                    LDSM4T(af, sb + kr * 256 + ((ch ^ (kr & 7)) << 4));
                }
#pragma unroll
                for (int jj = 0; jj < 8; ++jj) {
                    uint32_t bf[4];
                    {
                        int kr = j * 16 + (l & 7) + ((l >> 3) & 1) * 8;
                        int ch = 2 * jj + (l >> 4);
                        LDSM4T(bf, phb + kr * 256 + ((ch ^ (kr & 7)) << 4));
                    }
                    mma_f16(sacc[2 * jj],     af, bf);
                    mma_f16(sacc[2 * jj + 1], af, bf + 2);
                }
            }
            __syncthreads();
            if (it < 7) {
                stage256<128>(Pb + (size_t)(h * 128) * N_ + m0 + 128, phb, t);
                CP_COMMIT();
            }
        }

        float tmax0 = -1e30f, tmax1 = -1e30f;
#pragma unroll
        for (int nt = 0; nt < 16; ++nt) {
            tmax0 = fmaxf(tmax0, fmaxf(sacc[nt][0], sacc[nt][1]));
            tmax1 = fmaxf(tmax1, fmaxf(sacc[nt][2], sacc[nt][3]));
        }
        tmax0 = fmaxf(tmax0, __shfl_xor_sync(~0u, tmax0, 1));
        tmax0 = fmaxf(tmax0, __shfl_xor_sync(~0u, tmax0, 2));
        tmax1 = fmaxf(tmax1, __shfl_xor_sync(~0u, tmax1, 1));
        tmax1 = fmaxf(tmax1, __shfl_xor_sync(~0u, tmax1, 2));
        float Mn0 = fmaxf(M0, tmax0), Mn1 = fmaxf(M1, tmax1);
        float sc0 = __expf(M0 - Mn0), sc1 = __expf(M1 - Mn1);
        float ts0 = 0.f, ts1 = 0.f;
        uint32_t afp[8][4];
#pragma unroll
        for (int j = 0; j < 8; ++j) {
            float p00 = __expf(sacc[2 * j][0] - Mn0);
            float p01 = __expf(sacc[2 * j][1] - Mn0);
            float p02 = __expf(sacc[2 * j][2] - Mn1);
            float p03 = __expf(sacc[2 * j][3] - Mn1);
            float p10 = __expf(sacc[2 * j + 1][0] - Mn0);
            float p11 = __expf(sacc[2 * j + 1][1] - Mn0);
            float p12 = __expf(sacc[2 * j + 1][2] - Mn1);
            float p13 = __expf(sacc[2 * j + 1][3] - Mn1);
            ts0 += p00 + p01 + p10 + p11;
            ts1 += p02 + p03 + p12 + p13;
            afp[j][0] = h2pack(p00, p01);
            afp[j][1] = h2pack(p02, p03);
            afp[j][2] = h2pack(p10, p11);
            afp[j][3] = h2pack(p12, p13);
        }
        ts0 += __shfl_xor_sync(~0u, ts0, 1); ts0 += __shfl_xor_sync(~0u, ts0, 2);
        ts1 += __shfl_xor_sync(~0u, ts1, 1); ts1 += __shfl_xor_sync(~0u, ts1, 2);
        L0 = L0 * sc0 + ts0; L1 = L1 * sc1 + ts1;
        M0 = Mn0; M1 = Mn1;
#pragma unroll
        for (int nt = 0; nt < 32; ++nt) {
            oacc[nt][0] *= sc0; oacc[nt][1] *= sc0;
            oacc[nt][2] *= sc1; oacc[nt][3] *= sc1;
        }

        if (it < 7) { CP_WAIT2(); } else { CP_WAIT0(); }
        __syncthreads();
#pragma unroll
        for (int ks = 0; ks < 8; ++ks) {
#pragma unroll
            for (int jj = 0; jj < 16; ++jj) {
                uint32_t bf[4];
                {
                    int row = 16 * jj + (l & 7) + (l >> 4) * 8;
                    int ch  = ks * 2 + ((l >> 3) & 1);
                    LDSM4(bf, gbuf + row * 256 + ((ch ^ (row & 7)) << 4));
                }
                mma_f16(oacc[2 * jj],     afp[ks], bf);
                mma_f16(oacc[2 * jj + 1], afp[ks], bf + 2);
            }
        }
        __syncthreads();
        if (it < 7) {
            stage256<256>(Gb + m0 + 128, gbuf, t);
            CP_COMMIT();
        }
    }

    const float i0 = 1.f / L0, i1 = 1.f / L1;
    __half* Yb = Y + (size_t)blockIdx.y * N_ * CI_;
    const int row0 = n0 + w * 16 + (l >> 2);
#pragma unroll
    for (int nt = 0; nt < 32; ++nt) {
        const int col = nt * 8 + (l & 3) * 2;
        *(__half2*)(Yb + (size_t)row0 * CI_ + col) =
            __floats2half2_rn(oacc[nt][0] * i0, oacc[nt][1] * i0);
        *(__half2*)(Yb + (size_t)(row0 + 8) * CI_ + col) =
            __floats2half2_rn(oacc[nt][2] * i1, oacc[nt][3] * i1);
    }
}

// ---------------- prep: zero stats + cvt x + pack weights/biases ----------------
#define XQ_ (B_ * C_ * N_ / 4)       // 4194304
#define WQ_ ((768 * C_) / 4)         // 98304
#define ZQ_ ((C_ * CI_) / 4)         // 32768

__global__ __launch_bounds__(256)
void prep_kernel(const float* __restrict__ x,
                 const float* __restrict__ Wg, const float* __restrict__ Wt,
                 const float* __restrict__ Wp, const float* __restrict__ Wz,
                 const float* __restrict__ bg, const float* __restrict__ bt,
                 const float* __restrict__ bp,
                 __half* __restrict__ x16,
                 __half* __restrict__ Wstk, __half* __restrict__ Wz16,
                 float* __restrict__ bstk) {
    int i = blockIdx.x * 256 + threadIdx.x;
    if (i < XQ_) {
        float4 v = ((const float4*)x)[i];
        __half2 h0 = __floats2half2_rn(v.x, v.y);
        __half2 h1 = __floats2half2_rn(v.z, v.w);
        uint2 u = { *(uint32_t*)&h0, *(uint32_t*)&h1 };
        ((uint2*)x16)[i] = u;
        return;
    }
    int j = i - XQ_;
    if (j < WQ_) {
        int row = (j * 4) >> 9;
        int col = (j * 4) & 511;
        const float* src = row < 256 ? Wg + row * C_
                         : row < 512 ? Wt + (row - 256) * C_
                                     : Wp + (row - 512) * C_;
        float4 v = *(const float4*)(src + col);
        __half2 h0 = __floats2half2_rn(v.x, v.y);
        __half2 h1 = __floats2half2_rn(v.z, v.w);
        uint2 u = { *(uint32_t*)&h0, *(uint32_t*)&h1 };
        ((uint2*)Wstk)[j] = u;
    } else if (j < WQ_ + ZQ_) {
        int k = j - WQ_;
        float4 v = ((const float4*)Wz)[k];
        __half2 h0 = __floats2half2_rn(v.x, v.y);
        __half2 h1 = __floats2half2_rn(v.z, v.w);
        uint2 u = { *(uint32_t*)&h0, *(uint32_t*)&h1 };
        ((uint2*)Wz16)[k] = u;
    } else if (j < WQ_ + ZQ_ + 192) {
        int e = (j - WQ_ - ZQ_) * 4;
#pragma unroll
        for (int q = 0; q < 4; ++q) {
            int r = e + q;
            bstk[r] = r < 256 ? bg[r] : r < 512 ? bt[r - 256] : bp[r - 512];
        }
    } else if (j < WQ_ + ZQ_ + 192 + 128) {
        int c = (j - WQ_ - ZQ_ - 192) * 4;
#pragma unroll
        for (int q = 0; q < 4; ++q) { d_ssum[c + q] = 0.f; d_ssq[c + q] = 0.f; }
    }
}

// ---------------- finalize: BN scale/shift inline + residual (x16) ----------------
__global__ __launch_bounds__(256)
void finalize_kernel(const __half* __restrict__ WY, const __half* __restrict__ x16,
                     const float* __restrict__ gamma, const float* __restrict__ beta,
                     float* __restrict__ out) {
    size_t i4 = (size_t)blockIdx.x * 256 + threadIdx.x;
    int c = (int)((i4 >> 8) & (C_ - 1));            // whole block shares one channel
    const float invN = 1.0f / (float)(B_ * N_);
    float mean = d_ssum[c] * invN;
    float var  = d_ssq[c] * invN - mean * mean;
    float inv  = rsqrtf(var + 1e-5f);
    float sc   = gamma[c] * inv;
    float sh   = beta[c] - mean * sc;

    uint2 uw = ((const uint2*)WY)[i4];
    uint2 ux = ((const uint2*)x16)[i4];
    float2 w0 = __half22float2(*(__half2*)&uw.x);
    float2 w1 = __half22float2(*(__half2*)&uw.y);
    float2 x0 = __half22float2(*(__half2*)&ux.x);
    float2 x1 = __half22float2(*(__half2*)&ux.y);
    float4 o;
    o.x = w0.x * sc + sh + x0.x;
    o.y = w0.y * sc + sh + x0.y;
    o.z = w1.x * sc + sh + x1.x;
    o.w = w1.y * sc + sh + x1.y;
    ((float4*)out)[i4] = o;
}

// ---------------- launch ----------------
extern "C" void kernel_launch(void* const* d_in, const int* in_sizes, int n_in,
                              void* d_out, int out_size) {
    const float* x     = (const float*)d_in[0];
    const float* Wg    = (const float*)d_in[1];
    const float* bg    = (const float*)d_in[2];
    const float* Wt    = (const float*)d_in[3];
    const float* bt    = (const float*)d_in[4];
    const float* Wp    = (const float*)d_in[5];
    const float* bp    = (const float*)d_in[6];
    const float* Wz    = (const float*)d_in[7];
    const float* bz    = (const float*)d_in[8];
    const float* gamma = (const float*)d_in[9];
    const float* beta  = (const float*)d_in[10];
    float* out = (float*)d_out;

    __half *x16, *Wstk, *Wz16, *GTP, *Yh, *WYh;
    float *bstk, *gs, *gs2;
    cudaGetSymbolAddress((void**)&x16,  d_x16);
    cudaGetSymbolAddress((void**)&Wstk, d_Wstk);
    cudaGetSymbolAddress((void**)&Wz16, d_Wz16);
    cudaGetSymbolAddress((void**)&GTP,  d_GTP);
    cudaGetSymbolAddress((void**)&Yh,   d_Yh);
    cudaGetSymbolAddress((void**)&WYh,  d_WYh);
    cudaGetSymbolAddress((void**)&bstk, d_bstk);
    cudaGetSymbolAddress((void**)&gs,   d_ssum);
    cudaGetSymbolAddress((void**)&gs2,  d_ssq);

    cudaFuncSetAttribute(mm_f16<true,  true, false>, cudaFuncAttributeMaxDynamicSharedMemorySize, SMEM_BYTES);
    cudaFuncSetAttribute(mm_f16<false, true, true >, cudaFuncAttributeMaxDynamicSharedMemorySize, SMEM_BYTES);
    cudaFuncSetAttribute(flash_kernel, cudaFuncAttributeMaxDynamicSharedMemorySize, FL_SMEM);

    const long sC  = (long)C_ * N_;
    const long sCi = (long)CI_ * N_;

    prep_kernel<<<(XQ_ + WQ_ + ZQ_ + 192 + 128 + 255) / 256, 256>>>(
        x, Wg, Wt, Wp, Wz, bg, bt, bp, x16, Wstk, Wz16, bstk);

    // stacked projections: GTP[b] (768 x N) = Wstk (768 x C) * x[b] (C x N)
    mm_f16<true, true, false><<<dim3(8, 6, 32), 128, SMEM_BYTES>>>(
        Wstk, x16, bstk, GTP, C_, C_, N_, 0, sC, (long)GSTRIDE, nullptr, nullptr);

    // fused attention: Y[b][n][ci]
    flash_kernel<<<dim3(8, 32), 256, FL_SMEM>>>(GTP, Yh);

    // z-conv + BN partial stats: WY[b] (C x N) = Wz (C x Ci) * Y[b] (N x Ci)
    mm_f16<false, true, true><<<dim3(8, 4, 32), 128, SMEM_BYTES>>>(
        Wz16, Yh, bz, WYh, CI_, CI_, CI_, 0, sCi, sC, gs, gs2);

    finalize_kernel<<<(B_ * C_ * N_) / 4 / 256, 256>>>(WYh, x16, gamma, beta, out);
}

// round 10
// speedup vs baseline: 7.3234x; 1.0015x over previous
#include <cuda_runtime.h>
#include <cuda_fp16.h>
#include <cstdint>

// Problem constants
#define B_  32
#define C_  512
#define CI_ 256
#define N_  1024   // H*W

// ---------------- static device scratch ----------------
__device__ __align__(128) __half d_x16[(size_t)B_ * C_ * N_];
__device__ __align__(128) __half d_Wstk[768 * C_];              // [g;theta;phi] stacked
__device__ __align__(128) float  d_bstk[768];
__device__ __align__(128) __half d_Wz16[C_ * CI_];
__device__ __align__(128) __half d_GTP[(size_t)B_ * 768 * N_];  // [b][768][N]
__device__ __align__(128) __half d_Yh[(size_t)B_ * N_ * CI_];   // y [b][N][Ci]
__device__ __align__(128) __half d_WYh[(size_t)B_ * C_ * N_];
__device__ float d_ssum[C_];
__device__ float d_ssq[C_];

// ---------------- helpers ----------------
static __device__ __forceinline__ uint32_t smem_u32(const void* p) {
    uint32_t a;
    asm("{ .reg .u64 t; cvta.to.shared.u64 t, %1; cvt.u32.u64 %0, t; }" : "=r"(a) : "l"(p));
    return a;
}

#define CP16(dst, src) \
    asm volatile("cp.async.cg.shared.global [%0], [%1], 16;" :: "r"(dst), "l"(src))
#define CP_COMMIT() asm volatile("cp.async.commit_group;" ::: "memory")
#define CP_WAIT0()  asm volatile("cp.async.wait_group 0;" ::: "memory")
#define CP_WAIT1()  asm volatile("cp.async.wait_group 1;" ::: "memory")
#define CP_WAIT2()  asm volatile("cp.async.wait_group 2;" ::: "memory")

#define LDSM4(r, addr) \
    asm volatile("ldmatrix.sync.aligned.m8n8.x4.shared.b16 {%0,%1,%2,%3}, [%4];" \
        : "=r"((r)[0]), "=r"((r)[1]), "=r"((r)[2]), "=r"((r)[3]) : "r"(addr))
#define LDSM4T(r, addr) \
    asm volatile("ldmatrix.sync.aligned.m8n8.x4.trans.shared.b16 {%0,%1,%2,%3}, [%4];" \
        : "=r"((r)[0]), "=r"((r)[1]), "=r"((r)[2]), "=r"((r)[3]) : "r"(addr))

static __device__ __forceinline__ void mma_f16(float* c, const uint32_t* a, const uint32_t* b) {
    asm volatile(
        "mma.sync.aligned.m16n8k16.row.col.f32.f16.f16.f32 "
        "{%0,%1,%2,%3},{%4,%5,%6,%7},{%8,%9},{%0,%1,%2,%3};"
        : "+f"(c[0]), "+f"(c[1]), "+f"(c[2]), "+f"(c[3])
        : "r"(a[0]), "r"(a[1]), "r"(a[2]), "r"(a[3]), "r"(b[0]), "r"(b[1]));
}

static __device__ __forceinline__ uint32_t h2pack(float a, float b) {
    __half2 h = __floats2half2_rn(a, b);
    return *(uint32_t*)&h;
}

// =====================================================================
//     GEMM: 128x128 block, 128 threads (2x2 warps, 64x64 warp tiles)
//     3-stage cp.async pipeline. A always [M][K] K-major.
// =====================================================================
// SMEM: A bufs @0,16K,32K; B bufs @48K,64K,80K  (96 KB)
#define SMEM_BYTES (96 * 1024)

template <bool TR>
static __device__ __forceinline__ void stage_tile128(const __half* __restrict__ src, int ld,
                                                     uint32_t dst, int k0, int t) {
#pragma unroll
    for (int i = 0; i < 8; ++i) {
        int idx = t + i * 128;
        if constexpr (!TR) {
            int r = idx >> 3, c = idx & 7;
            const __half* s = src + (size_t)r * ld + k0 + c * 8;
            CP16(dst + r * 128 + ((c ^ (r & 7)) << 4), s);
        } else {
            int k = idx >> 4, c = idx & 15;
            const __half* s = src + (size_t)(k0 + k) * ld + c * 8;
            CP16(dst + k * 256 + ((c ^ (k & 7)) << 4), s);
        }
    }
}

template <bool TB, bool BIAS, bool STATS>
__global__ __launch_bounds__(128, 2)
void mm_f16(const __half* __restrict__ A, const __half* __restrict__ Bm,
            const float* __restrict__ bias, __half* __restrict__ Out,
            int K, int ldA, int ldB,
            long strideA, long strideB, long strideO,
            float* gs, float* gs2) {
    extern __shared__ __align__(128) char smem[];
    const uint32_t sb = smem_u32(smem);
    const int t = threadIdx.x;
    const int l = t & 31;
    const int w = t >> 5;            // 0..3
    const int wm = (w >> 1) * 64;
    const int wn = (w & 1) * 64;
    const int m0 = blockIdx.y * 128;
    const int n0 = blockIdx.x * 128;
    const __half* Ab = A  + (size_t)blockIdx.z * strideA + (size_t)m0 * ldA;
    const __half* Bb = Bm + (size_t)blockIdx.z * strideB + (TB ? n0 : (size_t)n0 * ldB);

    float acc[4][8][4];
#pragma unroll
    for (int mt = 0; mt < 4; ++mt)
#pragma unroll
        for (int nt = 0; nt < 8; ++nt)
#pragma unroll
            for (int q = 0; q < 4; ++q) acc[mt][nt][q] = 0.f;

    const int S = K / 64;
    stage_tile128<false>(Ab, ldA, sb,                 0, t);
    stage_tile128<TB>   (Bb, ldB, sb + 49152,         0, t);
    CP_COMMIT();
    stage_tile128<false>(Ab, ldA, sb + 16384,        64, t);
    stage_tile128<TB>   (Bb, ldB, sb + 49152 + 16384, 64, t);
    CP_COMMIT();

    int rb = 0;
    for (int s = 0; s < S; ++s) {
        if (s == S - 1) { CP_WAIT0(); } else { CP_WAIT1(); }
        __syncthreads();
        if (s + 2 < S) {
            int sbuf = rb >= 1 ? rb - 1 : rb + 2;
            stage_tile128<false>(Ab, ldA, sb + sbuf * 16384,         (s + 2) * 64, t);
            stage_tile128<TB>   (Bb, ldB, sb + 49152 + sbuf * 16384, (s + 2) * 64, t);
            CP_COMMIT();
        }

        const uint32_t abase = sb + rb * 16384;
        const uint32_t bbase = sb + 49152 + rb * 16384;
#pragma unroll
        for (int ks = 0; ks < 4; ++ks) {
            uint32_t af[4][4], bf[4][4];
#pragma unroll
            for (int mt = 0; mt < 4; ++mt) {
                int row = wm + mt * 16 + (l & 7) + ((l >> 3) & 1) * 8;
                int ch  = ks * 2 + (l >> 4);
                LDSM4(af[mt], abase + row * 128 + ((ch ^ (row & 7)) << 4));
            }
#pragma unroll
            for (int np = 0; np < 4; ++np) {
                if constexpr (!TB) {
                    int row = wn + np * 16 + (l & 7) + (l >> 4) * 8;
                    int ch  = ks * 2 + ((l >> 3) & 1);
                    LDSM4(bf[np], bbase + row * 128 + ((ch ^ (row & 7)) << 4));
                } else {
                    int kr = ks * 16 + (l & 7) + ((l >> 3) & 1) * 8;
                    int ch = ((wn + np * 16) >> 3) + (l >> 4);
                    LDSM4T(bf[np], bbase + kr * 256 + ((ch ^ (kr & 7)) << 4));
                }
            }
#pragma unroll
            for (int mt = 0; mt < 4; ++mt)
#pragma unroll
                for (int nt = 0; nt < 8; ++nt)
                    mma_f16(acc[mt][nt], af[mt], &bf[nt >> 1][(nt & 1) * 2]);
        }
        rb = rb == 2 ? 0 : rb + 1;
    }

    if constexpr (STATS) {
        __syncthreads();
        ((float*)smem)[t] = 0.f;
        ((float*)smem)[t + 128] = 0.f;
        __syncthreads();
    }

#pragma unroll
    for (int mt = 0; mt < 4; ++mt) {
        const int row = m0 + wm + mt * 16 + (l >> 2);
        float bv0 = 0.f, bv1 = 0.f;
        if constexpr (BIAS) { bv0 = bias[row]; bv1 = bias[row + 8]; }
        __half* Ob = Out + (size_t)blockIdx.z * strideO;
        float s0 = 0.f, q0 = 0.f, s1 = 0.f, q1 = 0.f;
#pragma unroll
        for (int nt = 0; nt < 8; ++nt) {
            const int col = n0 + wn + nt * 8 + 2 * (l & 3);
            float v00 = acc[mt][nt][0] + bv0, v01 = acc[mt][nt][1] + bv0;
            float v10 = acc[mt][nt][2] + bv1, v11 = acc[mt][nt][3] + bv1;
            *(__half2*)(Ob + (size_t)row * N_ + col)       = __floats2half2_rn(v00, v01);
            *(__half2*)(Ob + (size_t)(row + 8) * N_ + col) = __floats2half2_rn(v10, v11);
            if constexpr (STATS) {
                s0 += v00 + v01; q0 += v00 * v00 + v01 * v01;
                s1 += v10 + v11; q1 += v10 * v10 + v11 * v11;
            }
        }
        if constexpr (STATS) {
            s0 += __shfl_xor_sync(~0u, s0, 1); s0 += __shfl_xor_sync(~0u, s0, 2);
            q0 += __shfl_xor_sync(~0u, q0, 1); q0 += __shfl_xor_sync(~0u, q0, 2);
            s1 += __shfl_xor_sync(~0u, s1, 1); s1 += __shfl_xor_sync(~0u, s1, 2);
            q1 += __shfl_xor_sync(~0u, q1, 1); q1 += __shfl_xor_sync(~0u, q1, 2);
            if ((l & 3) == 0) {
                const int lr = wm + mt * 16 + (l >> 2);
                float* ss = (float*)smem;
                atomicAdd(ss + lr, s0);       atomicAdd(ss + 128 + lr, q0);
                atomicAdd(ss + lr + 8, s1);   atomicAdd(ss + 128 + lr + 8, q1);
            }
        }
    }

    if constexpr (STATS) {
        __syncthreads();
        atomicAdd(gs  + m0 + t, ((float*)smem)[t]);
        atomicAdd(gs2 + m0 + t, ((float*)smem)[t + 128]);
    }
}

// =====================================================================
//          Flash-fused attention (reads from stacked GTP tensor)
// =====================================================================
#define FL_SMEM (192 * 1024)
#define GSTRIDE ((size_t)768 * N_)

template <int ROWS>
static __device__ __forceinline__ void stage256(const __half* __restrict__ src, uint32_t dst, int t) {
#pragma unroll
    for (int i = 0; i < ROWS / 16; ++i) {
        int idx = t + i * 256;
        int r = idx >> 4, c = idx & 15;
        CP16(dst + r * 256 + ((c ^ (r & 7)) << 4), src + (size_t)r * N_ + c * 8);
    }
}

__global__ __launch_bounds__(256, 1)
void flash_kernel(const __half* __restrict__ GTP, __half* __restrict__ Y) {
    extern __shared__ __align__(128) char smem[];
    const uint32_t sb = smem_u32(smem);
    const int t = threadIdx.x, l = t & 31, w = t >> 5;
    const int n0 = blockIdx.x * 128;
    const __half* Gb = GTP + (size_t)blockIdx.y * GSTRIDE;
    const __half* Tb = Gb + (size_t)256 * N_;
    const __half* Pb = Gb + (size_t)512 * N_;
    const uint32_t ph0 = sb + 65536, gbuf = sb + 131072;

    float oacc[32][4];
#pragma unroll
    for (int nt = 0; nt < 32; ++nt)
#pragma unroll
        for (int q = 0; q < 4; ++q) oacc[nt][q] = 0.f;
    float M0 = -1e30f, M1 = -1e30f, L0 = 0.f, L1 = 0.f;

    stage256<256>(Tb + n0, sb, t);
    stage256<128>(Pb + 0, ph0, t);
    CP_COMMIT();
    stage256<256>(Gb + 0, gbuf, t);
    CP_COMMIT();
    stage256<128>(Pb + (size_t)128 * N_ + 0, ph0 + 32768, t);
    CP_COMMIT();

    for (int it = 0; it < 8; ++it) {
        const int m0 = it * 128;
        float sacc[16][4];
#pragma unroll
        for (int nt = 0; nt < 16; ++nt)
#pragma unroll
            for (int q = 0; q < 4; ++q) sacc[nt][q] = 0.f;

#pragma unroll
        for (int h = 0; h < 2; ++h) {
            if (h == 0) { CP_WAIT2(); }
            else if (it == 0 || it == 7) { CP_WAIT1(); } else { CP_WAIT2(); }
            __syncthreads();
            const uint32_t phb = ph0 + h * 32768;
#pragma unroll
            for (int j = 0; j < 8; ++j) {
                uint32_t af[4];
                {
                    int kr = (h * 8 + j) * 16 + (l & 7) + (l >> 4) * 8;
                    int ch = 2 * w + ((l >> 3) & 1);
                    LDSM4T(af, sb + kr * 256 + ((ch ^ (kr & 7)) << 4));
                }
#pragma unroll
                for (int jj = 0; jj < 8; ++jj) {
                    uint32_t bf[4];
                    {
                        int kr = j * 16 + (l & 7) + ((l >> 3) & 1) * 8;
                        int ch = 2 * jj + (l >> 4);
                        LDSM4T(bf, phb + kr * 256 + ((ch ^ (kr & 7)) << 4));
                    }
                    mma_f16(sacc[2 * jj],     af, bf);
                    mma_f16(sacc[2 * jj + 1], af, bf + 2);
                }
            }
            __syncthreads();
            if (it < 7) {
                stage256<128>(Pb + (size_t)(h * 128) * N_ + m0 + 128, phb, t);
                CP_COMMIT();
            }
        }

        float tmax0 = -1e30f, tmax1 = -1e30f;
#pragma unroll
        for (int nt = 0; nt < 16; ++nt) {
            tmax0 = fmaxf(tmax0, fmaxf(sacc[nt][0], sacc[nt][1]));
            tmax1 = fmaxf(tmax1, fmaxf(sacc[nt][2], sacc[nt][3]));
        }
        tmax0 = fmaxf(tmax0, __shfl_xor_sync(~0u, tmax0, 1));
        tmax0 = fmaxf(tmax0, __shfl_xor_sync(~0u, tmax0, 2));
        tmax1 = fmaxf(tmax1, __shfl_xor_sync(~0u, tmax1, 1));
        tmax1 = fmaxf(tmax1, __shfl_xor_sync(~0u, tmax1, 2));
        float Mn0 = fmaxf(M0, tmax0), Mn1 = fmaxf(M1, tmax1);
        float sc0 = __expf(M0 - Mn0), sc1 = __expf(M1 - Mn1);
        float ts0 = 0.f, ts1 = 0.f;
        uint32_t afp[8][4];
#pragma unroll
        for (int j = 0; j < 8; ++j) {
            float p00 = __expf(sacc[2 * j][0] - Mn0);
            float p01 = __expf(sacc[2 * j][1] - Mn0);
            float p02 = __expf(sacc[2 * j][2] - Mn1);
            float p03 = __expf(sacc[2 * j][3] - Mn1);
            float p10 = __expf(sacc[2 * j + 1][0] - Mn0);
            float p11 = __expf(sacc[2 * j + 1][1] - Mn0);
            float p12 = __expf(sacc[2 * j + 1][2] - Mn1);
            float p13 = __expf(sacc[2 * j + 1][3] - Mn1);
            ts0 += p00 + p01 + p10 + p11;
            ts1 += p02 + p03 + p12 + p13;
            afp[j][0] = h2pack(p00, p01);
            afp[j][1] = h2pack(p02, p03);
            afp[j][2] = h2pack(p10, p11);
            afp[j][3] = h2pack(p12, p13);
        }
        ts0 += __shfl_xor_sync(~0u, ts0, 1); ts0 += __shfl_xor_sync(~0u, ts0, 2);
        ts1 += __shfl_xor_sync(~0u, ts1, 1); ts1 += __shfl_xor_sync(~0u, ts1, 2);
        L0 = L0 * sc0 + ts0; L1 = L1 * sc1 + ts1;
        M0 = Mn0; M1 = Mn1;
#pragma unroll
        for (int nt = 0; nt < 32; ++nt) {
            oacc[nt][0] *= sc0; oacc[nt][1] *= sc0;
            oacc[nt][2] *= sc1; oacc[nt][3] *= sc1;
        }

        if (it < 7) { CP_WAIT2(); } else { CP_WAIT0(); }
        __syncthreads();
#pragma unroll
        for (int ks = 0; ks < 8; ++ks) {
#pragma unroll
            for (int jj = 0; jj < 16; ++jj) {
                uint32_t bf[4];
                {
                    int row = 16 * jj + (l & 7) + (l >> 4) * 8;
                    int ch  = ks * 2 + ((l >> 3) & 1);
                    LDSM4(bf, gbuf + row * 256 + ((ch ^ (row & 7)) << 4));
                }
                mma_f16(oacc[2 * jj],     afp[ks], bf);
                mma_f16(oacc[2 * jj + 1], afp[ks], bf + 2);
            }
        }
        __syncthreads();
        if (it < 7) {
            stage256<256>(Gb + m0 + 128, gbuf, t);
            CP_COMMIT();
        }
    }

    const float i0 = 1.f / L0, i1 = 1.f / L1;
    __half* Yb = Y + (size_t)blockIdx.y * N_ * CI_;
    const int row0 = n0 + w * 16 + (l >> 2);
#pragma unroll
    for (int nt = 0; nt < 32; ++nt) {
        const int col = nt * 8 + (l & 3) * 2;
        *(__half2*)(Yb + (size_t)row0 * CI_ + col) =
            __floats2half2_rn(oacc[nt][0] * i0, oacc[nt][1] * i0);
        *(__half2*)(Yb + (size_t)(row0 + 8) * CI_ + col) =
            __floats2half2_rn(oacc[nt][2] * i1, oacc[nt][3] * i1);
    }
}

// ---------------- prep: zero stats + cvt x + pack weights/biases ----------------
#define XQ_ (B_ * C_ * N_ / 4)       // 4194304
#define WQ_ ((768 * C_) / 4)         // 98304
#define ZQ_ ((C_ * CI_) / 4)         // 32768

__global__ __launch_bounds__(256)
void prep_kernel(const float* __restrict__ x,
                 const float* __restrict__ Wg, const float* __restrict__ Wt,
                 const float* __restrict__ Wp, const float* __restrict__ Wz,
                 const float* __restrict__ bg, const float* __restrict__ bt,
                 const float* __restrict__ bp,
                 __half* __restrict__ x16,
                 __half* __restrict__ Wstk, __half* __restrict__ Wz16,
                 float* __restrict__ bstk) {
    int i = blockIdx.x * 256 + threadIdx.x;
    if (i < XQ_) {
        float4 v = ((const float4*)x)[i];
        __half2 h0 = __floats2half2_rn(v.x, v.y);
        __half2 h1 = __floats2half2_rn(v.z, v.w);
        uint2 u = { *(uint32_t*)&h0, *(uint32_t*)&h1 };
        ((uint2*)x16)[i] = u;
        return;
    }
    int j = i - XQ_;
    if (j < WQ_) {
        int row = (j * 4) >> 9;
        int col = (j * 4) & 511;
        const float* src = row < 256 ? Wg + row * C_
                         : row < 512 ? Wt + (row - 256) * C_
                                     : Wp + (row - 512) * C_;
        float4 v = *(const float4*)(src + col);
        __half2 h0 = __floats2half2_rn(v.x, v.y);
        __half2 h1 = __floats2half2_rn(v.z, v.w);
        uint2 u = { *(uint32_t*)&h0, *(uint32_t*)&h1 };
        ((uint2*)Wstk)[j] = u;
    } else if (j < WQ_ + ZQ_) {
        int k = j - WQ_;
        float4 v = ((const float4*)Wz)[k];
        __half2 h0 = __floats2half2_rn(v.x, v.y);
        __half2 h1 = __floats2half2_rn(v.z, v.w);
        uint2 u = { *(uint32_t*)&h0, *(uint32_t*)&h1 };
        ((uint2*)Wz16)[k] = u;
    } else if (j < WQ_ + ZQ_ + 192) {
        int e = (j - WQ_ - ZQ_) * 4;
#pragma unroll
        for (int q = 0; q < 4; ++q) {
            int r = e + q;
            bstk[r] = r < 256 ? bg[r] : r < 512 ? bt[r - 256] : bp[r - 512];
        }
    } else if (j < WQ_ + ZQ_ + 192 + 128) {
        int c = (j - WQ_ - ZQ_ - 192) * 4;
#pragma unroll
        for (int q = 0; q < 4; ++q) { d_ssum[c + q] = 0.f; d_ssq[c + q] = 0.f; }
    }
}

// ---------------- finalize: BN scale/shift inline + residual (x16) ----------------
__global__ __launch_bounds__(256)
void finalize_kernel(const __half* __restrict__ WY, const __half* __restrict__ x16,
                     const float* __restrict__ gamma, const float* __restrict__ beta,
                     float* __restrict__ out) {
    size_t i4 = (size_t)blockIdx.x * 256 + threadIdx.x;
    int c = (int)((i4 >> 8) & (C_ - 1));            // whole block shares one channel
    const float invN = 1.0f / (float)(B_ * N_);
    float mean = d_ssum[c] * invN;
    float var  = d_ssq[c] * invN - mean * mean;
    float inv  = rsqrtf(var + 1e-5f);
    float sc   = gamma[c] * inv;
    float sh   = beta[c] - mean * sc;

    uint2 uw = ((const uint2*)WY)[i4];
    uint2 ux = ((const uint2*)x16)[i4];
    float2 w0 = __half22float2(*(__half2*)&uw.x);
    float2 w1 = __half22float2(*(__half2*)&uw.y);
    float2 x0 = __half22float2(*(__half2*)&ux.x);
    float2 x1 = __half22float2(*(__half2*)&ux.y);
    float4 o;
    o.x = w0.x * sc + sh + x0.x;
    o.y = w0.y * sc + sh + x0.y;
    o.z = w1.x * sc + sh + x1.x;
    o.w = w1.y * sc + sh + x1.y;
    ((float4*)out)[i4] = o;
}

// ---------------- launch ----------------
extern "C" void kernel_launch(void* const* d_in, const int* in_sizes, int n_in,
                              void* d_out, int out_size) {
    const float* x     = (const float*)d_in[0];
    const float* Wg    = (const float*)d_in[1];
    const float* bg    = (const float*)d_in[2];
    const float* Wt    = (const float*)d_in[3];
    const float* bt    = (const float*)d_in[4];
    const float* Wp    = (const float*)d_in[5];
    const float* bp    = (const float*)d_in[6];
    const float* Wz    = (const float*)d_in[7];
    const float* bz    = (const float*)d_in[8];
    const float* gamma = (const float*)d_in[9];
    const float* beta  = (const float*)d_in[10];
    float* out = (float*)d_out;

    __half *x16, *Wstk, *Wz16, *GTP, *Yh, *WYh;
    float *bstk, *gs, *gs2;
    cudaGetSymbolAddress((void**)&x16,  d_x16);
    cudaGetSymbolAddress((void**)&Wstk, d_Wstk);
    cudaGetSymbolAddress((void**)&Wz16, d_Wz16);
    cudaGetSymbolAddress((void**)&GTP,  d_GTP);
    cudaGetSymbolAddress((void**)&Yh,   d_Yh);
    cudaGetSymbolAddress((void**)&WYh,  d_WYh);
    cudaGetSymbolAddress((void**)&bstk, d_bstk);
    cudaGetSymbolAddress((void**)&gs,   d_ssum);
    cudaGetSymbolAddress((void**)&gs2,  d_ssq);

    cudaFuncSetAttribute(mm_f16<true,  true, false>, cudaFuncAttributeMaxDynamicSharedMemorySize, SMEM_BYTES);
    cudaFuncSetAttribute(mm_f16<false, true, true >, cudaFuncAttributeMaxDynamicSharedMemorySize, SMEM_BYTES);
    cudaFuncSetAttribute(flash_kernel, cudaFuncAttributeMaxDynamicSharedMemorySize, FL_SMEM);

    const long sC  = (long)C_ * N_;
    const long sCi = (long)CI_ * N_;

    prep_kernel<<<(XQ_ + WQ_ + ZQ_ + 192 + 128 + 255) / 256, 256>>>(
        x, Wg, Wt, Wp, Wz, bg, bt, bp, x16, Wstk, Wz16, bstk);

    // stacked projections: GTP[b] (768 x N) = Wstk (768 x C) * x[b] (C x N)
    mm_f16<true, true, false><<<dim3(8, 6, 32), 128, SMEM_BYTES>>>(
        Wstk, x16, bstk, GTP, C_, C_, N_, 0, sC, (long)GSTRIDE, nullptr, nullptr);

    // fused attention: Y[b][n][ci]
    flash_kernel<<<dim3(8, 32), 256, FL_SMEM>>>(GTP, Yh);

    // z-conv + BN partial stats: WY[b] (C x N) = Wz (C x Ci) * Y[b] (N x Ci)
    mm_f16<false, true, true><<<dim3(8, 4, 32), 128, SMEM_BYTES>>>(
        Wz16, Yh, bz, WYh, CI_, CI_, CI_, 0, sCi, sC, gs, gs2);

    finalize_kernel<<<(B_ * C_ * N_) / 4 / 256, 256>>>(WYh, x16, gamma, beta, out);
}

// round 11
// speedup vs baseline: 7.3510x; 1.0038x over previous
#include <cuda_runtime.h>
#include <cuda_fp16.h>
#include <cstdint>

// Problem constants
#define B_  32
#define C_  512
#define CI_ 256
#define N_  1024   // H*W

// ---------------- static device scratch ----------------
__device__ __align__(128) __half d_x16[(size_t)B_ * C_ * N_];
__device__ __align__(128) __half d_Wstk[768 * C_];              // [g;theta;phi] stacked
__device__ __align__(128) float  d_bstk[768];
__device__ __align__(128) __half d_Wz16[C_ * CI_];
__device__ __align__(128) __half d_GTP[(size_t)B_ * 768 * N_];  // [b][768][N]
__device__ __align__(128) __half d_Yh[(size_t)B_ * N_ * CI_];   // y [b][N][Ci]
__device__ __align__(128) __half d_WYh[(size_t)B_ * C_ * N_];
__device__ float d_ssum[C_];
__device__ float d_ssq[C_];

// ---------------- helpers ----------------
static __device__ __forceinline__ uint32_t smem_u32(const void* p) {
    uint32_t a;
    asm("{ .reg .u64 t; cvta.to.shared.u64 t, %1; cvt.u32.u64 %0, t; }" : "=r"(a) : "l"(p));
    return a;
}

#define CP16(dst, src) \
    asm volatile("cp.async.cg.shared.global [%0], [%1], 16;" :: "r"(dst), "l"(src))
#define CP_COMMIT() asm volatile("cp.async.commit_group;" ::: "memory")
#define CP_WAIT0()  asm volatile("cp.async.wait_group 0;" ::: "memory")
#define CP_WAIT1()  asm volatile("cp.async.wait_group 1;" ::: "memory")
#define CP_WAIT2()  asm volatile("cp.async.wait_group 2;" ::: "memory")

#define LDSM4(r, addr) \
    asm volatile("ldmatrix.sync.aligned.m8n8.x4.shared.b16 {%0,%1,%2,%3}, [%4];" \
        : "=r"((r)[0]), "=r"((r)[1]), "=r"((r)[2]), "=r"((r)[3]) : "r"(addr))
#define LDSM4T(r, addr) \
    asm volatile("ldmatrix.sync.aligned.m8n8.x4.trans.shared.b16 {%0,%1,%2,%3}, [%4];" \
        : "=r"((r)[0]), "=r"((r)[1]), "=r"((r)[2]), "=r"((r)[3]) : "r"(addr))

static __device__ __forceinline__ void mma_f16(float* c, const uint32_t* a, const uint32_t* b) {
    asm volatile(
        "mma.sync.aligned.m16n8k16.row.col.f32.f16.f16.f32 "
        "{%0,%1,%2,%3},{%4,%5,%6,%7},{%8,%9},{%0,%1,%2,%3};"
        : "+f"(c[0]), "+f"(c[1]), "+f"(c[2]), "+f"(c[3])
        : "r"(a[0]), "r"(a[1]), "r"(a[2]), "r"(a[3]), "r"(b[0]), "r"(b[1]));
}

static __device__ __forceinline__ uint32_t h2pack(float a, float b) {
    __half2 h = __floats2half2_rn(a, b);
    return *(uint32_t*)&h;
}

// =====================================================================
//     GEMM: 128x128 block, 128 threads (2x2 warps, 64x64 warp tiles)
//     3-stage cp.async pipeline. A always [M][K] K-major.
// =====================================================================
// SMEM: A bufs @0,16K,32K; B bufs @48K,64K,80K  (96 KB)
#define SMEM_BYTES (96 * 1024)

template <bool TR>
static __device__ __forceinline__ void stage_tile128(const __half* __restrict__ src, int ld,
                                                     uint32_t dst, int k0, int t) {
#pragma unroll
    for (int i = 0; i < 8; ++i) {
        int idx = t + i * 128;
        if constexpr (!TR) {
            int r = idx >> 3, c = idx & 7;
            const __half* s = src + (size_t)r * ld + k0 + c * 8;
            CP16(dst + r * 128 + ((c ^ (r & 7)) << 4), s);
        } else {
            int k = idx >> 4, c = idx & 15;
            const __half* s = src + (size_t)(k0 + k) * ld + c * 8;
            CP16(dst + k * 256 + ((c ^ (k & 7)) << 4), s);
        }
    }
}

template <bool TB, bool BIAS, bool STATS>
__global__ __launch_bounds__(128, 2)
void mm_f16(const __half* __restrict__ A, const __half* __restrict__ Bm,
            const float* __restrict__ bias, __half* __restrict__ Out,
            int K, int ldA, int ldB,
            long strideA, long strideB, long strideO,
            float* gs, float* gs2) {
    extern __shared__ __align__(128) char smem[];
    const uint32_t sb = smem_u32(smem);
    const int t = threadIdx.x;
    const int l = t & 31;
    const int w = t >> 5;            // 0..3
    const int wm = (w >> 1) * 64;
    const int wn = (w & 1) * 64;
    const int m0 = blockIdx.y * 128;
    const int n0 = blockIdx.x * 128;
    const __half* Ab = A  + (size_t)blockIdx.z * strideA + (size_t)m0 * ldA;
    const __half* Bb = Bm + (size_t)blockIdx.z * strideB + (TB ? n0 : (size_t)n0 * ldB);

    float acc[4][8][4];
#pragma unroll
    for (int mt = 0; mt < 4; ++mt)
#pragma unroll
        for (int nt = 0; nt < 8; ++nt)
#pragma unroll
            for (int q = 0; q < 4; ++q) acc[mt][nt][q] = 0.f;

    const int S = K / 64;
    stage_tile128<false>(Ab, ldA, sb,                 0, t);
    stage_tile128<TB>   (Bb, ldB, sb + 49152,         0, t);
    CP_COMMIT();
    stage_tile128<false>(Ab, ldA, sb + 16384,        64, t);
    stage_tile128<TB>   (Bb, ldB, sb + 49152 + 16384, 64, t);
    CP_COMMIT();

    int rb = 0;
    for (int s = 0; s < S; ++s) {
        if (s == S - 1) { CP_WAIT0(); } else { CP_WAIT1(); }
        __syncthreads();
        if (s + 2 < S) {
            int sbuf = rb >= 1 ? rb - 1 : rb + 2;
            stage_tile128<false>(Ab, ldA, sb + sbuf * 16384,         (s + 2) * 64, t);
            stage_tile128<TB>   (Bb, ldB, sb + 49152 + sbuf * 16384, (s + 2) * 64, t);
            CP_COMMIT();
        }

        const uint32_t abase = sb + rb * 16384;
        const uint32_t bbase = sb + 49152 + rb * 16384;
#pragma unroll
        for (int ks = 0; ks < 4; ++ks) {
            uint32_t af[4][4], bf[4][4];
#pragma unroll
            for (int mt = 0; mt < 4; ++mt) {
                int row = wm + mt * 16 + (l & 7) + ((l >> 3) & 1) * 8;
                int ch  = ks * 2 + (l >> 4);
                LDSM4(af[mt], abase + row * 128 + ((ch ^ (row & 7)) << 4));
            }
#pragma unroll
            for (int np = 0; np < 4; ++np) {
                if constexpr (!TB) {
                    int row = wn + np * 16 + (l & 7) + (l >> 4) * 8;
                    int ch  = ks * 2 + ((l >> 3) & 1);
                    LDSM4(bf[np], bbase + row * 128 + ((ch ^ (row & 7)) << 4));
                } else {
                    int kr = ks * 16 + (l & 7) + ((l >> 3) & 1) * 8;
                    int ch = ((wn + np * 16) >> 3) + (l >> 4);
                    LDSM4T(bf[np], bbase + kr * 256 + ((ch ^ (kr & 7)) << 4));
                }
            }
#pragma unroll
            for (int mt = 0; mt < 4; ++mt)
#pragma unroll
                for (int nt = 0; nt < 8; ++nt)
                    mma_f16(acc[mt][nt], af[mt], &bf[nt >> 1][(nt & 1) * 2]);
        }
        rb = rb == 2 ? 0 : rb + 1;
    }

    if constexpr (STATS) {
        __syncthreads();
        ((float*)smem)[t] = 0.f;
        ((float*)smem)[t + 128] = 0.f;
        __syncthreads();
    }

#pragma unroll
    for (int mt = 0; mt < 4; ++mt) {
        const int row = m0 + wm + mt * 16 + (l >> 2);
        float bv0 = 0.f, bv1 = 0.f;
        if constexpr (BIAS) { bv0 = bias[row]; bv1 = bias[row + 8]; }
        __half* Ob = Out + (size_t)blockIdx.z * strideO;
        float s0 = 0.f, q0 = 0.f, s1 = 0.f, q1 = 0.f;
#pragma unroll
        for (int nt = 0; nt < 8; ++nt) {
            const int col = n0 + wn + nt * 8 + 2 * (l & 3);
            float v00 = acc[mt][nt][0] + bv0, v01 = acc[mt][nt][1] + bv0;
            float v10 = acc[mt][nt][2] + bv1, v11 = acc[mt][nt][3] + bv1;
            *(__half2*)(Ob + (size_t)row * N_ + col)       = __floats2half2_rn(v00, v01);
            *(__half2*)(Ob + (size_t)(row + 8) * N_ + col) = __floats2half2_rn(v10, v11);
            if constexpr (STATS) {
                s0 += v00 + v01; q0 += v00 * v00 + v01 * v01;
                s1 += v10 + v11; q1 += v10 * v10 + v11 * v11;
            }
        }
        if constexpr (STATS) {
            s0 += __shfl_xor_sync(~0u, s0, 1); s0 += __shfl_xor_sync(~0u, s0, 2);
            q0 += __shfl_xor_sync(~0u, q0, 1); q0 += __shfl_xor_sync(~0u, q0, 2);
            s1 += __shfl_xor_sync(~0u, s1, 1); s1 += __shfl_xor_sync(~0u, s1, 2);
            q1 += __shfl_xor_sync(~0u, q1, 1); q1 += __shfl_xor_sync(~0u, q1, 2);
            if ((l & 3) == 0) {
                const int lr = wm + mt * 16 + (l >> 2);
                float* ss = (float*)smem;
                atomicAdd(ss + lr, s0);       atomicAdd(ss + 128 + lr, q0);
                atomicAdd(ss + lr + 8, s1);   atomicAdd(ss + 128 + lr + 8, q1);
            }
        }
    }

    if constexpr (STATS) {
        __syncthreads();
        atomicAdd(gs  + m0 + t, ((float*)smem)[t]);
        atomicAdd(gs2 + m0 + t, ((float*)smem)[t + 128]);
    }
}

// =====================================================================
//          Flash-fused attention (reads from stacked GTP tensor)
// =====================================================================
#define FL_SMEM (192 * 1024)
#define GSTRIDE ((size_t)768 * N_)

template <int ROWS>
static __device__ __forceinline__ void stage256(const __half* __restrict__ src, uint32_t dst, int t) {
#pragma unroll
    for (int i = 0; i < ROWS / 16; ++i) {
        int idx = t + i * 256;
        int r = idx >> 4, c = idx & 15;
        CP16(dst + r * 256 + ((c ^ (r & 7)) << 4), src + (size_t)r * N_ + c * 8);
    }
}

__global__ __launch_bounds__(256, 1)
void flash_kernel(const __half* __restrict__ GTP, __half* __restrict__ Y) {
    extern __shared__ __align__(128) char smem[];
    const uint32_t sb = smem_u32(smem);
    const int t = threadIdx.x, l = t & 31, w = t >> 5;
    const int n0 = blockIdx.x * 128;
    const __half* Gb = GTP + (size_t)blockIdx.y * GSTRIDE;
    const __half* Tb = Gb + (size_t)256 * N_;
    const __half* Pb = Gb + (size_t)512 * N_;
    const uint32_t ph0 = sb + 65536, gbuf = sb + 131072;

    float oacc[32][4];
#pragma unroll
    for (int nt = 0; nt < 32; ++nt)
#pragma unroll
        for (int q = 0; q < 4; ++q) oacc[nt][q] = 0.f;
    float M0 = -1e30f, M1 = -1e30f, L0 = 0.f, L1 = 0.f;

    stage256<256>(Tb + n0, sb, t);
    stage256<128>(Pb + 0, ph0, t);
    CP_COMMIT();
    stage256<256>(Gb + 0, gbuf, t);
    CP_COMMIT();
    stage256<128>(Pb + (size_t)128 * N_ + 0, ph0 + 32768, t);
    CP_COMMIT();

    for (int it = 0; it < 8; ++it) {
        const int m0 = it * 128;
        float sacc[16][4];
#pragma unroll
        for (int nt = 0; nt < 16; ++nt)
#pragma unroll
            for (int q = 0; q < 4; ++q) sacc[nt][q] = 0.f;

#pragma unroll
        for (int h = 0; h < 2; ++h) {
            if (h == 0) { CP_WAIT2(); }
            else if (it == 0 || it == 7) { CP_WAIT1(); } else { CP_WAIT2(); }
            __syncthreads();
            const uint32_t phb = ph0 + h * 32768;
#pragma unroll
            for (int j = 0; j < 8; ++j) {
                uint32_t af[4];
                {
                    int kr = (h * 8 + j) * 16 + (l & 7) + (l >> 4) * 8;
                    int ch = 2 * w + ((l >> 3) & 1);
                    LDSM4T(af, sb + kr * 256 + ((ch ^ (kr & 7)) << 4));
                }
#pragma unroll
                for (int jj = 0; jj < 8; ++jj) {
                    uint32_t bf[4];
                    {
                        int kr = j * 16 + (l & 7) + ((l >> 3) & 1) * 8;
                        int ch = 2 * jj + (l >> 4);
                        LDSM4T(bf, phb + kr * 256 + ((ch ^ (kr & 7)) << 4));
                    }
                    mma_f16(sacc[2 * jj],     af, bf);
                    mma_f16(sacc[2 * jj + 1], af, bf + 2);
                }
            }
            __syncthreads();
            if (it < 7) {
                stage256<128>(Pb + (size_t)(h * 128) * N_ + m0 + 128, phb, t);
                CP_COMMIT();
            }
        }

        float tmax0 = -1e30f, tmax1 = -1e30f;
#pragma unroll
        for (int nt = 0; nt < 16; ++nt) {
            tmax0 = fmaxf(tmax0, fmaxf(sacc[nt][0], sacc[nt][1]));
            tmax1 = fmaxf(tmax1, fmaxf(sacc[nt][2], sacc[nt][3]));
        }
        tmax0 = fmaxf(tmax0, __shfl_xor_sync(~0u, tmax0, 1));
        tmax0 = fmaxf(tmax0, __shfl_xor_sync(~0u, tmax0, 2));
        tmax1 = fmaxf(tmax1, __shfl_xor_sync(~0u, tmax1, 1));
        tmax1 = fmaxf(tmax1, __shfl_xor_sync(~0u, tmax1, 2));
        float Mn0 = fmaxf(M0, tmax0), Mn1 = fmaxf(M1, tmax1);
        float sc0 = __expf(M0 - Mn0), sc1 = __expf(M1 - Mn1);
        float ts0 = 0.f, ts1 = 0.f;
        uint32_t afp[8][4];
#pragma unroll
        for (int j = 0; j < 8; ++j) {
            float p00 = __expf(sacc[2 * j][0] - Mn0);
            float p01 = __expf(sacc[2 * j][1] - Mn0);
            float p02 = __expf(sacc[2 * j][2] - Mn1);
            float p03 = __expf(sacc[2 * j][3] - Mn1);
            float p10 = __expf(sacc[2 * j + 1][0] - Mn0);
            float p11 = __expf(sacc[2 * j + 1][1] - Mn0);
            float p12 = __expf(sacc[2 * j + 1][2] - Mn1);
            float p13 = __expf(sacc[2 * j + 1][3] - Mn1);
            ts0 += p00 + p01 + p10 + p11;
            ts1 += p02 + p03 + p12 + p13;
            afp[j][0] = h2pack(p00, p01);
            afp[j][1] = h2pack(p02, p03);
            afp[j][2] = h2pack(p10, p11);
            afp[j][3] = h2pack(p12, p13);
        }
        ts0 += __shfl_xor_sync(~0u, ts0, 1); ts0 += __shfl_xor_sync(~0u, ts0, 2);
        ts1 += __shfl_xor_sync(~0u, ts1, 1); ts1 += __shfl_xor_sync(~0u, ts1, 2);
        L0 = L0 * sc0 + ts0; L1 = L1 * sc1 + ts1;
        M0 = Mn0; M1 = Mn1;
#pragma unroll
        for (int nt = 0; nt < 32; ++nt) {
            oacc[nt][0] *= sc0; oacc[nt][1] *= sc0;
            oacc[nt][2] *= sc1; oacc[nt][3] *= sc1;
        }

        if (it < 7) { CP_WAIT2(); } else { CP_WAIT0(); }
        __syncthreads();
#pragma unroll
        for (int ks = 0; ks < 8; ++ks) {
#pragma unroll
            for (int jj = 0; jj < 16; ++jj) {
                uint32_t bf[4];
                {
                    int row = 16 * jj + (l & 7) + (l >> 4) * 8;
                    int ch  = ks * 2 + ((l >> 3) & 1);
                    LDSM4(bf, gbuf + row * 256 + ((ch ^ (row & 7)) << 4));
                }
                mma_f16(oacc[2 * jj],     afp[ks], bf);
                mma_f16(oacc[2 * jj + 1], afp[ks], bf + 2);
            }
        }
        __syncthreads();
        if (it < 7) {
            stage256<256>(Gb + m0 + 128, gbuf, t);
            CP_COMMIT();
        }
    }

    const float i0 = 1.f / L0, i1 = 1.f / L1;
    __half* Yb = Y + (size_t)blockIdx.y * N_ * CI_;
    const int row0 = n0 + w * 16 + (l >> 2);
#pragma unroll
    for (int nt = 0; nt < 32; ++nt) {
        const int col = nt * 8 + (l & 3) * 2;
        *(__half2*)(Yb + (size_t)row0 * CI_ + col) =
            __floats2half2_rn(oacc[nt][0] * i0, oacc[nt][1] * i0);
        *(__half2*)(Yb + (size_t)(row0 + 8) * CI_ + col) =
            __floats2half2_rn(oacc[nt][2] * i1, oacc[nt][3] * i1);
    }
}

// ---------------- prep: zero stats + cvt x + pack weights/biases ----------------
#define XQ_ (B_ * C_ * N_ / 4)       // 4194304
#define WQ_ ((768 * C_) / 4)         // 98304
#define ZQ_ ((C_ * CI_) / 4)         // 32768

__global__ __launch_bounds__(256)
void prep_kernel(const float* __restrict__ x,
                 const float* __restrict__ Wg, const float* __restrict__ Wt,
                 const float* __restrict__ Wp, const float* __restrict__ Wz,
                 const float* __restrict__ bg, const float* __restrict__ bt,
                 const float* __restrict__ bp,
                 __half* __restrict__ x16,
                 __half* __restrict__ Wstk, __half* __restrict__ Wz16,
                 float* __restrict__ bstk) {
    int i = blockIdx.x * 256 + threadIdx.x;
    if (i < XQ_) {
        float4 v = ((const float4*)x)[i];
        __half2 h0 = __floats2half2_rn(v.x, v.y);
        __half2 h1 = __floats2half2_rn(v.z, v.w);
        uint2 u = { *(uint32_t*)&h0, *(uint32_t*)&h1 };
        ((uint2*)x16)[i] = u;
        return;
    }
    int j = i - XQ_;
    if (j < WQ_) {
        int row = (j * 4) >> 9;
        int col = (j * 4) & 511;
        const float* src = row < 256 ? Wg + row * C_
                         : row < 512 ? Wt + (row - 256) * C_
                                     : Wp + (row - 512) * C_;
        float4 v = *(const float4*)(src + col);
        __half2 h0 = __floats2half2_rn(v.x, v.y);
        __half2 h1 = __floats2half2_rn(v.z, v.w);
        uint2 u = { *(uint32_t*)&h0, *(uint32_t*)&h1 };
        ((uint2*)Wstk)[j] = u;
    } else if (j < WQ_ + ZQ_) {
        int k = j - WQ_;
        float4 v = ((const float4*)Wz)[k];
        __half2 h0 = __floats2half2_rn(v.x, v.y);
        __half2 h1 = __floats2half2_rn(v.z, v.w);
        uint2 u = { *(uint32_t*)&h0, *(uint32_t*)&h1 };
        ((uint2*)Wz16)[k] = u;
    } else if (j < WQ_ + ZQ_ + 192) {
        int e = (j - WQ_ - ZQ_) * 4;
#pragma unroll
        for (int q = 0; q < 4; ++q) {
            int r = e + q;
            bstk[r] = r < 256 ? bg[r] : r < 512 ? bt[r - 256] : bp[r - 512];
        }
    } else if (j < WQ_ + ZQ_ + 192 + 128) {
        int c = (j - WQ_ - ZQ_ - 192) * 4;
#pragma unroll
        for (int q = 0; q < 4; ++q) { d_ssum[c + q] = 0.f; d_ssq[c + q] = 0.f; }
    }
}

// ---------------- finalize: BN scale/shift inline + residual (x16) ----------------
__global__ __launch_bounds__(256)
void finalize_kernel(const __half* __restrict__ WY, const __half* __restrict__ x16,
                     const float* __restrict__ gamma, const float* __restrict__ beta,
                     float* __restrict__ out) {
    size_t i4 = (size_t)blockIdx.x * 256 + threadIdx.x;
    int c = (int)((i4 >> 8) & (C_ - 1));            // whole block shares one channel
    const float invN = 1.0f / (float)(B_ * N_);
    float mean = d_ssum[c] * invN;
    float var  = d_ssq[c] * invN - mean * mean;
    float inv  = rsqrtf(var + 1e-5f);
    float sc   = gamma[c] * inv;
    float sh   = beta[c] - mean * sc;

    uint2 uw = ((const uint2*)WY)[i4];
    uint2 ux = ((const uint2*)x16)[i4];
    float2 w0 = __half22float2(*(__half2*)&uw.x);
    float2 w1 = __half22float2(*(__half2*)&uw.y);
    float2 x0 = __half22float2(*(__half2*)&ux.x);
    float2 x1 = __half22float2(*(__half2*)&ux.y);
    float4 o;
    o.x = w0.x * sc + sh + x0.x;
    o.y = w0.y * sc + sh + x0.y;
    o.z = w1.x * sc + sh + x1.x;
    o.w = w1.y * sc + sh + x1.y;
    ((float4*)out)[i4] = o;
}

// ---------------- launch ----------------
extern "C" void kernel_launch(void* const* d_in, const int* in_sizes, int n_in,
                              void* d_out, int out_size) {
    const float* x     = (const float*)d_in[0];
    const float* Wg    = (const float*)d_in[1];
    const float* bg    = (const float*)d_in[2];
    const float* Wt    = (const float*)d_in[3];
    const float* bt    = (const float*)d_in[4];
    const float* Wp    = (const float*)d_in[5];
    const float* bp    = (const float*)d_in[6];
    const float* Wz    = (const float*)d_in[7];
    const float* bz    = (const float*)d_in[8];
    const float* gamma = (const float*)d_in[9];
    const float* beta  = (const float*)d_in[10];
    float* out = (float*)d_out;

    __half *x16, *Wstk, *Wz16, *GTP, *Yh, *WYh;
    float *bstk, *gs, *gs2;
    cudaGetSymbolAddress((void**)&x16,  d_x16);
    cudaGetSymbolAddress((void**)&Wstk, d_Wstk);
    cudaGetSymbolAddress((void**)&Wz16, d_Wz16);
    cudaGetSymbolAddress((void**)&GTP,  d_GTP);
    cudaGetSymbolAddress((void**)&Yh,   d_Yh);
    cudaGetSymbolAddress((void**)&WYh,  d_WYh);
    cudaGetSymbolAddress((void**)&bstk, d_bstk);
    cudaGetSymbolAddress((void**)&gs,   d_ssum);
    cudaGetSymbolAddress((void**)&gs2,  d_ssq);

    cudaFuncSetAttribute(mm_f16<true,  true, false>, cudaFuncAttributeMaxDynamicSharedMemorySize, SMEM_BYTES);
    cudaFuncSetAttribute(mm_f16<false, true, true >, cudaFuncAttributeMaxDynamicSharedMemorySize, SMEM_BYTES);
    cudaFuncSetAttribute(flash_kernel, cudaFuncAttributeMaxDynamicSharedMemorySize, FL_SMEM);

    const long sC  = (long)C_ * N_;
    const long sCi = (long)CI_ * N_;

    prep_kernel<<<(XQ_ + WQ_ + ZQ_ + 192 + 128 + 255) / 256, 256>>>(
        x, Wg, Wt, Wp, Wz, bg, bt, bp, x16, Wstk, Wz16, bstk);

    // stacked projections: GTP[b] (768 x N) = Wstk (768 x C) * x[b] (C x N)
    mm_f16<true, true, false><<<dim3(8, 6, 32), 128, SMEM_BYTES>>>(
        Wstk, x16, bstk, GTP, C_, C_, N_, 0, sC, (long)GSTRIDE, nullptr, nullptr);

    // fused attention: Y[b][n][ci]
    flash_kernel<<<dim3(8, 32), 256, FL_SMEM>>>(GTP, Yh);

    // z-conv + BN partial stats: WY[b] (C x N) = Wz (C x Ci) * Y[b] (N x Ci)
    mm_f16<false, true, true><<<dim3(8, 4, 32), 128, SMEM_BYTES>>>(
        Wz16, Yh, bz, WYh, CI_, CI_, CI_, 0, sCi, sC, gs, gs2);

    finalize_kernel<<<(B_ * C_ * N_) / 4 / 256, 256>>>(WYh, x16, gamma, beta, out);
}